// round 1
// baseline (speedup 1.0000x reference)
#include <cuda_runtime.h>
#include <cstdint>

// Problem constants
#define B_  4
#define L_  4096
#define D_  1024
#define H_  16
#define HD_ 64
#define P_  128
#define MAXLEN_ 4096
#define BH_ (B_ * H_)
#define M_FULL (B_ * L_)       // 16384
#define M_KV   (B_ * P_)       // 512

// -------- scratch (no allocation allowed -> device globals) --------
__device__ float g_Q [M_FULL * (size_t)D_];   // 64 MB
__device__ float g_K [M_KV   * (size_t)D_];   // 2 MB
__device__ float g_V [M_KV   * (size_t)D_];   // 2 MB
__device__ float g_Kp[BH_ * P_ * HD_];        // 2 MB
__device__ float g_Vp[BH_ * P_ * HD_];        // 2 MB
__device__ float g_A [M_FULL * (size_t)D_];   // 64 MB

// ===================================================================
// SGEMM:  C[M,N] = A[M,K] * W[N,K]^T   (both K-major, "NT")
// Block tile 128x128, K-tile 16, 256 threads, 8x8 per-thread microtile.
// A-row remap: actual_row = (m / rpb) * bstride + (m % rpb)
//   identity: rpb = M, bstride = anything
//   KV gather: rpb = 128, bstride = L (pick rows l<128 of each batch)
// ===================================================================
__global__ __launch_bounds__(256) void sgemm_nt(
    const float* __restrict__ A, const float* __restrict__ W,
    float* __restrict__ C, int M, int N, int K, int rpb, int bstride)
{
    __shared__ float As[16][128];
    __shared__ float Ws[16][128];

    const int tid = threadIdx.x;
    const int bx = blockIdx.x;   // N tile
    const int by = blockIdx.y;   // M tile

    // loader indexing: 128 rows x 16 cols per operand; 4 float4 per row
    const int lr = tid >> 2;          // 0..63
    const int lc = (tid & 3) << 2;    // 0,4,8,12

    const int gr0 = by * 128 + lr;
    const int gr1 = gr0 + 64;
    const float* a0 = A + ((size_t)(gr0 / rpb) * bstride + (gr0 % rpb)) * K;
    const float* a1 = A + ((size_t)(gr1 / rpb) * bstride + (gr1 % rpb)) * K;
    const float* w0 = W + (size_t)(bx * 128 + lr) * K;
    const float* w1 = W + (size_t)(bx * 128 + lr + 64) * K;

    const int ty = tid >> 4;   // 0..15 (row group)
    const int tx = tid & 15;   // 0..15 (col group)

    float acc[8][8];
    #pragma unroll
    for (int i = 0; i < 8; ++i)
        #pragma unroll
        for (int j = 0; j < 8; ++j) acc[i][j] = 0.f;

    for (int k0 = 0; k0 < K; k0 += 16) {
        float4 av0 = *(const float4*)(a0 + k0 + lc);
        float4 av1 = *(const float4*)(a1 + k0 + lc);
        float4 wv0 = *(const float4*)(w0 + k0 + lc);
        float4 wv1 = *(const float4*)(w1 + k0 + lc);

        As[lc + 0][lr]      = av0.x; As[lc + 1][lr]      = av0.y;
        As[lc + 2][lr]      = av0.z; As[lc + 3][lr]      = av0.w;
        As[lc + 0][lr + 64] = av1.x; As[lc + 1][lr + 64] = av1.y;
        As[lc + 2][lr + 64] = av1.z; As[lc + 3][lr + 64] = av1.w;

        Ws[lc + 0][lr]      = wv0.x; Ws[lc + 1][lr]      = wv0.y;
        Ws[lc + 2][lr]      = wv0.z; Ws[lc + 3][lr]      = wv0.w;
        Ws[lc + 0][lr + 64] = wv1.x; Ws[lc + 1][lr + 64] = wv1.y;
        Ws[lc + 2][lr + 64] = wv1.z; Ws[lc + 3][lr + 64] = wv1.w;

        __syncthreads();

        #pragma unroll
        for (int k = 0; k < 16; ++k) {
            float4 m0 = *(const float4*)&As[k][ty * 8];
            float4 m1 = *(const float4*)&As[k][ty * 8 + 4];
            float4 n0 = *(const float4*)&Ws[k][tx * 8];
            float4 n1 = *(const float4*)&Ws[k][tx * 8 + 4];
            float rm[8] = {m0.x, m0.y, m0.z, m0.w, m1.x, m1.y, m1.z, m1.w};
            float rn[8] = {n0.x, n0.y, n0.z, n0.w, n1.x, n1.y, n1.z, n1.w};
            #pragma unroll
            for (int i = 0; i < 8; ++i)
                #pragma unroll
                for (int j = 0; j < 8; ++j)
                    acc[i][j] += rm[i] * rn[j];
        }
        __syncthreads();
    }

    // store (output rows are compact, not remapped)
    #pragma unroll
    for (int i = 0; i < 8; ++i) {
        float* crow = C + (size_t)(by * 128 + ty * 8 + i) * N + bx * 128 + tx * 8;
        *(float4*)(crow)     = make_float4(acc[i][0], acc[i][1], acc[i][2], acc[i][3]);
        *(float4*)(crow + 4) = make_float4(acc[i][4], acc[i][5], acc[i][6], acc[i][7]);
    }
}

// ===================================================================
// RoPE in place on (rows, D) buffer laid out (b, l, h, hd).
// position l = row % lmod. Pair j within a head: elements (2j, 2j+1).
// ===================================================================
__global__ void rope_kernel(float* __restrict__ T,
                            const float* __restrict__ cosT,
                            const float* __restrict__ sinT,
                            int rows, int lmod)
{
    int i = blockIdx.x * blockDim.x + threadIdx.x;   // pair index
    int total = rows * (D_ / 2);
    if (i >= total) return;
    int row = i >> 9;          // / 512 pairs per row
    int pi  = i & 511;
    int h = pi >> 5;           // head
    int f = pi & 31;           // freq
    int l = row % lmod;
    float c = cosT[l * 32 + f];
    float s = sinT[l * 32 + f];
    float* p = T + (size_t)row * D_ + h * HD_ + 2 * f;
    float tr = p[0], ti = p[1];
    p[0] = tr * c - ti * s;
    p[1] = tr * s + ti * c;
}

// ===================================================================
// K_proj/V_proj: out[bh, p, d] = sum_{l<=p} mat[p,l] * KV[b*128+l, h*64+d]
// grid (P, BH), block 64 (one thread per d)
// ===================================================================
__global__ void proj_kernel(const float* __restrict__ Kb, const float* __restrict__ Vb,
                            const float* __restrict__ kpm, const float* __restrict__ vpm,
                            float* __restrict__ Kp, float* __restrict__ Vp)
{
    int p  = blockIdx.x;
    int bh = blockIdx.y;
    int b = bh >> 4, h = bh & 15;
    int d = threadIdx.x;
    const float* kbase = Kb + (size_t)b * P_ * D_ + h * HD_ + d;
    const float* vbase = Vb + (size_t)b * P_ * D_ + h * HD_ + d;
    float ak = 0.f, av = 0.f;
    for (int l = 0; l <= p; ++l) {
        float mk = kpm[p * MAXLEN_ + l];
        float mv = vpm[p * MAXLEN_ + l];
        ak += mk * kbase[(size_t)l * D_];
        av += mv * vbase[(size_t)l * D_];
    }
    size_t o = ((size_t)bh * P_ + p) * HD_ + d;
    Kp[o] = ak;
    Vp[o] = av;
}

// ===================================================================
// Attention: per (b,h): scores = Q·Kp^T / 8, mask p>l, softmax over P=128,
// out = w·Vp. Kp/Vp resident in smem (stride 65 to avoid bank conflicts).
// grid (L/256, BH), 256 threads = 8 warps, each warp handles 32 l's.
// ===================================================================
#define KP_STRIDE 65
#define ATTN_SMEM_FLOATS (2 * P_ * KP_STRIDE + 8 * (HD_ + P_))
#define ATTN_SMEM_BYTES  (ATTN_SMEM_FLOATS * 4)

__global__ __launch_bounds__(256) void attn_kernel(
    const float* __restrict__ Q, const float* __restrict__ Kp,
    const float* __restrict__ Vp, float* __restrict__ Out)
{
    extern __shared__ float smem[];
    float* kp = smem;
    float* vp = smem + P_ * KP_STRIDE;
    const int tid  = threadIdx.x;
    const int lane = tid & 31;
    const int warp = tid >> 5;
    float* qs = smem + 2 * P_ * KP_STRIDE + warp * (HD_ + P_);
    float* ws = qs + HD_;

    const int bh = blockIdx.y;
    const int b = bh >> 4, h = bh & 15;

    // stage Kp/Vp tiles (128 x 64 each) into padded smem
    const float* kpg = Kp + (size_t)bh * P_ * HD_;
    const float* vpg = Vp + (size_t)bh * P_ * HD_;
    for (int i = tid; i < P_ * HD_; i += 256) {
        int p = i >> 6, d = i & 63;
        kp[p * KP_STRIDE + d] = kpg[i];
        vp[p * KP_STRIDE + d] = vpg[i];
    }
    __syncthreads();

    for (int t = 0; t < 32; ++t) {
        int l = blockIdx.x * 256 + warp * 32 + t;
        const float* qg = Q + ((size_t)b * L_ + l) * D_ + h * HD_;
        qs[lane]      = qg[lane];
        qs[lane + 32] = qg[lane + 32];
        __syncwarp();

        // scores: lane owns p = lane + 32*j
        float s[4];
        #pragma unroll
        for (int j = 0; j < 4; ++j) {
            int p = lane + 32 * j;
            const float* krow = kp + p * KP_STRIDE;
            float acc = 0.f;
            #pragma unroll
            for (int d = 0; d < HD_; ++d) acc += krow[d] * qs[d];
            s[j] = (p <= l) ? acc * 0.125f : -INFINITY;
        }
        // warp softmax over 128 scores
        float m = fmaxf(fmaxf(s[0], s[1]), fmaxf(s[2], s[3]));
        #pragma unroll
        for (int o = 16; o > 0; o >>= 1) m = fmaxf(m, __shfl_xor_sync(0xffffffffu, m, o));
        float e[4], sum = 0.f;
        #pragma unroll
        for (int j = 0; j < 4; ++j) { e[j] = __expf(s[j] - m); sum += e[j]; }
        #pragma unroll
        for (int o = 16; o > 0; o >>= 1) sum += __shfl_xor_sync(0xffffffffu, sum, o);
        float inv = __frcp_rn(sum);
        #pragma unroll
        for (int j = 0; j < 4; ++j) ws[lane + 32 * j] = e[j] * inv;
        __syncwarp();

        // out: lane owns d = lane, lane+32
        float a0 = 0.f, a1 = 0.f;
        #pragma unroll 8
        for (int p = 0; p < P_; ++p) {
            float wv = ws[p];
            a0 += wv * vp[p * KP_STRIDE + lane];
            a1 += wv * vp[p * KP_STRIDE + lane + 32];
        }
        float* og = Out + ((size_t)b * L_ + l) * D_ + h * HD_;
        og[lane]      = a0;
        og[lane + 32] = a1;
        __syncwarp();
    }
}

// ===================================================================
extern "C" void kernel_launch(void* const* d_in, const int* in_sizes, int n_in,
                              void* d_out, int out_size)
{
    const float* x   = (const float*)d_in[0];
    const float* fc  = (const float*)d_in[1];
    const float* fs  = (const float*)d_in[2];
    const float* Wq  = (const float*)d_in[3];
    const float* Wk  = (const float*)d_in[4];
    const float* Wv  = (const float*)d_in[5];
    const float* Wo  = (const float*)d_in[6];
    const float* kpm = (const float*)d_in[7];
    const float* vpm = (const float*)d_in[8];
    float* out = (float*)d_out;

    float *Qp, *Kb, *Vb, *Kpp, *Vpp, *Ap;
    cudaGetSymbolAddress((void**)&Qp,  g_Q);
    cudaGetSymbolAddress((void**)&Kb,  g_K);
    cudaGetSymbolAddress((void**)&Vb,  g_V);
    cudaGetSymbolAddress((void**)&Kpp, g_Kp);
    cudaGetSymbolAddress((void**)&Vpp, g_Vp);
    cudaGetSymbolAddress((void**)&Ap,  g_A);

    // Q = x @ Wq^T (full), K/V = x @ W^T on first 128 rows of each batch only
    sgemm_nt<<<dim3(D_ / 128, M_FULL / 128), 256>>>(x, Wq, Qp, M_FULL, D_, D_, M_FULL, M_FULL);
    sgemm_nt<<<dim3(D_ / 128, M_KV / 128), 256>>>(x, Wk, Kb, M_KV, D_, D_, P_, L_);
    sgemm_nt<<<dim3(D_ / 128, M_KV / 128), 256>>>(x, Wv, Vb, M_KV, D_, D_, P_, L_);

    // RoPE on Q (pos = row % L) and K (pos = row % 128)
    {
        int totQ = M_FULL * (D_ / 2);
        rope_kernel<<<(totQ + 255) / 256, 256>>>(Qp, fc, fs, M_FULL, L_);
        int totK = M_KV * (D_ / 2);
        rope_kernel<<<(totK + 255) / 256, 256>>>(Kb, fc, fs, M_KV, P_);
    }

    // low-rank projections (tril-masked)
    proj_kernel<<<dim3(P_, BH_), 64>>>(Kb, Vb, kpm, vpm, Kpp, Vpp);

    // fused attention
    cudaFuncSetAttribute(attn_kernel, cudaFuncAttributeMaxDynamicSharedMemorySize,
                         ATTN_SMEM_BYTES);
    attn_kernel<<<dim3(L_ / 256, BH_), 256, ATTN_SMEM_BYTES>>>(Qp, Kpp, Vpp, Ap);

    // final projection: out = attn @ Wo^T
    sgemm_nt<<<dim3(D_ / 128, M_FULL / 128), 256>>>(Ap, Wo, out, M_FULL, D_, D_, M_FULL, M_FULL);
}

// round 3
// speedup vs baseline: 1.5355x; 1.5355x over previous
#include <cuda_runtime.h>
#include <cuda_bf16.h>
#include <cstdint>

// Problem constants
#define B_  4
#define L_  4096
#define D_  1024
#define H_  16
#define HD_ 64
#define P_  128
#define MAXLEN_ 4096
#define BH_ (B_ * H_)
#define M_FULL (B_ * L_)       // 16384
#define M_KV   (B_ * P_)       // 512
#define KS_    3072            // split K' = 3*D

__device__ __forceinline__ uint32_t smem_u32(const void* p) {
    uint32_t a;
    asm("{ .reg .u64 t; cvta.to.shared.u64 t, %1; cvt.u32.u64 %0, t; }" : "=r"(a) : "l"(p));
    return a;
}
#define CP_ASYNC16(dst, src) \
    asm volatile("cp.async.cg.shared.global [%0], [%1], 16;" :: "r"(dst), "l"(src))
#define CP_COMMIT() asm volatile("cp.async.commit_group;" ::: "memory")
#define CP_WAIT2()  asm volatile("cp.async.wait_group 2;" ::: "memory")

#define LDSM_X4(R0, R1, R2, R3, A) \
    asm volatile("ldmatrix.sync.aligned.m8n8.x4.shared.b16 {%0,%1,%2,%3}, [%4];" \
        : "=r"(R0), "=r"(R1), "=r"(R2), "=r"(R3) : "r"(A))

#define MMA16816(D0, D1, D2, D3, A0, A1, A2, A3, B0, B1) \
    asm volatile("mma.sync.aligned.m16n8k16.row.col.f32.bf16.bf16.f32 " \
        "{%0,%1,%2,%3}, {%4,%5,%6,%7}, {%8,%9}, {%0,%1,%2,%3};" \
        : "+f"(D0), "+f"(D1), "+f"(D2), "+f"(D3) \
        : "r"(A0), "r"(A1), "r"(A2), "r"(A3), "r"(B0), "r"(B1))

// -------- scratch (no allocation allowed -> device globals) --------
__device__ __nv_bfloat16 g_xs [M_FULL * (size_t)KS_];  // 96 MB  [hi|hi|lo]
__device__ __nv_bfloat16 g_As [M_FULL * (size_t)KS_];  // 96 MB
__device__ __nv_bfloat16 g_kvs[M_KV   * (size_t)KS_];  // 3 MB
__device__ __nv_bfloat16 g_Wq3[D_ * (size_t)KS_];      // 6 MB   [hi|lo|hi]
__device__ __nv_bfloat16 g_Wk3[D_ * (size_t)KS_];
__device__ __nv_bfloat16 g_Wv3[D_ * (size_t)KS_];
__device__ __nv_bfloat16 g_Wo3[D_ * (size_t)KS_];
__device__ float g_Q [M_FULL * (size_t)D_];            // 64 MB
__device__ float g_K [M_KV   * (size_t)D_];
__device__ float g_V [M_KV   * (size_t)D_];
__device__ float g_Kp[BH_ * P_ * HD_];
__device__ float g_Vp[BH_ * P_ * HD_];
__device__ float g_A [M_FULL * (size_t)D_];            // 64 MB

// ===================================================================
// split: fp32 (rows x 1024) -> bf16 (rows x 3072)
//   wmode 0 (activations): [hi | hi | lo];  wmode 1 (weights): [hi | lo | hi]
//   row remap: src_row = (row/rpb)*bstride + row%rpb (gather first 128 l's)
// ===================================================================
__global__ __launch_bounds__(256) void split_kernel(
    const float* __restrict__ src, __nv_bfloat16* __restrict__ dst,
    int rows, int rpb, int bstride, int wmode)
{
    int i = blockIdx.x * 256 + threadIdx.x;
    if (i >= rows * 128) return;
    int row = i >> 7;
    int c = (i & 127) * 8;
    int srow = (row / rpb) * bstride + (row % rpb);
    const float4* s = (const float4*)(src + (size_t)srow * D_ + c);
    float4 f0 = s[0], f1 = s[1];
    float f[8] = {f0.x, f0.y, f0.z, f0.w, f1.x, f1.y, f1.z, f1.w};
    uint32_t hv[4], lv[4];
    #pragma unroll
    for (int j = 0; j < 4; ++j) {
        __nv_bfloat16 h0 = __float2bfloat16(f[2*j]);
        __nv_bfloat16 h1 = __float2bfloat16(f[2*j+1]);
        __nv_bfloat16 l0 = __float2bfloat16(f[2*j]   - __bfloat162float(h0));
        __nv_bfloat16 l1 = __float2bfloat16(f[2*j+1] - __bfloat162float(h1));
        hv[j] = (uint32_t)__bfloat16_as_ushort(h0) | ((uint32_t)__bfloat16_as_ushort(h1) << 16);
        lv[j] = (uint32_t)__bfloat16_as_ushort(l0) | ((uint32_t)__bfloat16_as_ushort(l1) << 16);
    }
    uint4 Hv = make_uint4(hv[0], hv[1], hv[2], hv[3]);
    uint4 Lo = make_uint4(lv[0], lv[1], lv[2], lv[3]);
    char* d0 = (char*)(dst + (size_t)row * KS_ + c);
    *(uint4*)(d0) = Hv;
    if (wmode == 0) {
        *(uint4*)(d0 + 1024 * 2) = Hv;
        *(uint4*)(d0 + 2048 * 2) = Lo;
    } else {
        *(uint4*)(d0 + 1024 * 2) = Lo;
        *(uint4*)(d0 + 2048 * 2) = Hv;
    }
}

// ===================================================================
// mma.sync bf16 GEMM:  C[M,1024] = A[M,Kp] * W[1024,Kp]^T, fp32 accum.
// 128x128 block, BK=32, 8 warps (2M x 4N), warp tile 64x32.
// 4-stage cp.async pipeline, XOR-swizzled smem, ldmatrix.x4.
// ===================================================================
#define BM 128
#define BN 128
#define BK 32
#define NSTG 4
#define OP_BYTES (BM * 64)              // 8 KB per operand tile (64B rows)
#define STG_BYTES (2 * OP_BYTES)        // 16 KB
#define GEMM_SMEM (NSTG * STG_BYTES)    // 64 KB

__global__ __launch_bounds__(256) void gemm_mma(
    const __nv_bfloat16* __restrict__ A, const __nv_bfloat16* __restrict__ Bw,
    float* __restrict__ C, int Kp)
{
    extern __shared__ char dsm[];
    const uint32_t s0 = smem_u32(dsm);
    const int tid = threadIdx.x;
    const int wid = tid >> 5;
    const int lane = tid & 31;
    const int bx = blockIdx.x, by = blockIdx.y;
    const int NKC = Kp / BK;

    // ---- loader assignments: j=0,1: li = tid + 256*j -> (row, 16B-chunk)
    uint32_t swo[2];
    const char* gsA[2];
    const char* gsB[2];
    #pragma unroll
    for (int j = 0; j < 2; ++j) {
        int li = tid + 256 * j;
        int row = li >> 2;
        int ch = li & 3;
        swo[j] = (uint32_t)(row * 64 + ((ch ^ (row & 3)) << 4));
        gsA[j] = (const char*)(A + (size_t)(by * BM + row) * Kp + ch * 8);
        gsB[j] = (const char*)(Bw + (size_t)(bx * BN + row) * Kp + ch * 8);
    }

    // ---- ldmatrix per-lane geometry
    const int wm = wid >> 2;       // 0..1  (M)
    const int wn = wid & 3;        // 0..3  (N)
    const int lhalf = lane >> 4;   // 0/1 -> k chunk select
    int arow[4], brow[2];
    #pragma unroll
    for (int mt = 0; mt < 4; ++mt) arow[mt] = wm * 64 + mt * 16 + (lane & 15);
    #pragma unroll
    for (int np = 0; np < 2; ++np) brow[np] = wn * 32 + np * 16 + (lane & 15);

    float acc[4][4][4];
    #pragma unroll
    for (int i = 0; i < 4; ++i)
        #pragma unroll
        for (int j = 0; j < 4; ++j)
            #pragma unroll
            for (int q = 0; q < 4; ++q) acc[i][j][q] = 0.f;

    // ---- prologue: stages 0..2
    #pragma unroll
    for (int c = 0; c < NSTG - 1; ++c) {
        uint32_t sb = s0 + c * STG_BYTES;
        #pragma unroll
        for (int j = 0; j < 2; ++j) {
            CP_ASYNC16(sb + swo[j],            gsA[j] + (size_t)c * 64);
            CP_ASYNC16(sb + OP_BYTES + swo[j], gsB[j] + (size_t)c * 64);
        }
        CP_COMMIT();
    }

    for (int kc = 0; kc < NKC; ++kc) {
        const int stage = kc & (NSTG - 1);
        CP_WAIT2();
        __syncthreads();

        // issue stage kc+3 (empty commit keeps group arithmetic uniform)
        {
            int ldc = kc + NSTG - 1;
            if (ldc < NKC) {
                uint32_t sb = s0 + (ldc & (NSTG - 1)) * STG_BYTES;
                #pragma unroll
                for (int j = 0; j < 2; ++j) {
                    CP_ASYNC16(sb + swo[j],            gsA[j] + (size_t)ldc * 64);
                    CP_ASYNC16(sb + OP_BYTES + swo[j], gsB[j] + (size_t)ldc * 64);
                }
            }
            CP_COMMIT();
        }

        const uint32_t ab = s0 + stage * STG_BYTES;
        const uint32_t bb = ab + OP_BYTES;
        #pragma unroll
        for (int ks = 0; ks < 2; ++ks) {
            uint32_t a[4][4], b[4][2];
            #pragma unroll
            for (int mt = 0; mt < 4; ++mt) {
                int row = arow[mt];
                int ch = ks * 2 + lhalf;
                uint32_t ad = ab + row * 64 + (((ch ^ (row & 3))) << 4);
                LDSM_X4(a[mt][0], a[mt][1], a[mt][2], a[mt][3], ad);
            }
            #pragma unroll
            for (int np = 0; np < 2; ++np) {
                int row = brow[np];
                int ch = ks * 2 + lhalf;
                uint32_t bd = bb + row * 64 + (((ch ^ (row & 3))) << 4);
                uint32_t r0, r1, r2, r3;
                LDSM_X4(r0, r1, r2, r3, bd);
                b[np * 2 + 0][0] = r0; b[np * 2 + 0][1] = r2;
                b[np * 2 + 1][0] = r1; b[np * 2 + 1][1] = r3;
            }
            #pragma unroll
            for (int mt = 0; mt < 4; ++mt)
                #pragma unroll
                for (int nt = 0; nt < 4; ++nt)
                    MMA16816(acc[mt][nt][0], acc[mt][nt][1], acc[mt][nt][2], acc[mt][nt][3],
                             a[mt][0], a[mt][1], a[mt][2], a[mt][3],
                             b[nt][0], b[nt][1]);
        }
    }

    // ---- epilogue: direct fp32 stores (float2 per fragment row)
    #pragma unroll
    for (int mt = 0; mt < 4; ++mt) {
        int row0 = by * BM + wm * 64 + mt * 16 + (lane >> 2);
        #pragma unroll
        for (int nt = 0; nt < 4; ++nt) {
            int col = bx * BN + wn * 32 + nt * 8 + (lane & 3) * 2;
            float2* p0 = (float2*)(C + (size_t)row0 * D_ + col);
            float2* p1 = (float2*)(C + (size_t)(row0 + 8) * D_ + col);
            *p0 = make_float2(acc[mt][nt][0], acc[mt][nt][1]);
            *p1 = make_float2(acc[mt][nt][2], acc[mt][nt][3]);
        }
    }
}

// ===================================================================
// RoPE in place on (rows, D) buffer laid out (b, l, h, hd).
// ===================================================================
__global__ void rope_kernel(float* __restrict__ T,
                            const float* __restrict__ cosT,
                            const float* __restrict__ sinT,
                            int rows, int lmod)
{
    int i = blockIdx.x * blockDim.x + threadIdx.x;
    int total = rows * (D_ / 2);
    if (i >= total) return;
    int row = i >> 9;
    int pi  = i & 511;
    int h = pi >> 5;
    int f = pi & 31;
    int l = row % lmod;
    float c = cosT[l * 32 + f];
    float s = sinT[l * 32 + f];
    float* p = T + (size_t)row * D_ + h * HD_ + 2 * f;
    float tr = p[0], ti = p[1];
    p[0] = tr * c - ti * s;
    p[1] = tr * s + ti * c;
}

// ===================================================================
// K_proj/V_proj: out[bh,p,d] = sum_{l<=p} mat[p,l] * KV[b*128+l, h*64+d]
// ===================================================================
__global__ void proj_kernel(const float* __restrict__ Kb, const float* __restrict__ Vb,
                            const float* __restrict__ kpm, const float* __restrict__ vpm,
                            float* __restrict__ Kp, float* __restrict__ Vp)
{
    int p  = blockIdx.x;
    int bh = blockIdx.y;
    int b = bh >> 4, h = bh & 15;
    int d = threadIdx.x;
    const float* kbase = Kb + (size_t)b * P_ * D_ + h * HD_ + d;
    const float* vbase = Vb + (size_t)b * P_ * D_ + h * HD_ + d;
    float ak = 0.f, av = 0.f;
    for (int l = 0; l <= p; ++l) {
        float mk = kpm[p * MAXLEN_ + l];
        float mv = vpm[p * MAXLEN_ + l];
        ak += mk * kbase[(size_t)l * D_];
        av += mv * vbase[(size_t)l * D_];
    }
    size_t o = ((size_t)bh * P_ + p) * HD_ + d;
    Kp[o] = ak;
    Vp[o] = av;
}

// ===================================================================
// Attention (fp32 SIMT, Kp/Vp resident in smem)
// ===================================================================
#define KP_STRIDE 65
#define ATTN_SMEM_FLOATS (2 * P_ * KP_STRIDE + 8 * (HD_ + P_))
#define ATTN_SMEM_BYTES  (ATTN_SMEM_FLOATS * 4)

__global__ __launch_bounds__(256) void attn_kernel(
    const float* __restrict__ Q, const float* __restrict__ Kp,
    const float* __restrict__ Vp, float* __restrict__ Out)
{
    extern __shared__ float smem[];
    float* kp = smem;
    float* vp = smem + P_ * KP_STRIDE;
    const int tid  = threadIdx.x;
    const int lane = tid & 31;
    const int warp = tid >> 5;
    float* qs = smem + 2 * P_ * KP_STRIDE + warp * (HD_ + P_);
    float* ws = qs + HD_;

    const int bh = blockIdx.y;
    const int b = bh >> 4, h = bh & 15;

    const float* kpg = Kp + (size_t)bh * P_ * HD_;
    const float* vpg = Vp + (size_t)bh * P_ * HD_;
    for (int i = tid; i < P_ * HD_; i += 256) {
        int p = i >> 6, d = i & 63;
        kp[p * KP_STRIDE + d] = kpg[i];
        vp[p * KP_STRIDE + d] = vpg[i];
    }
    __syncthreads();

    for (int t = 0; t < 32; ++t) {
        int l = blockIdx.x * 256 + warp * 32 + t;
        const float* qg = Q + ((size_t)b * L_ + l) * D_ + h * HD_;
        qs[lane]      = qg[lane];
        qs[lane + 32] = qg[lane + 32];
        __syncwarp();

        float s[4];
        #pragma unroll
        for (int j = 0; j < 4; ++j) {
            int p = lane + 32 * j;
            const float* krow = kp + p * KP_STRIDE;
            float acc = 0.f;
            #pragma unroll
            for (int d = 0; d < HD_; ++d) acc += krow[d] * qs[d];
            s[j] = (p <= l) ? acc * 0.125f : -INFINITY;
        }
        float m = fmaxf(fmaxf(s[0], s[1]), fmaxf(s[2], s[3]));
        #pragma unroll
        for (int o = 16; o > 0; o >>= 1) m = fmaxf(m, __shfl_xor_sync(0xffffffffu, m, o));
        float e[4], sum = 0.f;
        #pragma unroll
        for (int j = 0; j < 4; ++j) { e[j] = __expf(s[j] - m); sum += e[j]; }
        #pragma unroll
        for (int o = 16; o > 0; o >>= 1) sum += __shfl_xor_sync(0xffffffffu, sum, o);
        float inv = __frcp_rn(sum);
        #pragma unroll
        for (int j = 0; j < 4; ++j) ws[lane + 32 * j] = e[j] * inv;
        __syncwarp();

        float a0 = 0.f, a1 = 0.f;
        #pragma unroll 8
        for (int p = 0; p < P_; ++p) {
            float wv = ws[p];
            a0 += wv * vp[p * KP_STRIDE + lane];
            a1 += wv * vp[p * KP_STRIDE + lane + 32];
        }
        float* og = Out + ((size_t)b * L_ + l) * D_ + h * HD_;
        og[lane]      = a0;
        og[lane + 32] = a1;
        __syncwarp();
    }
}

// ===================================================================
extern "C" void kernel_launch(void* const* d_in, const int* in_sizes, int n_in,
                              void* d_out, int out_size)
{
    const float* x   = (const float*)d_in[0];
    const float* fc  = (const float*)d_in[1];
    const float* fs  = (const float*)d_in[2];
    const float* Wq  = (const float*)d_in[3];
    const float* Wk  = (const float*)d_in[4];
    const float* Wv  = (const float*)d_in[5];
    const float* Wo  = (const float*)d_in[6];
    const float* kpm = (const float*)d_in[7];
    const float* vpm = (const float*)d_in[8];
    float* out = (float*)d_out;

    __nv_bfloat16 *xs, *As, *kvs, *Wq3, *Wk3, *Wv3, *Wo3;
    float *Qp, *Kb, *Vb, *Kpp, *Vpp, *Ap;
    cudaGetSymbolAddress((void**)&xs,  g_xs);
    cudaGetSymbolAddress((void**)&As,  g_As);
    cudaGetSymbolAddress((void**)&kvs, g_kvs);
    cudaGetSymbolAddress((void**)&Wq3, g_Wq3);
    cudaGetSymbolAddress((void**)&Wk3, g_Wk3);
    cudaGetSymbolAddress((void**)&Wv3, g_Wv3);
    cudaGetSymbolAddress((void**)&Wo3, g_Wo3);
    cudaGetSymbolAddress((void**)&Qp,  g_Q);
    cudaGetSymbolAddress((void**)&Kb,  g_K);
    cudaGetSymbolAddress((void**)&Vb,  g_V);
    cudaGetSymbolAddress((void**)&Kpp, g_Kp);
    cudaGetSymbolAddress((void**)&Vpp, g_Vp);
    cudaGetSymbolAddress((void**)&Ap,  g_A);

    cudaFuncSetAttribute(gemm_mma, cudaFuncAttributeMaxDynamicSharedMemorySize, GEMM_SMEM);
    cudaFuncSetAttribute(attn_kernel, cudaFuncAttributeMaxDynamicSharedMemorySize, ATTN_SMEM_BYTES);

    // split conversions
    split_kernel<<<(M_FULL * 128 + 255) / 256, 256>>>(x, xs, M_FULL, M_FULL, M_FULL, 0);
    split_kernel<<<(M_KV * 128 + 255) / 256, 256>>>(x, kvs, M_KV, P_, L_, 0);   // gather l<128
    split_kernel<<<(D_ * 128 + 255) / 256, 256>>>(Wq, Wq3, D_, D_, D_, 1);
    split_kernel<<<(D_ * 128 + 255) / 256, 256>>>(Wk, Wk3, D_, D_, D_, 1);
    split_kernel<<<(D_ * 128 + 255) / 256, 256>>>(Wv, Wv3, D_, D_, D_, 1);
    split_kernel<<<(D_ * 128 + 255) / 256, 256>>>(Wo, Wo3, D_, D_, D_, 1);

    // projections on tensor cores (HMMA)
    gemm_mma<<<dim3(D_ / BN, M_FULL / BM), 256, GEMM_SMEM>>>(xs, Wq3, Qp, KS_);
    gemm_mma<<<dim3(D_ / BN, M_KV / BM), 256, GEMM_SMEM>>>(kvs, Wk3, Kb, KS_);
    gemm_mma<<<dim3(D_ / BN, M_KV / BM), 256, GEMM_SMEM>>>(kvs, Wv3, Vb, KS_);

    // RoPE on Q (pos = l) and K (pos = l, first 128 only)
    rope_kernel<<<(M_FULL * (D_ / 2) + 255) / 256, 256>>>(Qp, fc, fs, M_FULL, L_);
    rope_kernel<<<(M_KV * (D_ / 2) + 255) / 256, 256>>>(Kb, fc, fs, M_KV, P_);

    // low-rank projections (tril-masked)
    proj_kernel<<<dim3(P_, BH_), 64>>>(Kb, Vb, kpm, vpm, Kpp, Vpp);

    // fused attention
    attn_kernel<<<dim3(L_ / 256, BH_), 256, ATTN_SMEM_BYTES>>>(Qp, Kpp, Vpp, Ap);

    // final projection
    split_kernel<<<(M_FULL * 128 + 255) / 256, 256>>>(Ap, As, M_FULL, M_FULL, M_FULL, 0);
    gemm_mma<<<dim3(D_ / BN, M_FULL / BM), 256, GEMM_SMEM>>>(As, Wo3, out, KS_);
}

// round 4
// speedup vs baseline: 2.2767x; 1.4827x over previous
#include <cuda_runtime.h>
#include <cuda_bf16.h>
#include <cuda_fp16.h>
#include <cstdint>

// Problem constants
#define B_  4
#define L_  4096
#define D_  1024
#define H_  16
#define HD_ 64
#define P_  128
#define MAXLEN_ 4096
#define BH_ (B_ * H_)
#define M_FULL (B_ * L_)       // 16384
#define M_KV   (B_ * P_)       // 512
#define KS_    3072            // split K' = 3*D

__device__ __forceinline__ uint32_t smem_u32(const void* p) {
    uint32_t a;
    asm("{ .reg .u64 t; cvta.to.shared.u64 t, %1; cvt.u32.u64 %0, t; }" : "=r"(a) : "l"(p));
    return a;
}
#define CP_ASYNC16(dst, src) \
    asm volatile("cp.async.cg.shared.global [%0], [%1], 16;" :: "r"(dst), "l"(src))
#define CP_COMMIT() asm volatile("cp.async.commit_group;" ::: "memory")
#define CP_WAIT2()  asm volatile("cp.async.wait_group 2;" ::: "memory")

#define LDSM_X4(R0, R1, R2, R3, A) \
    asm volatile("ldmatrix.sync.aligned.m8n8.x4.shared.b16 {%0,%1,%2,%3}, [%4];" \
        : "=r"(R0), "=r"(R1), "=r"(R2), "=r"(R3) : "r"(A))

#define MMA16816(D0, D1, D2, D3, A0, A1, A2, A3, B0, B1) \
    asm volatile("mma.sync.aligned.m16n8k16.row.col.f32.bf16.bf16.f32 " \
        "{%0,%1,%2,%3}, {%4,%5,%6,%7}, {%8,%9}, {%0,%1,%2,%3};" \
        : "+f"(D0), "+f"(D1), "+f"(D2), "+f"(D3) \
        : "r"(A0), "r"(A1), "r"(A2), "r"(A3), "r"(B0), "r"(B1))

#define MMAF16(D0, D1, D2, D3, A0, A1, A2, A3, B0, B1) \
    asm volatile("mma.sync.aligned.m16n8k16.row.col.f32.f16.f16.f32 " \
        "{%0,%1,%2,%3}, {%4,%5,%6,%7}, {%8,%9}, {%0,%1,%2,%3};" \
        : "+f"(D0), "+f"(D1), "+f"(D2), "+f"(D3) \
        : "r"(A0), "r"(A1), "r"(A2), "r"(A3), "r"(B0), "r"(B1))

// -------- scratch (no allocation allowed -> device globals) --------
__device__ __nv_bfloat16 g_xs [M_FULL * (size_t)KS_];  // 96 MB  [hi|hi|lo]
__device__ __nv_bfloat16 g_As [M_FULL * (size_t)KS_];  // 96 MB
__device__ __nv_bfloat16 g_kvs[M_KV   * (size_t)KS_];  // 3 MB
__device__ __nv_bfloat16 g_Wq3[D_ * (size_t)KS_];      // 6 MB   [hi|lo|hi]
__device__ __nv_bfloat16 g_Wk3[D_ * (size_t)KS_];
__device__ __nv_bfloat16 g_Wv3[D_ * (size_t)KS_];
__device__ __nv_bfloat16 g_Wo3[D_ * (size_t)KS_];
__device__ float g_Q [M_FULL * (size_t)D_];            // 64 MB
__device__ float g_K [M_KV   * (size_t)D_];
__device__ float g_V [M_KV   * (size_t)D_];
__device__ float g_Kp[BH_ * P_ * HD_];
__device__ float g_Vp[BH_ * P_ * HD_];

// ===================================================================
// split: fp32 (rows x 1024) -> bf16 (rows x 3072)
// ===================================================================
__global__ __launch_bounds__(256) void split_kernel(
    const float* __restrict__ src, __nv_bfloat16* __restrict__ dst,
    int rows, int rpb, int bstride, int wmode)
{
    int i = blockIdx.x * 256 + threadIdx.x;
    if (i >= rows * 128) return;
    int row = i >> 7;
    int c = (i & 127) * 8;
    int srow = (row / rpb) * bstride + (row % rpb);
    const float4* s = (const float4*)(src + (size_t)srow * D_ + c);
    float4 f0 = s[0], f1 = s[1];
    float f[8] = {f0.x, f0.y, f0.z, f0.w, f1.x, f1.y, f1.z, f1.w};
    uint32_t hv[4], lv[4];
    #pragma unroll
    for (int j = 0; j < 4; ++j) {
        __nv_bfloat16 h0 = __float2bfloat16(f[2*j]);
        __nv_bfloat16 h1 = __float2bfloat16(f[2*j+1]);
        __nv_bfloat16 l0 = __float2bfloat16(f[2*j]   - __bfloat162float(h0));
        __nv_bfloat16 l1 = __float2bfloat16(f[2*j+1] - __bfloat162float(h1));
        hv[j] = (uint32_t)__bfloat16_as_ushort(h0) | ((uint32_t)__bfloat16_as_ushort(h1) << 16);
        lv[j] = (uint32_t)__bfloat16_as_ushort(l0) | ((uint32_t)__bfloat16_as_ushort(l1) << 16);
    }
    uint4 Hv = make_uint4(hv[0], hv[1], hv[2], hv[3]);
    uint4 Lo = make_uint4(lv[0], lv[1], lv[2], lv[3]);
    char* d0 = (char*)(dst + (size_t)row * KS_ + c);
    *(uint4*)(d0) = Hv;
    if (wmode == 0) {
        *(uint4*)(d0 + 1024 * 2) = Hv;
        *(uint4*)(d0 + 2048 * 2) = Lo;
    } else {
        *(uint4*)(d0 + 1024 * 2) = Lo;
        *(uint4*)(d0 + 2048 * 2) = Hv;
    }
}

// ===================================================================
// mma.sync bf16 GEMM + optional fused RoPE epilogue
// ===================================================================
#define BM 128
#define BN 128
#define BK 32
#define NSTG 4
#define OP_BYTES (BM * 64)
#define STG_BYTES (2 * OP_BYTES)
#define GEMM_SMEM (NSTG * STG_BYTES)

__global__ __launch_bounds__(256) void gemm_mma(
    const __nv_bfloat16* __restrict__ A, const __nv_bfloat16* __restrict__ Bw,
    float* __restrict__ C, int Kp,
    const float* __restrict__ rcos, const float* __restrict__ rsin, int lmask)
{
    extern __shared__ char dsm[];
    const uint32_t s0 = smem_u32(dsm);
    const int tid = threadIdx.x;
    const int wid = tid >> 5;
    const int lane = tid & 31;
    const int bx = blockIdx.x, by = blockIdx.y;
    const int NKC = Kp / BK;

    uint32_t swo[2];
    const char* gsA[2];
    const char* gsB[2];
    #pragma unroll
    for (int j = 0; j < 2; ++j) {
        int li = tid + 256 * j;
        int row = li >> 2;
        int ch = li & 3;
        swo[j] = (uint32_t)(row * 64 + ((ch ^ (row & 3)) << 4));
        gsA[j] = (const char*)(A + (size_t)(by * BM + row) * Kp + ch * 8);
        gsB[j] = (const char*)(Bw + (size_t)(bx * BN + row) * Kp + ch * 8);
    }

    const int wm = wid >> 2;
    const int wn = wid & 3;
    const int lhalf = lane >> 4;
    int arow[4], brow[2];
    #pragma unroll
    for (int mt = 0; mt < 4; ++mt) arow[mt] = wm * 64 + mt * 16 + (lane & 15);
    #pragma unroll
    for (int np = 0; np < 2; ++np) brow[np] = wn * 32 + np * 16 + (lane & 15);

    float acc[4][4][4];
    #pragma unroll
    for (int i = 0; i < 4; ++i)
        #pragma unroll
        for (int j = 0; j < 4; ++j)
            #pragma unroll
            for (int q = 0; q < 4; ++q) acc[i][j][q] = 0.f;

    #pragma unroll
    for (int c = 0; c < NSTG - 1; ++c) {
        uint32_t sb = s0 + c * STG_BYTES;
        #pragma unroll
        for (int j = 0; j < 2; ++j) {
            CP_ASYNC16(sb + swo[j],            gsA[j] + (size_t)c * 64);
            CP_ASYNC16(sb + OP_BYTES + swo[j], gsB[j] + (size_t)c * 64);
        }
        CP_COMMIT();
    }

    for (int kc = 0; kc < NKC; ++kc) {
        const int stage = kc & (NSTG - 1);
        CP_WAIT2();
        __syncthreads();
        {
            int ldc = kc + NSTG - 1;
            if (ldc < NKC) {
                uint32_t sb = s0 + (ldc & (NSTG - 1)) * STG_BYTES;
                #pragma unroll
                for (int j = 0; j < 2; ++j) {
                    CP_ASYNC16(sb + swo[j],            gsA[j] + (size_t)ldc * 64);
                    CP_ASYNC16(sb + OP_BYTES + swo[j], gsB[j] + (size_t)ldc * 64);
                }
            }
            CP_COMMIT();
        }

        const uint32_t ab = s0 + stage * STG_BYTES;
        const uint32_t bb = ab + OP_BYTES;
        #pragma unroll
        for (int ks = 0; ks < 2; ++ks) {
            uint32_t a[4][4], b[4][2];
            #pragma unroll
            for (int mt = 0; mt < 4; ++mt) {
                int row = arow[mt];
                int ch = ks * 2 + lhalf;
                uint32_t ad = ab + row * 64 + (((ch ^ (row & 3))) << 4);
                LDSM_X4(a[mt][0], a[mt][1], a[mt][2], a[mt][3], ad);
            }
            #pragma unroll
            for (int np = 0; np < 2; ++np) {
                int row = brow[np];
                int ch = ks * 2 + lhalf;
                uint32_t bd = bb + row * 64 + (((ch ^ (row & 3))) << 4);
                uint32_t r0, r1, r2, r3;
                LDSM_X4(r0, r1, r2, r3, bd);
                b[np * 2 + 0][0] = r0; b[np * 2 + 0][1] = r2;
                b[np * 2 + 1][0] = r1; b[np * 2 + 1][1] = r3;
            }
            #pragma unroll
            for (int mt = 0; mt < 4; ++mt)
                #pragma unroll
                for (int nt = 0; nt < 4; ++nt)
                    MMA16816(acc[mt][nt][0], acc[mt][nt][1], acc[mt][nt][2], acc[mt][nt][3],
                             a[mt][0], a[mt][1], a[mt][2], a[mt][3],
                             b[nt][0], b[nt][1]);
        }
    }

    // epilogue with optional fused RoPE (acc pairs (c0,c1)/(c2,c3) are (2f,2f+1) col pairs)
    #pragma unroll
    for (int mt = 0; mt < 4; ++mt) {
        int row0 = by * BM + wm * 64 + mt * 16 + (lane >> 2);
        if (rcos != nullptr) {
            int la = row0 & lmask;
            int lb = (row0 + 8) & lmask;
            #pragma unroll
            for (int nt = 0; nt < 4; ++nt) {
                int col = bx * BN + wn * 32 + nt * 8 + (lane & 3) * 2;
                int f = (col & 63) >> 1;
                float ca = rcos[la * 32 + f], sa = rsin[la * 32 + f];
                float cb = rcos[lb * 32 + f], sb = rsin[lb * 32 + f];
                float a0 = acc[mt][nt][0], a1 = acc[mt][nt][1];
                acc[mt][nt][0] = a0 * ca - a1 * sa;
                acc[mt][nt][1] = a0 * sa + a1 * ca;
                a0 = acc[mt][nt][2]; a1 = acc[mt][nt][3];
                acc[mt][nt][2] = a0 * cb - a1 * sb;
                acc[mt][nt][3] = a0 * sb + a1 * cb;
            }
        }
        #pragma unroll
        for (int nt = 0; nt < 4; ++nt) {
            int col = bx * BN + wn * 32 + nt * 8 + (lane & 3) * 2;
            float2* p0 = (float2*)(C + (size_t)row0 * D_ + col);
            float2* p1 = (float2*)(C + (size_t)(row0 + 8) * D_ + col);
            *p0 = make_float2(acc[mt][nt][0], acc[mt][nt][1]);
            *p1 = make_float2(acc[mt][nt][2], acc[mt][nt][3]);
        }
    }
}

// ===================================================================
// K_proj/V_proj: out[bh,p,d] = sum_{l<=p} mat[p,l] * KV[b*128+l, h*64+d]
// ===================================================================
__global__ void proj_kernel(const float* __restrict__ Kb, const float* __restrict__ Vb,
                            const float* __restrict__ kpm, const float* __restrict__ vpm,
                            float* __restrict__ Kp, float* __restrict__ Vp)
{
    int p  = blockIdx.x;
    int bh = blockIdx.y;
    int b = bh >> 4, h = bh & 15;
    int d = threadIdx.x;
    const float* kbase = Kb + (size_t)b * P_ * D_ + h * HD_ + d;
    const float* vbase = Vb + (size_t)b * P_ * D_ + h * HD_ + d;
    float ak = 0.f, av = 0.f;
    for (int l = 0; l <= p; ++l) {
        float mk = kpm[p * MAXLEN_ + l];
        float mv = vpm[p * MAXLEN_ + l];
        ak += mk * kbase[(size_t)l * D_];
        av += mv * vbase[(size_t)l * D_];
    }
    size_t o = ((size_t)bh * P_ + p) * HD_ + d;
    Kp[o] = ak;
    Vp[o] = av;
}

// ===================================================================
// Attention on fp16 tensor cores. One CTA = (128 l's) x (one bh).
// S = Q*Kp^T (K=64), softmax (fragment shfl + cross-warp smem),
// O = P*Vp (K=128). Output written directly as 3-term bf16 split (As).
// smem: padded-stride fp16 tiles (stride shifts 4 banks/row -> LDSM clean)
// ===================================================================
#define QH_OFF   0                      // 128 x 72 half  = 18432
#define KH_OFF   18432                  // 128 x 72 half  = 18432
#define VT_OFF   36864                  // 64  x 136 half = 17408 (V transposed)
#define PH_OFF   54272                  // 128 x 136 half = 34816
#define REDM_OFF 89088                  // 512 f32
#define REDS_OFF 91136                  // 512 f32
#define ATT_SMEM 93184

__global__ __launch_bounds__(256) void attn_mma(
    const float* __restrict__ Q, const float* __restrict__ Kp,
    const float* __restrict__ Vp, __nv_bfloat16* __restrict__ As)
{
    extern __shared__ char sm[];
    const uint32_t s0 = smem_u32(sm);
    const int tid = threadIdx.x;
    const int lane = tid & 31;
    const int wid = tid >> 5;
    const int wm = wid >> 2;           // 0..1
    const int wn = wid & 3;            // 0..3
    const int lhalf = lane >> 4;
    const int bh = blockIdx.y;
    const int b = bh >> 4, h = bh & 15;
    const int l0 = blockIdx.x * 128;

    // ---- load & convert tiles
    const float* qg = Q + ((size_t)(b * L_ + l0)) * D_ + h * HD_;
    const float* kg = Kp + (size_t)bh * P_ * HD_;
    const float* vg = Vp + (size_t)bh * P_ * HD_;
    #pragma unroll
    for (int t = 0; t < 8; ++t) {
        int e = t * 256 + tid;
        int r = e >> 4;
        int d0 = (e & 15) * 4;
        float4 v = *(const float4*)(qg + (size_t)r * D_ + d0);
        __half2* dq = (__half2*)(sm + QH_OFF + (r * 72 + d0) * 2);
        dq[0] = __floats2half2_rn(v.x, v.y);
        dq[1] = __floats2half2_rn(v.z, v.w);
        float4 k = *(const float4*)(kg + r * HD_ + d0);
        __half2* dk = (__half2*)(sm + KH_OFF + (r * 72 + d0) * 2);
        dk[0] = __floats2half2_rn(k.x, k.y);
        dk[1] = __floats2half2_rn(k.z, k.w);
        float4 w = *(const float4*)(vg + r * HD_ + d0);
        __half* vt = (__half*)(sm + VT_OFF);
        vt[(d0 + 0) * 136 + r] = __float2half_rn(w.x);
        vt[(d0 + 1) * 136 + r] = __float2half_rn(w.y);
        vt[(d0 + 2) * 136 + r] = __float2half_rn(w.z);
        vt[(d0 + 3) * 136 + r] = __float2half_rn(w.w);
    }
    __syncthreads();

    // ---- S = Q * Kp^T  (M=128 N=128 K=64), warp tile 64x32
    float sc[4][4][4];
    #pragma unroll
    for (int i = 0; i < 4; ++i)
        #pragma unroll
        for (int j = 0; j < 4; ++j)
            #pragma unroll
            for (int q = 0; q < 4; ++q) sc[i][j][q] = 0.f;

    #pragma unroll
    for (int kc = 0; kc < 4; ++kc) {
        uint32_t a[4][4], bfr[4][2];
        #pragma unroll
        for (int mt = 0; mt < 4; ++mt) {
            uint32_t ad = s0 + QH_OFF + ((wm * 64 + mt * 16 + (lane & 15)) * 72) * 2
                        + (kc * 2 + lhalf) * 16;
            LDSM_X4(a[mt][0], a[mt][1], a[mt][2], a[mt][3], ad);
        }
        #pragma unroll
        for (int np = 0; np < 2; ++np) {
            uint32_t bd = s0 + KH_OFF + ((wn * 32 + np * 16 + (lane & 15)) * 72) * 2
                        + (kc * 2 + lhalf) * 16;
            uint32_t r0, r1, r2, r3;
            LDSM_X4(r0, r1, r2, r3, bd);
            bfr[np * 2 + 0][0] = r0; bfr[np * 2 + 0][1] = r2;
            bfr[np * 2 + 1][0] = r1; bfr[np * 2 + 1][1] = r3;
        }
        #pragma unroll
        for (int mt = 0; mt < 4; ++mt)
            #pragma unroll
            for (int nt = 0; nt < 4; ++nt)
                MMAF16(sc[mt][nt][0], sc[mt][nt][1], sc[mt][nt][2], sc[mt][nt][3],
                       a[mt][0], a[mt][1], a[mt][2], a[mt][3],
                       bfr[nt][0], bfr[nt][1]);
    }

    // ---- scale + causal mask (only first l-tile has p > l cases)
    const bool dom = (blockIdx.x == 0);
    #pragma unroll
    for (int mt = 0; mt < 4; ++mt) {
        int r0 = wm * 64 + mt * 16 + (lane >> 2);
        #pragma unroll
        for (int nt = 0; nt < 4; ++nt) {
            int c0 = wn * 32 + nt * 8 + (lane & 3) * 2;
            #pragma unroll
            for (int q = 0; q < 4; ++q) {
                sc[mt][nt][q] *= 0.125f;
                if (dom) {
                    int rr = r0 + ((q >= 2) ? 8 : 0);
                    int cc = c0 + (q & 1);
                    if (cc > rr) sc[mt][nt][q] = -1e30f;
                }
            }
        }
    }

    float* redm = (float*)(sm + REDM_OFF);
    float* reds = (float*)(sm + REDS_OFF);

    // ---- row max (partial within warp -> smem -> combine)
    #pragma unroll
    for (int mt = 0; mt < 4; ++mt) {
        float mlo = -1e30f, mhi = -1e30f;
        #pragma unroll
        for (int nt = 0; nt < 4; ++nt) {
            mlo = fmaxf(mlo, fmaxf(sc[mt][nt][0], sc[mt][nt][1]));
            mhi = fmaxf(mhi, fmaxf(sc[mt][nt][2], sc[mt][nt][3]));
        }
        #pragma unroll
        for (int o = 1; o <= 2; o <<= 1) {
            mlo = fmaxf(mlo, __shfl_xor_sync(0xffffffffu, mlo, o));
            mhi = fmaxf(mhi, __shfl_xor_sync(0xffffffffu, mhi, o));
        }
        if ((lane & 3) == 0) {
            int r0 = wm * 64 + mt * 16 + (lane >> 2);
            redm[wn * 128 + r0] = mlo;
            redm[wn * 128 + r0 + 8] = mhi;
        }
    }
    __syncthreads();

    // ---- exp + row sum
    #pragma unroll
    for (int mt = 0; mt < 4; ++mt) {
        int r0 = wm * 64 + mt * 16 + (lane >> 2);
        float mlo = fmaxf(fmaxf(redm[r0], redm[128 + r0]),
                          fmaxf(redm[256 + r0], redm[384 + r0]));
        int r1 = r0 + 8;
        float mhi = fmaxf(fmaxf(redm[r1], redm[128 + r1]),
                          fmaxf(redm[256 + r1], redm[384 + r1]));
        float slo = 0.f, shi = 0.f;
        #pragma unroll
        for (int nt = 0; nt < 4; ++nt) {
            sc[mt][nt][0] = __expf(sc[mt][nt][0] - mlo);
            sc[mt][nt][1] = __expf(sc[mt][nt][1] - mlo);
            sc[mt][nt][2] = __expf(sc[mt][nt][2] - mhi);
            sc[mt][nt][3] = __expf(sc[mt][nt][3] - mhi);
            slo += sc[mt][nt][0] + sc[mt][nt][1];
            shi += sc[mt][nt][2] + sc[mt][nt][3];
        }
        #pragma unroll
        for (int o = 1; o <= 2; o <<= 1) {
            slo += __shfl_xor_sync(0xffffffffu, slo, o);
            shi += __shfl_xor_sync(0xffffffffu, shi, o);
        }
        if ((lane & 3) == 0) {
            reds[wn * 128 + r0] = slo;
            reds[wn * 128 + r0 + 8] = shi;
        }
    }
    __syncthreads();

    // ---- normalize -> fp16 P tile [l][p] (stride 136)
    #pragma unroll
    for (int mt = 0; mt < 4; ++mt) {
        int r0 = wm * 64 + mt * 16 + (lane >> 2);
        int r1 = r0 + 8;
        float ilo = __frcp_rn(reds[r0] + reds[128 + r0] + reds[256 + r0] + reds[384 + r0]);
        float ihi = __frcp_rn(reds[r1] + reds[128 + r1] + reds[256 + r1] + reds[384 + r1]);
        #pragma unroll
        for (int nt = 0; nt < 4; ++nt) {
            int c0 = wn * 32 + nt * 8 + (lane & 3) * 2;
            *(__half2*)(sm + PH_OFF + (r0 * 136 + c0) * 2) =
                __floats2half2_rn(sc[mt][nt][0] * ilo, sc[mt][nt][1] * ilo);
            *(__half2*)(sm + PH_OFF + (r1 * 136 + c0) * 2) =
                __floats2half2_rn(sc[mt][nt][2] * ihi, sc[mt][nt][3] * ihi);
        }
    }
    __syncthreads();

    // ---- O = P * Vp  (M=128 N=64 K=128), warp tile 64x16
    float oc[4][2][4];
    #pragma unroll
    for (int i = 0; i < 4; ++i)
        #pragma unroll
        for (int j = 0; j < 2; ++j)
            #pragma unroll
            for (int q = 0; q < 4; ++q) oc[i][j][q] = 0.f;

    #pragma unroll
    for (int kc = 0; kc < 8; ++kc) {
        uint32_t a[4][4], bfr[2][2];
        #pragma unroll
        for (int mt = 0; mt < 4; ++mt) {
            uint32_t ad = s0 + PH_OFF + ((wm * 64 + mt * 16 + (lane & 15)) * 136) * 2
                        + (kc * 2 + lhalf) * 16;
            LDSM_X4(a[mt][0], a[mt][1], a[mt][2], a[mt][3], ad);
        }
        {
            uint32_t bd = s0 + VT_OFF + ((wn * 16 + (lane & 15)) * 136) * 2
                        + (kc * 2 + lhalf) * 16;
            uint32_t r0, r1, r2, r3;
            LDSM_X4(r0, r1, r2, r3, bd);
            bfr[0][0] = r0; bfr[0][1] = r2;
            bfr[1][0] = r1; bfr[1][1] = r3;
        }
        #pragma unroll
        for (int mt = 0; mt < 4; ++mt)
            #pragma unroll
            for (int nt = 0; nt < 2; ++nt)
                MMAF16(oc[mt][nt][0], oc[mt][nt][1], oc[mt][nt][2], oc[mt][nt][3],
                       a[mt][0], a[mt][1], a[mt][2], a[mt][3],
                       bfr[nt][0], bfr[nt][1]);
    }

    // ---- store as 3-term bf16 split [hi | hi | lo] feeding the Wo GEMM
    #pragma unroll
    for (int mt = 0; mt < 4; ++mt) {
        int r0 = wm * 64 + mt * 16 + (lane >> 2);
        #pragma unroll
        for (int nt = 0; nt < 2; ++nt) {
            int cd = wn * 16 + nt * 8 + (lane & 3) * 2;
            size_t grow0 = (size_t)(b * L_ + l0 + r0) * KS_;
            size_t grow1 = (size_t)(b * L_ + l0 + r0 + 8) * KS_;
            int gcol = h * HD_ + cd;
            #pragma unroll
            for (int half = 0; half < 2; ++half) {
                float o0 = oc[mt][nt][half * 2 + 0];
                float o1 = oc[mt][nt][half * 2 + 1];
                __nv_bfloat16 h0 = __float2bfloat16(o0);
                __nv_bfloat16 h1 = __float2bfloat16(o1);
                __nv_bfloat16 e0 = __float2bfloat16(o0 - __bfloat162float(h0));
                __nv_bfloat16 e1 = __float2bfloat16(o1 - __bfloat162float(h1));
                uint32_t hi = (uint32_t)__bfloat16_as_ushort(h0)
                            | ((uint32_t)__bfloat16_as_ushort(h1) << 16);
                uint32_t lo = (uint32_t)__bfloat16_as_ushort(e0)
                            | ((uint32_t)__bfloat16_as_ushort(e1) << 16);
                __nv_bfloat16* base = As + (half ? grow1 : grow0) + gcol;
                *(uint32_t*)(base) = hi;
                *(uint32_t*)(base + 1024) = hi;
                *(uint32_t*)(base + 2048) = lo;
            }
        }
    }
}

// ===================================================================
extern "C" void kernel_launch(void* const* d_in, const int* in_sizes, int n_in,
                              void* d_out, int out_size)
{
    const float* x   = (const float*)d_in[0];
    const float* fc  = (const float*)d_in[1];
    const float* fs  = (const float*)d_in[2];
    const float* Wq  = (const float*)d_in[3];
    const float* Wk  = (const float*)d_in[4];
    const float* Wv  = (const float*)d_in[5];
    const float* Wo  = (const float*)d_in[6];
    const float* kpm = (const float*)d_in[7];
    const float* vpm = (const float*)d_in[8];
    float* out = (float*)d_out;

    __nv_bfloat16 *xs, *As, *kvs, *Wq3, *Wk3, *Wv3, *Wo3;
    float *Qp, *Kb, *Vb, *Kpp, *Vpp;
    cudaGetSymbolAddress((void**)&xs,  g_xs);
    cudaGetSymbolAddress((void**)&As,  g_As);
    cudaGetSymbolAddress((void**)&kvs, g_kvs);
    cudaGetSymbolAddress((void**)&Wq3, g_Wq3);
    cudaGetSymbolAddress((void**)&Wk3, g_Wk3);
    cudaGetSymbolAddress((void**)&Wv3, g_Wv3);
    cudaGetSymbolAddress((void**)&Wo3, g_Wo3);
    cudaGetSymbolAddress((void**)&Qp,  g_Q);
    cudaGetSymbolAddress((void**)&Kb,  g_K);
    cudaGetSymbolAddress((void**)&Vb,  g_V);
    cudaGetSymbolAddress((void**)&Kpp, g_Kp);
    cudaGetSymbolAddress((void**)&Vpp, g_Vp);

    cudaFuncSetAttribute(gemm_mma, cudaFuncAttributeMaxDynamicSharedMemorySize, GEMM_SMEM);
    cudaFuncSetAttribute(attn_mma, cudaFuncAttributeMaxDynamicSharedMemorySize, ATT_SMEM);

    // split conversions
    split_kernel<<<(M_FULL * 128 + 255) / 256, 256>>>(x, xs, M_FULL, M_FULL, M_FULL, 0);
    split_kernel<<<(M_KV * 128 + 255) / 256, 256>>>(x, kvs, M_KV, P_, L_, 0);
    split_kernel<<<(D_ * 128 + 255) / 256, 256>>>(Wq, Wq3, D_, D_, D_, 1);
    split_kernel<<<(D_ * 128 + 255) / 256, 256>>>(Wk, Wk3, D_, D_, D_, 1);
    split_kernel<<<(D_ * 128 + 255) / 256, 256>>>(Wv, Wv3, D_, D_, D_, 1);
    split_kernel<<<(D_ * 128 + 255) / 256, 256>>>(Wo, Wo3, D_, D_, D_, 1);

    // projections (RoPE fused into Q and K epilogues)
    gemm_mma<<<dim3(D_ / BN, M_FULL / BM), 256, GEMM_SMEM>>>(xs, Wq3, Qp, KS_, fc, fs, L_ - 1);
    gemm_mma<<<dim3(D_ / BN, M_KV / BM), 256, GEMM_SMEM>>>(kvs, Wk3, Kb, KS_, fc, fs, P_ - 1);
    gemm_mma<<<dim3(D_ / BN, M_KV / BM), 256, GEMM_SMEM>>>(kvs, Wv3, Vb, KS_, nullptr, nullptr, 0);

    // low-rank projections (tril-masked)
    proj_kernel<<<dim3(P_, BH_), 64>>>(Kb, Vb, kpm, vpm, Kpp, Vpp);

    // fp16 tensor-core attention -> bf16 split output
    attn_mma<<<dim3(L_ / 128, BH_), 256, ATT_SMEM>>>(Qp, Kpp, Vpp, As);

    // final projection
    gemm_mma<<<dim3(D_ / BN, M_FULL / BM), 256, GEMM_SMEM>>>(As, Wo3, out, KS_, nullptr, nullptr, 0);
}

// round 5
// speedup vs baseline: 3.6532x; 1.6046x over previous
#include <cuda_runtime.h>
#include <cuda_bf16.h>
#include <cuda_fp16.h>
#include <cstdint>

// Problem constants
#define B_  4
#define L_  4096
#define D_  1024
#define H_  16
#define HD_ 64
#define P_  128
#define MAXLEN_ 4096
#define BH_ (B_ * H_)
#define M_FULL (B_ * L_)       // 16384
#define M_KV   (B_ * P_)       // 512

__device__ __forceinline__ uint32_t smem_u32(const void* p) {
    uint32_t a;
    asm("{ .reg .u64 t; cvta.to.shared.u64 t, %1; cvt.u32.u64 %0, t; }" : "=r"(a) : "l"(p));
    return a;
}
#define CP_ASYNC16(dst, src) \
    asm volatile("cp.async.cg.shared.global [%0], [%1], 16;" :: "r"(dst), "l"(src))
#define CP_COMMIT() asm volatile("cp.async.commit_group;" ::: "memory")
#define CP_WAIT2()  asm volatile("cp.async.wait_group 2;" ::: "memory")

#define LDSM_X4(R0, R1, R2, R3, A) \
    asm volatile("ldmatrix.sync.aligned.m8n8.x4.shared.b16 {%0,%1,%2,%3}, [%4];" \
        : "=r"(R0), "=r"(R1), "=r"(R2), "=r"(R3) : "r"(A))

#define MMAF16(D0, D1, D2, D3, A0, A1, A2, A3, B0, B1) \
    asm volatile("mma.sync.aligned.m16n8k16.row.col.f32.f16.f16.f32 " \
        "{%0,%1,%2,%3}, {%4,%5,%6,%7}, {%8,%9}, {%0,%1,%2,%3};" \
        : "+f"(D0), "+f"(D1), "+f"(D2), "+f"(D3) \
        : "r"(A0), "r"(A1), "r"(A2), "r"(A3), "r"(B0), "r"(B1))

// -------- scratch (no allocation allowed -> device globals) --------
__device__ __half g_xh [M_FULL * (size_t)D_];   // 32 MB  fp16 activations
__device__ __half g_As [M_FULL * (size_t)D_];   // 32 MB  attention output fp16
__device__ __half g_kvh[M_KV   * (size_t)D_];   // 1 MB   gathered first-128 rows
__device__ __half g_Wq2[D_ * (size_t)(2 * D_)]; // 4 MB   [Whi | Wlo]
__device__ __half g_Wk2[D_ * (size_t)(2 * D_)];
__device__ __half g_Wv2[D_ * (size_t)(2 * D_)];
__device__ __half g_Wo2[D_ * (size_t)(2 * D_)];
__device__ __half g_Q [M_FULL * (size_t)D_];    // 32 MB  rope'd Q fp16
__device__ float g_K [M_KV   * (size_t)D_];
__device__ float g_V [M_KV   * (size_t)D_];
__device__ float g_Kp[BH_ * P_ * HD_];
__device__ float g_Vp[BH_ * P_ * HD_];

// ===================================================================
// conv_x: fp32 (rows x 1024, optional row gather) -> fp16 (rows x 1024)
// ===================================================================
__global__ __launch_bounds__(256) void conv_x(
    const float* __restrict__ src, __half* __restrict__ dst,
    int rows, int rpb, int bstride)
{
    int i = blockIdx.x * 256 + threadIdx.x;
    if (i >= rows * 128) return;
    int row = i >> 7;
    int c = (i & 127) * 8;
    int srow = (row / rpb) * bstride + (row % rpb);
    const float4* s = (const float4*)(src + (size_t)srow * D_ + c);
    float4 f0 = s[0], f1 = s[1];
    __half2 h[4];
    h[0] = __floats2half2_rn(f0.x, f0.y);
    h[1] = __floats2half2_rn(f0.z, f0.w);
    h[2] = __floats2half2_rn(f1.x, f1.y);
    h[3] = __floats2half2_rn(f1.z, f1.w);
    *(uint4*)(dst + (size_t)row * D_ + c) = *(uint4*)h;
}

// ===================================================================
// conv_w: fp32 W (1024 x 1024) -> fp16 [Whi | Wlo] (1024 x 2048)
// ===================================================================
__global__ __launch_bounds__(256) void conv_w(
    const float* __restrict__ src, __half* __restrict__ dst)
{
    int i = blockIdx.x * 256 + threadIdx.x;
    if (i >= D_ * 128) return;
    int row = i >> 7;
    int c = (i & 127) * 8;
    const float4* s = (const float4*)(src + (size_t)row * D_ + c);
    float4 f0 = s[0], f1 = s[1];
    float f[8] = {f0.x, f0.y, f0.z, f0.w, f1.x, f1.y, f1.z, f1.w};
    __half hi[8], lo[8];
    #pragma unroll
    for (int j = 0; j < 8; ++j) {
        hi[j] = __float2half_rn(f[j]);
        lo[j] = __float2half_rn(f[j] - __half2float(hi[j]));
    }
    *(uint4*)(dst + (size_t)row * (2 * D_) + c)      = *(uint4*)hi;
    *(uint4*)(dst + (size_t)row * (2 * D_) + D_ + c) = *(uint4*)lo;
}

// ===================================================================
// fp16 mma GEMM: C[M,1024] = A[M,1024] * (Whi+Wlo)[1024,2048]^T
// A columns cycled twice (kc & 15). BM=BN=128, BK=64, 4-stage cp.async.
// Optional fused RoPE; fp32 or fp16 output.
// ===================================================================
#define BM 128
#define BN 128
#define BK 64
#define NSTG 4
#define NKC2 32                          // K' = 2048 / 64
#define OP_BYTES (BM * 128)              // 16 KB per operand tile (128B rows)
#define STG_BYTES (2 * OP_BYTES)         // 32 KB
#define GEMM_SMEM (NSTG * STG_BYTES)     // 128 KB

__global__ __launch_bounds__(256) void gemm_f16(
    const __half* __restrict__ A, const __half* __restrict__ W2,
    float* __restrict__ Cf, __half* __restrict__ Ch,
    const float* __restrict__ rcos, const float* __restrict__ rsin, int lmask)
{
    extern __shared__ char dsm[];
    const uint32_t s0 = smem_u32(dsm);
    const int tid = threadIdx.x;
    const int wid = tid >> 5;
    const int lane = tid & 31;
    const int bx = blockIdx.x, by = blockIdx.y;

    // loader: j=0..3 -> (row, 16B-chunk) per operand; 8 chunks per 128B row
    uint32_t swo[4];
    const char* gsA[4];
    const char* gsB[4];
    #pragma unroll
    for (int j = 0; j < 4; ++j) {
        int li = tid + 256 * j;
        int row = li >> 3;
        int ch = li & 7;
        swo[j] = (uint32_t)(row * 128 + ((ch ^ (row & 7)) << 4));
        gsA[j] = (const char*)(A + (size_t)(by * BM + row) * D_ + ch * 8);
        gsB[j] = (const char*)(W2 + (size_t)(bx * BN + row) * (2 * D_) + ch * 8);
    }

    const int wm = wid >> 2;
    const int wn = wid & 3;
    const int lhalf = lane >> 4;
    int arow[4], brow[2];
    #pragma unroll
    for (int mt = 0; mt < 4; ++mt) arow[mt] = wm * 64 + mt * 16 + (lane & 15);
    #pragma unroll
    for (int np = 0; np < 2; ++np) brow[np] = wn * 32 + np * 16 + (lane & 15);

    float acc[4][4][4];
    #pragma unroll
    for (int i = 0; i < 4; ++i)
        #pragma unroll
        for (int j = 0; j < 4; ++j)
            #pragma unroll
            for (int q = 0; q < 4; ++q) acc[i][j][q] = 0.f;

    // prologue: stages 0..2 (A col offset = (c&15)*64 halfs = c*64 here)
    #pragma unroll
    for (int c = 0; c < NSTG - 1; ++c) {
        uint32_t sb = s0 + c * STG_BYTES;
        #pragma unroll
        for (int j = 0; j < 4; ++j) {
            CP_ASYNC16(sb + swo[j],            gsA[j] + (size_t)c * 128);
            CP_ASYNC16(sb + OP_BYTES + swo[j], gsB[j] + (size_t)c * 128);
        }
        CP_COMMIT();
    }

    for (int kc = 0; kc < NKC2; ++kc) {
        const int stage = kc & (NSTG - 1);
        CP_WAIT2();
        __syncthreads();
        {
            int ldc = kc + NSTG - 1;
            if (ldc < NKC2) {
                uint32_t sb = s0 + (ldc & (NSTG - 1)) * STG_BYTES;
                size_t aoff = (size_t)(ldc & 15) * 128;   // cycle A cols twice
                size_t boff = (size_t)ldc * 128;
                #pragma unroll
                for (int j = 0; j < 4; ++j) {
                    CP_ASYNC16(sb + swo[j],            gsA[j] + aoff);
                    CP_ASYNC16(sb + OP_BYTES + swo[j], gsB[j] + boff);
                }
            }
            CP_COMMIT();
        }

        const uint32_t ab = s0 + stage * STG_BYTES;
        const uint32_t bb = ab + OP_BYTES;
        #pragma unroll
        for (int ks = 0; ks < 4; ++ks) {
            uint32_t a[4][4], b[4][2];
            #pragma unroll
            for (int mt = 0; mt < 4; ++mt) {
                int row = arow[mt];
                int ch = ks * 2 + lhalf;
                uint32_t ad = ab + row * 128 + (((ch ^ (row & 7))) << 4);
                LDSM_X4(a[mt][0], a[mt][1], a[mt][2], a[mt][3], ad);
            }
            #pragma unroll
            for (int np = 0; np < 2; ++np) {
                int row = brow[np];
                int ch = ks * 2 + lhalf;
                uint32_t bd = bb + row * 128 + (((ch ^ (row & 7))) << 4);
                uint32_t r0, r1, r2, r3;
                LDSM_X4(r0, r1, r2, r3, bd);
                b[np * 2 + 0][0] = r0; b[np * 2 + 0][1] = r2;
                b[np * 2 + 1][0] = r1; b[np * 2 + 1][1] = r3;
            }
            #pragma unroll
            for (int mt = 0; mt < 4; ++mt)
                #pragma unroll
                for (int nt = 0; nt < 4; ++nt)
                    MMAF16(acc[mt][nt][0], acc[mt][nt][1], acc[mt][nt][2], acc[mt][nt][3],
                           a[mt][0], a[mt][1], a[mt][2], a[mt][3],
                           b[nt][0], b[nt][1]);
        }
    }

    // epilogue: optional RoPE (col pairs (2f,2f+1)), fp32 or fp16 store
    #pragma unroll
    for (int mt = 0; mt < 4; ++mt) {
        int row0 = by * BM + wm * 64 + mt * 16 + (lane >> 2);
        if (rcos != nullptr) {
            int la = row0 & lmask;
            int lb = (row0 + 8) & lmask;
            #pragma unroll
            for (int nt = 0; nt < 4; ++nt) {
                int col = bx * BN + wn * 32 + nt * 8 + (lane & 3) * 2;
                int f = (col & 63) >> 1;
                float ca = rcos[la * 32 + f], sa = rsin[la * 32 + f];
                float cb = rcos[lb * 32 + f], sb = rsin[lb * 32 + f];
                float a0 = acc[mt][nt][0], a1 = acc[mt][nt][1];
                acc[mt][nt][0] = a0 * ca - a1 * sa;
                acc[mt][nt][1] = a0 * sa + a1 * ca;
                a0 = acc[mt][nt][2]; a1 = acc[mt][nt][3];
                acc[mt][nt][2] = a0 * cb - a1 * sb;
                acc[mt][nt][3] = a0 * sb + a1 * cb;
            }
        }
        #pragma unroll
        for (int nt = 0; nt < 4; ++nt) {
            int col = bx * BN + wn * 32 + nt * 8 + (lane & 3) * 2;
            if (Ch != nullptr) {
                *(__half2*)(Ch + (size_t)row0 * D_ + col) =
                    __floats2half2_rn(acc[mt][nt][0], acc[mt][nt][1]);
                *(__half2*)(Ch + (size_t)(row0 + 8) * D_ + col) =
                    __floats2half2_rn(acc[mt][nt][2], acc[mt][nt][3]);
            } else {
                *(float2*)(Cf + (size_t)row0 * D_ + col) =
                    make_float2(acc[mt][nt][0], acc[mt][nt][1]);
                *(float2*)(Cf + (size_t)(row0 + 8) * D_ + col) =
                    make_float2(acc[mt][nt][2], acc[mt][nt][3]);
            }
        }
    }
}

// ===================================================================
// K_proj/V_proj: out[bh,p,d] = sum_{l<=p} mat[p,l] * KV[b*128+l, h*64+d]
// ===================================================================
__global__ void proj_kernel(const float* __restrict__ Kb, const float* __restrict__ Vb,
                            const float* __restrict__ kpm, const float* __restrict__ vpm,
                            float* __restrict__ Kp, float* __restrict__ Vp)
{
    int p  = blockIdx.x;
    int bh = blockIdx.y;
    int b = bh >> 4, h = bh & 15;
    int d = threadIdx.x;
    const float* kbase = Kb + (size_t)b * P_ * D_ + h * HD_ + d;
    const float* vbase = Vb + (size_t)b * P_ * D_ + h * HD_ + d;
    float ak = 0.f, av = 0.f;
    for (int l = 0; l <= p; ++l) {
        float mk = kpm[p * MAXLEN_ + l];
        float mv = vpm[p * MAXLEN_ + l];
        ak += mk * kbase[(size_t)l * D_];
        av += mv * vbase[(size_t)l * D_];
    }
    size_t o = ((size_t)bh * P_ + p) * HD_ + d;
    Kp[o] = ak;
    Vp[o] = av;
}

// ===================================================================
// Attention on fp16 tensor cores. One CTA = 128 l's x one bh.
// Q already fp16. Output single fp16 to As.
// ===================================================================
#define QH_OFF   0                      // 128 x 72 half  = 18432
#define KH_OFF   18432                  // 128 x 72 half  = 18432
#define VT_OFF   36864                  // 64  x 136 half = 17408 (V transposed)
#define PH_OFF   54272                  // 128 x 136 half = 34816
#define REDM_OFF 89088                  // 512 f32
#define REDS_OFF 91136                  // 512 f32
#define ATT_SMEM 93184

__global__ __launch_bounds__(256) void attn_mma(
    const __half* __restrict__ Q, const float* __restrict__ Kp,
    const float* __restrict__ Vp, __half* __restrict__ As)
{
    extern __shared__ char sm[];
    const uint32_t s0 = smem_u32(sm);
    const int tid = threadIdx.x;
    const int lane = tid & 31;
    const int wid = tid >> 5;
    const int wm = wid >> 2;
    const int wn = wid & 3;
    const int lhalf = lane >> 4;
    const int bh = blockIdx.y;
    const int b = bh >> 4, h = bh & 15;
    const int l0 = blockIdx.x * 128;

    // ---- Q tile (fp16 memcpy into stride-72 smem)
    const __half* qg = Q + ((size_t)(b * L_ + l0)) * D_ + h * HD_;
    #pragma unroll
    for (int t = 0; t < 4; ++t) {
        int e = t * 256 + tid;          // 1024 = 128 rows x 8 chunks
        int r = e >> 3;
        int c = (e & 7) * 8;
        uint4 v = *(const uint4*)(qg + (size_t)r * D_ + c);
        *(uint4*)(sm + QH_OFF + (r * 72 + c) * 2) = v;
    }
    // ---- K tile fp32->fp16, V tile fp32->fp16 transposed
    const float* kg = Kp + (size_t)bh * P_ * HD_;
    const float* vg = Vp + (size_t)bh * P_ * HD_;
    #pragma unroll
    for (int t = 0; t < 8; ++t) {
        int e = t * 256 + tid;          // 2048 = 128 rows x 16 float4
        int r = e >> 4;
        int d0 = (e & 15) * 4;
        float4 k = *(const float4*)(kg + r * HD_ + d0);
        __half2* dk = (__half2*)(sm + KH_OFF + (r * 72 + d0) * 2);
        dk[0] = __floats2half2_rn(k.x, k.y);
        dk[1] = __floats2half2_rn(k.z, k.w);
        float4 w = *(const float4*)(vg + r * HD_ + d0);
        __half* vt = (__half*)(sm + VT_OFF);
        vt[(d0 + 0) * 136 + r] = __float2half_rn(w.x);
        vt[(d0 + 1) * 136 + r] = __float2half_rn(w.y);
        vt[(d0 + 2) * 136 + r] = __float2half_rn(w.z);
        vt[(d0 + 3) * 136 + r] = __float2half_rn(w.w);
    }
    __syncthreads();

    // ---- S = Q * Kp^T
    float sc[4][4][4];
    #pragma unroll
    for (int i = 0; i < 4; ++i)
        #pragma unroll
        for (int j = 0; j < 4; ++j)
            #pragma unroll
            for (int q = 0; q < 4; ++q) sc[i][j][q] = 0.f;

    #pragma unroll
    for (int kc = 0; kc < 4; ++kc) {
        uint32_t a[4][4], bfr[4][2];
        #pragma unroll
        for (int mt = 0; mt < 4; ++mt) {
            uint32_t ad = s0 + QH_OFF + ((wm * 64 + mt * 16 + (lane & 15)) * 72) * 2
                        + (kc * 2 + lhalf) * 16;
            LDSM_X4(a[mt][0], a[mt][1], a[mt][2], a[mt][3], ad);
        }
        #pragma unroll
        for (int np = 0; np < 2; ++np) {
            uint32_t bd = s0 + KH_OFF + ((wn * 32 + np * 16 + (lane & 15)) * 72) * 2
                        + (kc * 2 + lhalf) * 16;
            uint32_t r0, r1, r2, r3;
            LDSM_X4(r0, r1, r2, r3, bd);
            bfr[np * 2 + 0][0] = r0; bfr[np * 2 + 0][1] = r2;
            bfr[np * 2 + 1][0] = r1; bfr[np * 2 + 1][1] = r3;
        }
        #pragma unroll
        for (int mt = 0; mt < 4; ++mt)
            #pragma unroll
            for (int nt = 0; nt < 4; ++nt)
                MMAF16(sc[mt][nt][0], sc[mt][nt][1], sc[mt][nt][2], sc[mt][nt][3],
                       a[mt][0], a[mt][1], a[mt][2], a[mt][3],
                       bfr[nt][0], bfr[nt][1]);
    }

    // ---- scale + causal mask
    const bool dom = (blockIdx.x == 0);
    #pragma unroll
    for (int mt = 0; mt < 4; ++mt) {
        int r0 = wm * 64 + mt * 16 + (lane >> 2);
        #pragma unroll
        for (int nt = 0; nt < 4; ++nt) {
            int c0 = wn * 32 + nt * 8 + (lane & 3) * 2;
            #pragma unroll
            for (int q = 0; q < 4; ++q) {
                sc[mt][nt][q] *= 0.125f;
                if (dom) {
                    int rr = r0 + ((q >= 2) ? 8 : 0);
                    int cc = c0 + (q & 1);
                    if (cc > rr) sc[mt][nt][q] = -1e30f;
                }
            }
        }
    }

    float* redm = (float*)(sm + REDM_OFF);
    float* reds = (float*)(sm + REDS_OFF);

    #pragma unroll
    for (int mt = 0; mt < 4; ++mt) {
        float mlo = -1e30f, mhi = -1e30f;
        #pragma unroll
        for (int nt = 0; nt < 4; ++nt) {
            mlo = fmaxf(mlo, fmaxf(sc[mt][nt][0], sc[mt][nt][1]));
            mhi = fmaxf(mhi, fmaxf(sc[mt][nt][2], sc[mt][nt][3]));
        }
        #pragma unroll
        for (int o = 1; o <= 2; o <<= 1) {
            mlo = fmaxf(mlo, __shfl_xor_sync(0xffffffffu, mlo, o));
            mhi = fmaxf(mhi, __shfl_xor_sync(0xffffffffu, mhi, o));
        }
        if ((lane & 3) == 0) {
            int r0 = wm * 64 + mt * 16 + (lane >> 2);
            redm[wn * 128 + r0] = mlo;
            redm[wn * 128 + r0 + 8] = mhi;
        }
    }
    __syncthreads();

    #pragma unroll
    for (int mt = 0; mt < 4; ++mt) {
        int r0 = wm * 64 + mt * 16 + (lane >> 2);
        float mlo = fmaxf(fmaxf(redm[r0], redm[128 + r0]),
                          fmaxf(redm[256 + r0], redm[384 + r0]));
        int r1 = r0 + 8;
        float mhi = fmaxf(fmaxf(redm[r1], redm[128 + r1]),
                          fmaxf(redm[256 + r1], redm[384 + r1]));
        float slo = 0.f, shi = 0.f;
        #pragma unroll
        for (int nt = 0; nt < 4; ++nt) {
            sc[mt][nt][0] = __expf(sc[mt][nt][0] - mlo);
            sc[mt][nt][1] = __expf(sc[mt][nt][1] - mlo);
            sc[mt][nt][2] = __expf(sc[mt][nt][2] - mhi);
            sc[mt][nt][3] = __expf(sc[mt][nt][3] - mhi);
            slo += sc[mt][nt][0] + sc[mt][nt][1];
            shi += sc[mt][nt][2] + sc[mt][nt][3];
        }
        #pragma unroll
        for (int o = 1; o <= 2; o <<= 1) {
            slo += __shfl_xor_sync(0xffffffffu, slo, o);
            shi += __shfl_xor_sync(0xffffffffu, shi, o);
        }
        if ((lane & 3) == 0) {
            reds[wn * 128 + r0] = slo;
            reds[wn * 128 + r0 + 8] = shi;
        }
    }
    __syncthreads();

    #pragma unroll
    for (int mt = 0; mt < 4; ++mt) {
        int r0 = wm * 64 + mt * 16 + (lane >> 2);
        int r1 = r0 + 8;
        float ilo = __frcp_rn(reds[r0] + reds[128 + r0] + reds[256 + r0] + reds[384 + r0]);
        float ihi = __frcp_rn(reds[r1] + reds[128 + r1] + reds[256 + r1] + reds[384 + r1]);
        #pragma unroll
        for (int nt = 0; nt < 4; ++nt) {
            int c0 = wn * 32 + nt * 8 + (lane & 3) * 2;
            *(__half2*)(sm + PH_OFF + (r0 * 136 + c0) * 2) =
                __floats2half2_rn(sc[mt][nt][0] * ilo, sc[mt][nt][1] * ilo);
            *(__half2*)(sm + PH_OFF + (r1 * 136 + c0) * 2) =
                __floats2half2_rn(sc[mt][nt][2] * ihi, sc[mt][nt][3] * ihi);
        }
    }
    __syncthreads();

    // ---- O = P * Vp
    float oc[4][2][4];
    #pragma unroll
    for (int i = 0; i < 4; ++i)
        #pragma unroll
        for (int j = 0; j < 2; ++j)
            #pragma unroll
            for (int q = 0; q < 4; ++q) oc[i][j][q] = 0.f;

    #pragma unroll
    for (int kc = 0; kc < 8; ++kc) {
        uint32_t a[4][4], bfr[2][2];
        #pragma unroll
        for (int mt = 0; mt < 4; ++mt) {
            uint32_t ad = s0 + PH_OFF + ((wm * 64 + mt * 16 + (lane & 15)) * 136) * 2
                        + (kc * 2 + lhalf) * 16;
            LDSM_X4(a[mt][0], a[mt][1], a[mt][2], a[mt][3], ad);
        }
        {
            uint32_t bd = s0 + VT_OFF + ((wn * 16 + (lane & 15)) * 136) * 2
                        + (kc * 2 + lhalf) * 16;
            uint32_t r0, r1, r2, r3;
            LDSM_X4(r0, r1, r2, r3, bd);
            bfr[0][0] = r0; bfr[0][1] = r2;
            bfr[1][0] = r1; bfr[1][1] = r3;
        }
        #pragma unroll
        for (int mt = 0; mt < 4; ++mt)
            #pragma unroll
            for (int nt = 0; nt < 2; ++nt)
                MMAF16(oc[mt][nt][0], oc[mt][nt][1], oc[mt][nt][2], oc[mt][nt][3],
                       a[mt][0], a[mt][1], a[mt][2], a[mt][3],
                       bfr[nt][0], bfr[nt][1]);
    }

    // ---- store single fp16 to As
    #pragma unroll
    for (int mt = 0; mt < 4; ++mt) {
        int r0 = wm * 64 + mt * 16 + (lane >> 2);
        #pragma unroll
        for (int nt = 0; nt < 2; ++nt) {
            int cd = wn * 16 + nt * 8 + (lane & 3) * 2;
            int gcol = h * HD_ + cd;
            *(__half2*)(As + (size_t)(b * L_ + l0 + r0) * D_ + gcol) =
                __floats2half2_rn(oc[mt][nt][0], oc[mt][nt][1]);
            *(__half2*)(As + (size_t)(b * L_ + l0 + r0 + 8) * D_ + gcol) =
                __floats2half2_rn(oc[mt][nt][2], oc[mt][nt][3]);
        }
    }
}

// ===================================================================
extern "C" void kernel_launch(void* const* d_in, const int* in_sizes, int n_in,
                              void* d_out, int out_size)
{
    const float* x   = (const float*)d_in[0];
    const float* fc  = (const float*)d_in[1];
    const float* fs  = (const float*)d_in[2];
    const float* Wq  = (const float*)d_in[3];
    const float* Wk  = (const float*)d_in[4];
    const float* Wv  = (const float*)d_in[5];
    const float* Wo  = (const float*)d_in[6];
    const float* kpm = (const float*)d_in[7];
    const float* vpm = (const float*)d_in[8];
    float* out = (float*)d_out;

    __half *xh, *As, *kvh, *Wq2, *Wk2, *Wv2, *Wo2, *Qh;
    float *Kb, *Vb, *Kpp, *Vpp;
    cudaGetSymbolAddress((void**)&xh,  g_xh);
    cudaGetSymbolAddress((void**)&As,  g_As);
    cudaGetSymbolAddress((void**)&kvh, g_kvh);
    cudaGetSymbolAddress((void**)&Wq2, g_Wq2);
    cudaGetSymbolAddress((void**)&Wk2, g_Wk2);
    cudaGetSymbolAddress((void**)&Wv2, g_Wv2);
    cudaGetSymbolAddress((void**)&Wo2, g_Wo2);
    cudaGetSymbolAddress((void**)&Qh,  g_Q);
    cudaGetSymbolAddress((void**)&Kb,  g_K);
    cudaGetSymbolAddress((void**)&Vb,  g_V);
    cudaGetSymbolAddress((void**)&Kpp, g_Kp);
    cudaGetSymbolAddress((void**)&Vpp, g_Vp);

    cudaFuncSetAttribute(gemm_f16, cudaFuncAttributeMaxDynamicSharedMemorySize, GEMM_SMEM);
    cudaFuncSetAttribute(attn_mma, cudaFuncAttributeMaxDynamicSharedMemorySize, ATT_SMEM);

    // conversions
    conv_x<<<(M_FULL * 128 + 255) / 256, 256>>>(x, xh, M_FULL, M_FULL, M_FULL);
    conv_x<<<(M_KV * 128 + 255) / 256, 256>>>(x, kvh, M_KV, P_, L_);
    conv_w<<<(D_ * 128 + 255) / 256, 256>>>(Wq, Wq2);
    conv_w<<<(D_ * 128 + 255) / 256, 256>>>(Wk, Wk2);
    conv_w<<<(D_ * 128 + 255) / 256, 256>>>(Wv, Wv2);
    conv_w<<<(D_ * 128 + 255) / 256, 256>>>(Wo, Wo2);

    // projections: Q (rope, fp16 out), K (rope, fp32), V (fp32)
    gemm_f16<<<dim3(D_ / BN, M_FULL / BM), 256, GEMM_SMEM>>>(xh, Wq2, nullptr, Qh, fc, fs, L_ - 1);
    gemm_f16<<<dim3(D_ / BN, M_KV / BM), 256, GEMM_SMEM>>>(kvh, Wk2, Kb, nullptr, fc, fs, P_ - 1);
    gemm_f16<<<dim3(D_ / BN, M_KV / BM), 256, GEMM_SMEM>>>(kvh, Wv2, Vb, nullptr, nullptr, nullptr, 0);

    // low-rank projections (tril-masked)
    proj_kernel<<<dim3(P_, BH_), 64>>>(Kb, Vb, kpm, vpm, Kpp, Vpp);

    // fp16 tensor-core attention -> fp16 output
    attn_mma<<<dim3(L_ / 128, BH_), 256, ATT_SMEM>>>(Qh, Kpp, Vpp, As);

    // final projection (fp32 out)
    gemm_f16<<<dim3(D_ / BN, M_FULL / BM), 256, GEMM_SMEM>>>(As, Wo2, out, nullptr, nullptr, nullptr, 0);
}

// round 6
// speedup vs baseline: 5.7809x; 1.5824x over previous
#include <cuda_runtime.h>
#include <cuda_bf16.h>
#include <cuda_fp16.h>
#include <cstdint>

// Problem constants
#define B_  4
#define L_  4096
#define D_  1024
#define H_  16
#define HD_ 64
#define P_  128
#define MAXLEN_ 4096
#define BH_ (B_ * H_)
#define M_FULL (B_ * L_)       // 16384
#define M_KV   (B_ * P_)       // 512

__device__ __forceinline__ uint32_t smem_u32(const void* p) {
    uint32_t a;
    asm("{ .reg .u64 t; cvta.to.shared.u64 t, %1; cvt.u32.u64 %0, t; }" : "=r"(a) : "l"(p));
    return a;
}
#define CP_ASYNC16(dst, src) \
    asm volatile("cp.async.cg.shared.global [%0], [%1], 16;" :: "r"(dst), "l"(src))
#define CP_COMMIT() asm volatile("cp.async.commit_group;" ::: "memory")
#define CP_WAIT2()  asm volatile("cp.async.wait_group 2;" ::: "memory")

#define LDSM_X4(R0, R1, R2, R3, A) \
    asm volatile("ldmatrix.sync.aligned.m8n8.x4.shared.b16 {%0,%1,%2,%3}, [%4];" \
        : "=r"(R0), "=r"(R1), "=r"(R2), "=r"(R3) : "r"(A))

#define MMAF16(D0, D1, D2, D3, A0, A1, A2, A3, B0, B1) \
    asm volatile("mma.sync.aligned.m16n8k16.row.col.f32.f16.f16.f32 " \
        "{%0,%1,%2,%3}, {%4,%5,%6,%7}, {%8,%9}, {%0,%1,%2,%3};" \
        : "+f"(D0), "+f"(D1), "+f"(D2), "+f"(D3) \
        : "r"(A0), "r"(A1), "r"(A2), "r"(A3), "r"(B0), "r"(B1))

// -------- scratch (no allocation allowed -> device globals) --------
__device__ __half g_xh [M_FULL * (size_t)D_];   // 32 MB  fp16 activations
__device__ __half g_As [M_FULL * (size_t)D_];   // 32 MB  attention output fp16
__device__ __half g_kvh[M_KV   * (size_t)D_];   // 1 MB   gathered first-128 rows
__device__ __half g_Wq2[D_ * (size_t)D_];       // 2 MB   fp16 weights
__device__ __half g_Wk2[D_ * (size_t)D_];
__device__ __half g_Wv2[D_ * (size_t)D_];
__device__ __half g_Wo2[D_ * (size_t)D_];
__device__ __half g_Q [M_FULL * (size_t)D_];    // 32 MB  rope'd Q fp16
__device__ float g_K [M_KV   * (size_t)D_];
__device__ float g_V [M_KV   * (size_t)D_];
__device__ float g_Kp[BH_ * P_ * HD_];
__device__ float g_Vp[BH_ * P_ * HD_];

// ===================================================================
// conv_x: fp32 (rows x 1024, optional row gather) -> fp16 (rows x 1024)
// (also used for weights: identity remap)
// ===================================================================
__global__ __launch_bounds__(256) void conv_x(
    const float* __restrict__ src, __half* __restrict__ dst,
    int rows, int rpb, int bstride)
{
    int i = blockIdx.x * 256 + threadIdx.x;
    if (i >= rows * 128) return;
    int row = i >> 7;
    int c = (i & 127) * 8;
    int srow = (row / rpb) * bstride + (row % rpb);
    const float4* s = (const float4*)(src + (size_t)srow * D_ + c);
    float4 f0 = s[0], f1 = s[1];
    __half2 h[4];
    h[0] = __floats2half2_rn(f0.x, f0.y);
    h[1] = __floats2half2_rn(f0.z, f0.w);
    h[2] = __floats2half2_rn(f1.x, f1.y);
    h[3] = __floats2half2_rn(f1.z, f1.w);
    *(uint4*)(dst + (size_t)row * D_ + c) = *(uint4*)h;
}

// ===================================================================
// fp16 mma GEMM: C[M,1024] = A[M,1024] * W[1024,1024]^T, fp32 accum.
// BM=BN=128, BK=64, 4-stage cp.async, XOR swizzle, 8 warps (2x4).
// Optional fused RoPE; fp32 or fp16 output.
// ===================================================================
#define BM 128
#define BN 128
#define BK 64
#define NSTG 4
#define NKC 16                           // K = 1024 / 64
#define OP_BYTES (BM * 128)              // 16 KB per operand tile (128B rows)
#define STG_BYTES (2 * OP_BYTES)         // 32 KB
#define GEMM_SMEM (NSTG * STG_BYTES)     // 128 KB

__global__ __launch_bounds__(256) void gemm_f16(
    const __half* __restrict__ A, const __half* __restrict__ W,
    float* __restrict__ Cf, __half* __restrict__ Ch,
    const float* __restrict__ rcos, const float* __restrict__ rsin, int lmask)
{
    extern __shared__ char dsm[];
    const uint32_t s0 = smem_u32(dsm);
    const int tid = threadIdx.x;
    const int wid = tid >> 5;
    const int lane = tid & 31;
    const int bx = blockIdx.x, by = blockIdx.y;

    // loader: j=0..3 -> (row, 16B-chunk) per operand; 8 chunks per 128B row
    uint32_t swo[4];
    const char* gsA[4];
    const char* gsB[4];
    #pragma unroll
    for (int j = 0; j < 4; ++j) {
        int li = tid + 256 * j;
        int row = li >> 3;
        int ch = li & 7;
        swo[j] = (uint32_t)(row * 128 + ((ch ^ (row & 7)) << 4));
        gsA[j] = (const char*)(A + (size_t)(by * BM + row) * D_ + ch * 8);
        gsB[j] = (const char*)(W + (size_t)(bx * BN + row) * D_ + ch * 8);
    }

    const int wm = wid >> 2;
    const int wn = wid & 3;
    const int lhalf = lane >> 4;
    int arow[4], brow[2];
    #pragma unroll
    for (int mt = 0; mt < 4; ++mt) arow[mt] = wm * 64 + mt * 16 + (lane & 15);
    #pragma unroll
    for (int np = 0; np < 2; ++np) brow[np] = wn * 32 + np * 16 + (lane & 15);

    float acc[4][4][4];
    #pragma unroll
    for (int i = 0; i < 4; ++i)
        #pragma unroll
        for (int j = 0; j < 4; ++j)
            #pragma unroll
            for (int q = 0; q < 4; ++q) acc[i][j][q] = 0.f;

    // prologue: stages 0..2
    #pragma unroll
    for (int c = 0; c < NSTG - 1; ++c) {
        uint32_t sb = s0 + c * STG_BYTES;
        #pragma unroll
        for (int j = 0; j < 4; ++j) {
            CP_ASYNC16(sb + swo[j],            gsA[j] + (size_t)c * 128);
            CP_ASYNC16(sb + OP_BYTES + swo[j], gsB[j] + (size_t)c * 128);
        }
        CP_COMMIT();
    }

    for (int kc = 0; kc < NKC; ++kc) {
        const int stage = kc & (NSTG - 1);
        CP_WAIT2();
        __syncthreads();
        {
            int ldc = kc + NSTG - 1;
            if (ldc < NKC) {
                uint32_t sb = s0 + (ldc & (NSTG - 1)) * STG_BYTES;
                size_t off = (size_t)ldc * 128;
                #pragma unroll
                for (int j = 0; j < 4; ++j) {
                    CP_ASYNC16(sb + swo[j],            gsA[j] + off);
                    CP_ASYNC16(sb + OP_BYTES + swo[j], gsB[j] + off);
                }
            }
            CP_COMMIT();
        }

        const uint32_t ab = s0 + stage * STG_BYTES;
        const uint32_t bb = ab + OP_BYTES;
        #pragma unroll
        for (int ks = 0; ks < 4; ++ks) {
            uint32_t a[4][4], b[4][2];
            #pragma unroll
            for (int mt = 0; mt < 4; ++mt) {
                int row = arow[mt];
                int ch = ks * 2 + lhalf;
                uint32_t ad = ab + row * 128 + (((ch ^ (row & 7))) << 4);
                LDSM_X4(a[mt][0], a[mt][1], a[mt][2], a[mt][3], ad);
            }
            #pragma unroll
            for (int np = 0; np < 2; ++np) {
                int row = brow[np];
                int ch = ks * 2 + lhalf;
                uint32_t bd = bb + row * 128 + (((ch ^ (row & 7))) << 4);
                uint32_t r0, r1, r2, r3;
                LDSM_X4(r0, r1, r2, r3, bd);
                b[np * 2 + 0][0] = r0; b[np * 2 + 0][1] = r2;
                b[np * 2 + 1][0] = r1; b[np * 2 + 1][1] = r3;
            }
            #pragma unroll
            for (int mt = 0; mt < 4; ++mt)
                #pragma unroll
                for (int nt = 0; nt < 4; ++nt)
                    MMAF16(acc[mt][nt][0], acc[mt][nt][1], acc[mt][nt][2], acc[mt][nt][3],
                           a[mt][0], a[mt][1], a[mt][2], a[mt][3],
                           b[nt][0], b[nt][1]);
        }
    }

    // epilogue: optional RoPE (col pairs (2f,2f+1)), fp32 or fp16 store
    #pragma unroll
    for (int mt = 0; mt < 4; ++mt) {
        int row0 = by * BM + wm * 64 + mt * 16 + (lane >> 2);
        if (rcos != nullptr) {
            int la = row0 & lmask;
            int lb = (row0 + 8) & lmask;
            #pragma unroll
            for (int nt = 0; nt < 4; ++nt) {
                int col = bx * BN + wn * 32 + nt * 8 + (lane & 3) * 2;
                int f = (col & 63) >> 1;
                float ca = rcos[la * 32 + f], sa = rsin[la * 32 + f];
                float cb = rcos[lb * 32 + f], sb = rsin[lb * 32 + f];
                float a0 = acc[mt][nt][0], a1 = acc[mt][nt][1];
                acc[mt][nt][0] = a0 * ca - a1 * sa;
                acc[mt][nt][1] = a0 * sa + a1 * ca;
                a0 = acc[mt][nt][2]; a1 = acc[mt][nt][3];
                acc[mt][nt][2] = a0 * cb - a1 * sb;
                acc[mt][nt][3] = a0 * sb + a1 * cb;
            }
        }
        #pragma unroll
        for (int nt = 0; nt < 4; ++nt) {
            int col = bx * BN + wn * 32 + nt * 8 + (lane & 3) * 2;
            if (Ch != nullptr) {
                *(__half2*)(Ch + (size_t)row0 * D_ + col) =
                    __floats2half2_rn(acc[mt][nt][0], acc[mt][nt][1]);
                *(__half2*)(Ch + (size_t)(row0 + 8) * D_ + col) =
                    __floats2half2_rn(acc[mt][nt][2], acc[mt][nt][3]);
            } else {
                *(float2*)(Cf + (size_t)row0 * D_ + col) =
                    make_float2(acc[mt][nt][0], acc[mt][nt][1]);
                *(float2*)(Cf + (size_t)(row0 + 8) * D_ + col) =
                    make_float2(acc[mt][nt][2], acc[mt][nt][3]);
            }
        }
    }
}

// ===================================================================
// K_proj/V_proj: out[bh,p,d] = sum_{l<=p} mat[p,l] * KV[b*128+l, h*64+d]
// ===================================================================
__global__ void proj_kernel(const float* __restrict__ Kb, const float* __restrict__ Vb,
                            const float* __restrict__ kpm, const float* __restrict__ vpm,
                            float* __restrict__ Kp, float* __restrict__ Vp)
{
    int p  = blockIdx.x;
    int bh = blockIdx.y;
    int b = bh >> 4, h = bh & 15;
    int d = threadIdx.x;
    const float* kbase = Kb + (size_t)b * P_ * D_ + h * HD_ + d;
    const float* vbase = Vb + (size_t)b * P_ * D_ + h * HD_ + d;
    float ak = 0.f, av = 0.f;
    for (int l = 0; l <= p; ++l) {
        float mk = kpm[p * MAXLEN_ + l];
        float mv = vpm[p * MAXLEN_ + l];
        ak += mk * kbase[(size_t)l * D_];
        av += mv * vbase[(size_t)l * D_];
    }
    size_t o = ((size_t)bh * P_ + p) * HD_ + d;
    Kp[o] = ak;
    Vp[o] = av;
}

// ===================================================================
// Attention on fp16 tensor cores. One CTA = 128 l's x one bh.
// ===================================================================
#define QH_OFF   0                      // 128 x 72 half  = 18432
#define KH_OFF   18432                  // 128 x 72 half  = 18432
#define VT_OFF   36864                  // 64  x 136 half = 17408 (V transposed)
#define PH_OFF   54272                  // 128 x 136 half = 34816
#define REDM_OFF 89088                  // 512 f32
#define REDS_OFF 91136                  // 512 f32
#define ATT_SMEM 93184

__global__ __launch_bounds__(256) void attn_mma(
    const __half* __restrict__ Q, const float* __restrict__ Kp,
    const float* __restrict__ Vp, __half* __restrict__ As)
{
    extern __shared__ char sm[];
    const uint32_t s0 = smem_u32(sm);
    const int tid = threadIdx.x;
    const int lane = tid & 31;
    const int wid = tid >> 5;
    const int wm = wid >> 2;
    const int wn = wid & 3;
    const int lhalf = lane >> 4;
    const int bh = blockIdx.y;
    const int b = bh >> 4, h = bh & 15;
    const int l0 = blockIdx.x * 128;

    const __half* qg = Q + ((size_t)(b * L_ + l0)) * D_ + h * HD_;
    #pragma unroll
    for (int t = 0; t < 4; ++t) {
        int e = t * 256 + tid;
        int r = e >> 3;
        int c = (e & 7) * 8;
        uint4 v = *(const uint4*)(qg + (size_t)r * D_ + c);
        *(uint4*)(sm + QH_OFF + (r * 72 + c) * 2) = v;
    }
    const float* kg = Kp + (size_t)bh * P_ * HD_;
    const float* vg = Vp + (size_t)bh * P_ * HD_;
    #pragma unroll
    for (int t = 0; t < 8; ++t) {
        int e = t * 256 + tid;
        int r = e >> 4;
        int d0 = (e & 15) * 4;
        float4 k = *(const float4*)(kg + r * HD_ + d0);
        __half2* dk = (__half2*)(sm + KH_OFF + (r * 72 + d0) * 2);
        dk[0] = __floats2half2_rn(k.x, k.y);
        dk[1] = __floats2half2_rn(k.z, k.w);
        float4 w = *(const float4*)(vg + r * HD_ + d0);
        __half* vt = (__half*)(sm + VT_OFF);
        vt[(d0 + 0) * 136 + r] = __float2half_rn(w.x);
        vt[(d0 + 1) * 136 + r] = __float2half_rn(w.y);
        vt[(d0 + 2) * 136 + r] = __float2half_rn(w.z);
        vt[(d0 + 3) * 136 + r] = __float2half_rn(w.w);
    }
    __syncthreads();

    // S = Q * Kp^T
    float sc[4][4][4];
    #pragma unroll
    for (int i = 0; i < 4; ++i)
        #pragma unroll
        for (int j = 0; j < 4; ++j)
            #pragma unroll
            for (int q = 0; q < 4; ++q) sc[i][j][q] = 0.f;

    #pragma unroll
    for (int kc = 0; kc < 4; ++kc) {
        uint32_t a[4][4], bfr[4][2];
        #pragma unroll
        for (int mt = 0; mt < 4; ++mt) {
            uint32_t ad = s0 + QH_OFF + ((wm * 64 + mt * 16 + (lane & 15)) * 72) * 2
                        + (kc * 2 + lhalf) * 16;
            LDSM_X4(a[mt][0], a[mt][1], a[mt][2], a[mt][3], ad);
        }
        #pragma unroll
        for (int np = 0; np < 2; ++np) {
            uint32_t bd = s0 + KH_OFF + ((wn * 32 + np * 16 + (lane & 15)) * 72) * 2
                        + (kc * 2 + lhalf) * 16;
            uint32_t r0, r1, r2, r3;
            LDSM_X4(r0, r1, r2, r3, bd);
            bfr[np * 2 + 0][0] = r0; bfr[np * 2 + 0][1] = r2;
            bfr[np * 2 + 1][0] = r1; bfr[np * 2 + 1][1] = r3;
        }
        #pragma unroll
        for (int mt = 0; mt < 4; ++mt)
            #pragma unroll
            for (int nt = 0; nt < 4; ++nt)
                MMAF16(sc[mt][nt][0], sc[mt][nt][1], sc[mt][nt][2], sc[mt][nt][3],
                       a[mt][0], a[mt][1], a[mt][2], a[mt][3],
                       bfr[nt][0], bfr[nt][1]);
    }

    const bool dom = (blockIdx.x == 0);
    #pragma unroll
    for (int mt = 0; mt < 4; ++mt) {
        int r0 = wm * 64 + mt * 16 + (lane >> 2);
        #pragma unroll
        for (int nt = 0; nt < 4; ++nt) {
            int c0 = wn * 32 + nt * 8 + (lane & 3) * 2;
            #pragma unroll
            for (int q = 0; q < 4; ++q) {
                sc[mt][nt][q] *= 0.125f;
                if (dom) {
                    int rr = r0 + ((q >= 2) ? 8 : 0);
                    int cc = c0 + (q & 1);
                    if (cc > rr) sc[mt][nt][q] = -1e30f;
                }
            }
        }
    }

    float* redm = (float*)(sm + REDM_OFF);
    float* reds = (float*)(sm + REDS_OFF);

    #pragma unroll
    for (int mt = 0; mt < 4; ++mt) {
        float mlo = -1e30f, mhi = -1e30f;
        #pragma unroll
        for (int nt = 0; nt < 4; ++nt) {
            mlo = fmaxf(mlo, fmaxf(sc[mt][nt][0], sc[mt][nt][1]));
            mhi = fmaxf(mhi, fmaxf(sc[mt][nt][2], sc[mt][nt][3]));
        }
        #pragma unroll
        for (int o = 1; o <= 2; o <<= 1) {
            mlo = fmaxf(mlo, __shfl_xor_sync(0xffffffffu, mlo, o));
            mhi = fmaxf(mhi, __shfl_xor_sync(0xffffffffu, mhi, o));
        }
        if ((lane & 3) == 0) {
            int r0 = wm * 64 + mt * 16 + (lane >> 2);
            redm[wn * 128 + r0] = mlo;
            redm[wn * 128 + r0 + 8] = mhi;
        }
    }
    __syncthreads();

    #pragma unroll
    for (int mt = 0; mt < 4; ++mt) {
        int r0 = wm * 64 + mt * 16 + (lane >> 2);
        float mlo = fmaxf(fmaxf(redm[r0], redm[128 + r0]),
                          fmaxf(redm[256 + r0], redm[384 + r0]));
        int r1 = r0 + 8;
        float mhi = fmaxf(fmaxf(redm[r1], redm[128 + r1]),
                          fmaxf(redm[256 + r1], redm[384 + r1]));
        float slo = 0.f, shi = 0.f;
        #pragma unroll
        for (int nt = 0; nt < 4; ++nt) {
            sc[mt][nt][0] = __expf(sc[mt][nt][0] - mlo);
            sc[mt][nt][1] = __expf(sc[mt][nt][1] - mlo);
            sc[mt][nt][2] = __expf(sc[mt][nt][2] - mhi);
            sc[mt][nt][3] = __expf(sc[mt][nt][3] - mhi);
            slo += sc[mt][nt][0] + sc[mt][nt][1];
            shi += sc[mt][nt][2] + sc[mt][nt][3];
        }
        #pragma unroll
        for (int o = 1; o <= 2; o <<= 1) {
            slo += __shfl_xor_sync(0xffffffffu, slo, o);
            shi += __shfl_xor_sync(0xffffffffu, shi, o);
        }
        if ((lane & 3) == 0) {
            reds[wn * 128 + r0] = slo;
            reds[wn * 128 + r0 + 8] = shi;
        }
    }
    __syncthreads();

    #pragma unroll
    for (int mt = 0; mt < 4; ++mt) {
        int r0 = wm * 64 + mt * 16 + (lane >> 2);
        int r1 = r0 + 8;
        float ilo = __frcp_rn(reds[r0] + reds[128 + r0] + reds[256 + r0] + reds[384 + r0]);
        float ihi = __frcp_rn(reds[r1] + reds[128 + r1] + reds[256 + r1] + reds[384 + r1]);
        #pragma unroll
        for (int nt = 0; nt < 4; ++nt) {
            int c0 = wn * 32 + nt * 8 + (lane & 3) * 2;
            *(__half2*)(sm + PH_OFF + (r0 * 136 + c0) * 2) =
                __floats2half2_rn(sc[mt][nt][0] * ilo, sc[mt][nt][1] * ilo);
            *(__half2*)(sm + PH_OFF + (r1 * 136 + c0) * 2) =
                __floats2half2_rn(sc[mt][nt][2] * ihi, sc[mt][nt][3] * ihi);
        }
    }
    __syncthreads();

    // O = P * Vp
    float oc[4][2][4];
    #pragma unroll
    for (int i = 0; i < 4; ++i)
        #pragma unroll
        for (int j = 0; j < 2; ++j)
            #pragma unroll
            for (int q = 0; q < 4; ++q) oc[i][j][q] = 0.f;

    #pragma unroll
    for (int kc = 0; kc < 8; ++kc) {
        uint32_t a[4][4], bfr[2][2];
        #pragma unroll
        for (int mt = 0; mt < 4; ++mt) {
            uint32_t ad = s0 + PH_OFF + ((wm * 64 + mt * 16 + (lane & 15)) * 136) * 2
                        + (kc * 2 + lhalf) * 16;
            LDSM_X4(a[mt][0], a[mt][1], a[mt][2], a[mt][3], ad);
        }
        {
            uint32_t bd = s0 + VT_OFF + ((wn * 16 + (lane & 15)) * 136) * 2
                        + (kc * 2 + lhalf) * 16;
            uint32_t r0, r1, r2, r3;
            LDSM_X4(r0, r1, r2, r3, bd);
            bfr[0][0] = r0; bfr[0][1] = r2;
            bfr[1][0] = r1; bfr[1][1] = r3;
        }
        #pragma unroll
        for (int mt = 0; mt < 4; ++mt)
            #pragma unroll
            for (int nt = 0; nt < 2; ++nt)
                MMAF16(oc[mt][nt][0], oc[mt][nt][1], oc[mt][nt][2], oc[mt][nt][3],
                       a[mt][0], a[mt][1], a[mt][2], a[mt][3],
                       bfr[nt][0], bfr[nt][1]);
    }

    #pragma unroll
    for (int mt = 0; mt < 4; ++mt) {
        int r0 = wm * 64 + mt * 16 + (lane >> 2);
        #pragma unroll
        for (int nt = 0; nt < 2; ++nt) {
            int cd = wn * 16 + nt * 8 + (lane & 3) * 2;
            int gcol = h * HD_ + cd;
            *(__half2*)(As + (size_t)(b * L_ + l0 + r0) * D_ + gcol) =
                __floats2half2_rn(oc[mt][nt][0], oc[mt][nt][1]);
            *(__half2*)(As + (size_t)(b * L_ + l0 + r0 + 8) * D_ + gcol) =
                __floats2half2_rn(oc[mt][nt][2], oc[mt][nt][3]);
        }
    }
}

// ===================================================================
extern "C" void kernel_launch(void* const* d_in, const int* in_sizes, int n_in,
                              void* d_out, int out_size)
{
    const float* x   = (const float*)d_in[0];
    const float* fc  = (const float*)d_in[1];
    const float* fs  = (const float*)d_in[2];
    const float* Wq  = (const float*)d_in[3];
    const float* Wk  = (const float*)d_in[4];
    const float* Wv  = (const float*)d_in[5];
    const float* Wo  = (const float*)d_in[6];
    const float* kpm = (const float*)d_in[7];
    const float* vpm = (const float*)d_in[8];
    float* out = (float*)d_out;

    __half *xh, *As, *kvh, *Wq2, *Wk2, *Wv2, *Wo2, *Qh;
    float *Kb, *Vb, *Kpp, *Vpp;
    cudaGetSymbolAddress((void**)&xh,  g_xh);
    cudaGetSymbolAddress((void**)&As,  g_As);
    cudaGetSymbolAddress((void**)&kvh, g_kvh);
    cudaGetSymbolAddress((void**)&Wq2, g_Wq2);
    cudaGetSymbolAddress((void**)&Wk2, g_Wk2);
    cudaGetSymbolAddress((void**)&Wv2, g_Wv2);
    cudaGetSymbolAddress((void**)&Wo2, g_Wo2);
    cudaGetSymbolAddress((void**)&Qh,  g_Q);
    cudaGetSymbolAddress((void**)&Kb,  g_K);
    cudaGetSymbolAddress((void**)&Vb,  g_V);
    cudaGetSymbolAddress((void**)&Kpp, g_Kp);
    cudaGetSymbolAddress((void**)&Vpp, g_Vp);

    cudaFuncSetAttribute(gemm_f16, cudaFuncAttributeMaxDynamicSharedMemorySize, GEMM_SMEM);
    cudaFuncSetAttribute(attn_mma, cudaFuncAttributeMaxDynamicSharedMemorySize, ATT_SMEM);

    // conversions (conv_x also handles the weights)
    conv_x<<<(M_FULL * 128 + 255) / 256, 256>>>(x, xh, M_FULL, M_FULL, M_FULL);
    conv_x<<<(M_KV * 128 + 255) / 256, 256>>>(x, kvh, M_KV, P_, L_);
    conv_x<<<(D_ * 128 + 255) / 256, 256>>>(Wq, Wq2, D_, D_, D_);
    conv_x<<<(D_ * 128 + 255) / 256, 256>>>(Wk, Wk2, D_, D_, D_);
    conv_x<<<(D_ * 128 + 255) / 256, 256>>>(Wv, Wv2, D_, D_, D_);
    conv_x<<<(D_ * 128 + 255) / 256, 256>>>(Wo, Wo2, D_, D_, D_);

    // projections: Q (rope, fp16 out), K (rope, fp32), V (fp32)
    gemm_f16<<<dim3(D_ / BN, M_FULL / BM), 256, GEMM_SMEM>>>(xh, Wq2, nullptr, Qh, fc, fs, L_ - 1);
    gemm_f16<<<dim3(D_ / BN, M_KV / BM), 256, GEMM_SMEM>>>(kvh, Wk2, Kb, nullptr, fc, fs, P_ - 1);
    gemm_f16<<<dim3(D_ / BN, M_KV / BM), 256, GEMM_SMEM>>>(kvh, Wv2, Vb, nullptr, nullptr, nullptr, 0);

    // low-rank projections (tril-masked)
    proj_kernel<<<dim3(P_, BH_), 64>>>(Kb, Vb, kpm, vpm, Kpp, Vpp);

    // fp16 tensor-core attention -> fp16 output
    attn_mma<<<dim3(L_ / 128, BH_), 256, ATT_SMEM>>>(Qh, Kpp, Vpp, As);

    // final projection (fp32 out)
    gemm_f16<<<dim3(D_ / BN, M_FULL / BM), 256, GEMM_SMEM>>>(As, Wo2, out, nullptr, nullptr, nullptr, 0);
}

// round 8
// speedup vs baseline: 6.0016x; 1.0382x over previous
#include <cuda_runtime.h>
#include <cuda_bf16.h>
#include <cuda_fp16.h>
#include <cstdint>

// Problem constants
#define B_  4
#define L_  4096
#define D_  1024
#define H_  16
#define HD_ 64
#define P_  128
#define MAXLEN_ 4096
#define BH_ (B_ * H_)
#define M_FULL (B_ * L_)       // 16384
#define M_KV   (B_ * P_)       // 512

__device__ __forceinline__ uint32_t smem_u32(const void* p) {
    uint32_t a;
    asm("{ .reg .u64 t; cvta.to.shared.u64 t, %1; cvt.u32.u64 %0, t; }" : "=r"(a) : "l"(p));
    return a;
}
#define CP_ASYNC16(dst, src) \
    asm volatile("cp.async.cg.shared.global [%0], [%1], 16;" :: "r"(dst), "l"(src))
#define CP_COMMIT() asm volatile("cp.async.commit_group;" ::: "memory")
#define CP_WAIT2()  asm volatile("cp.async.wait_group 2;" ::: "memory")

#define LDSM_X4(R0, R1, R2, R3, A) \
    asm volatile("ldmatrix.sync.aligned.m8n8.x4.shared.b16 {%0,%1,%2,%3}, [%4];" \
        : "=r"(R0), "=r"(R1), "=r"(R2), "=r"(R3) : "r"(A))

#define MMAF16(D0, D1, D2, D3, A0, A1, A2, A3, B0, B1) \
    asm volatile("mma.sync.aligned.m16n8k16.row.col.f32.f16.f16.f32 " \
        "{%0,%1,%2,%3}, {%4,%5,%6,%7}, {%8,%9}, {%0,%1,%2,%3};" \
        : "+f"(D0), "+f"(D1), "+f"(D2), "+f"(D3) \
        : "r"(A0), "r"(A1), "r"(A2), "r"(A3), "r"(B0), "r"(B1))

// -------- scratch --------
__device__ __half g_xh [M_FULL * (size_t)D_];
__device__ __half g_As [M_FULL * (size_t)D_];
__device__ __half g_kvh[M_KV   * (size_t)D_];
__device__ __half g_Wq2[D_ * (size_t)D_];
__device__ __half g_Wk2[D_ * (size_t)D_];
__device__ __half g_Wv2[D_ * (size_t)D_];
__device__ __half g_Wo2[D_ * (size_t)D_];
__device__ __half g_Q [M_FULL * (size_t)D_];
__device__ float g_K [M_KV   * (size_t)D_];
__device__ float g_V [M_KV   * (size_t)D_];
__device__ float g_Kp[BH_ * P_ * HD_];
__device__ float g_Vp[BH_ * P_ * HD_];

// ===================================================================
// conv_x: fp32 (rows x 1024, optional row gather) -> fp16
// ===================================================================
__global__ __launch_bounds__(256) void conv_x(
    const float* __restrict__ src, __half* __restrict__ dst,
    int rows, int rpb, int bstride)
{
    int i = blockIdx.x * 256 + threadIdx.x;
    if (i >= rows * 128) return;
    int row = i >> 7;
    int c = (i & 127) * 8;
    int srow = (row / rpb) * bstride + (row % rpb);
    const float4* s = (const float4*)(src + (size_t)srow * D_ + c);
    float4 f0 = s[0], f1 = s[1];
    __half2 h[4];
    h[0] = __floats2half2_rn(f0.x, f0.y);
    h[1] = __floats2half2_rn(f0.z, f0.w);
    h[2] = __floats2half2_rn(f1.x, f1.y);
    h[3] = __floats2half2_rn(f1.z, f1.w);
    *(uint4*)(dst + (size_t)row * D_ + c) = *(uint4*)h;
}

// conv_w4: all 4 weight matrices in one launch
__global__ __launch_bounds__(256) void conv_w4(
    const float* __restrict__ w0, const float* __restrict__ w1,
    const float* __restrict__ w2, const float* __restrict__ w3,
    __half* __restrict__ d0, __half* __restrict__ d1,
    __half* __restrict__ d2, __half* __restrict__ d3)
{
    int i = blockIdx.x * 256 + threadIdx.x;          // 4 * 1024 * 128 total
    int sel = i >> 17;                               // / (1024*128)
    int r = i & 131071;
    const float* src = (sel == 0) ? w0 : (sel == 1) ? w1 : (sel == 2) ? w2 : w3;
    __half* dst = (sel == 0) ? d0 : (sel == 1) ? d1 : (sel == 2) ? d2 : d3;
    int row = r >> 7;
    int c = (r & 127) * 8;
    const float4* s = (const float4*)(src + (size_t)row * D_ + c);
    float4 f0 = s[0], f1 = s[1];
    __half2 h[4];
    h[0] = __floats2half2_rn(f0.x, f0.y);
    h[1] = __floats2half2_rn(f0.z, f0.w);
    h[2] = __floats2half2_rn(f1.x, f1.y);
    h[3] = __floats2half2_rn(f1.z, f1.w);
    *(uint4*)(dst + (size_t)row * D_ + c) = *(uint4*)h;
}

// ===================================================================
// fp16 mma GEMM templated on warp N tile (32 or 64).
// BM=128, BN=4*WTN, BK=64, 4-stage cp.async, 8 warps (2x4).
// ===================================================================
#define BM 128
#define BK 64
#define NSTG 4
#define NKC 16

template<int WTN>
__global__ __launch_bounds__(256, 1) void gemm_f16(
    const __half* __restrict__ A, const __half* __restrict__ W,
    float* __restrict__ Cf, __half* __restrict__ Ch,
    const float* __restrict__ rcos, const float* __restrict__ rsin, int lmask)
{
    constexpr int BN = 4 * WTN;
    constexpr int NT = WTN / 8;          // nt count: 4 or 8
    constexpr int NP = WTN / 16;         // B ldsm count: 2 or 4
    constexpr int ROWS_TOT = BM + BN;
    constexpr int NLD = ROWS_TOT / 32;   // 16B chunks per thread per stage
    constexpr int OPA = BM * 128;
    constexpr int STGB = ROWS_TOT * 128;

    extern __shared__ char dsm[];
    const uint32_t s0 = smem_u32(dsm);
    const int tid = threadIdx.x;
    const int wid = tid >> 5;
    const int lane = tid & 31;
    const int bx = blockIdx.x, by = blockIdx.y;

    uint32_t swo[NLD];
    const char* gs[NLD];
    #pragma unroll
    for (int j = 0; j < NLD; ++j) {
        int li = tid + 256 * j;
        int row = li >> 3;
        int ch = li & 7;
        if (row < BM) {
            swo[j] = (uint32_t)(row * 128 + ((ch ^ (row & 7)) << 4));
            gs[j] = (const char*)(A + (size_t)(by * BM + row) * D_ + ch * 8);
        } else {
            int r2 = row - BM;
            swo[j] = (uint32_t)(OPA + r2 * 128 + ((ch ^ (r2 & 7)) << 4));
            gs[j] = (const char*)(W + (size_t)(bx * BN + r2) * D_ + ch * 8);
        }
    }

    const int wm = wid >> 2;
    const int wn = wid & 3;
    const int lhalf = lane >> 4;
    int arow[4], brow[NP];
    #pragma unroll
    for (int mt = 0; mt < 4; ++mt) arow[mt] = wm * 64 + mt * 16 + (lane & 15);
    #pragma unroll
    for (int np = 0; np < NP; ++np) brow[np] = wn * WTN + np * 16 + (lane & 15);

    float acc[4][NT][4];
    #pragma unroll
    for (int i = 0; i < 4; ++i)
        #pragma unroll
        for (int j = 0; j < NT; ++j)
            #pragma unroll
            for (int q = 0; q < 4; ++q) acc[i][j][q] = 0.f;

    #pragma unroll
    for (int c = 0; c < NSTG - 1; ++c) {
        uint32_t sb = s0 + c * STGB;
        #pragma unroll
        for (int j = 0; j < NLD; ++j) CP_ASYNC16(sb + swo[j], gs[j] + (size_t)c * 128);
        CP_COMMIT();
    }

    for (int kc = 0; kc < NKC; ++kc) {
        const int stage = kc & (NSTG - 1);
        CP_WAIT2();
        __syncthreads();
        {
            int ldc = kc + NSTG - 1;
            if (ldc < NKC) {
                uint32_t sb = s0 + (ldc & (NSTG - 1)) * STGB;
                size_t off = (size_t)ldc * 128;
                #pragma unroll
                for (int j = 0; j < NLD; ++j) CP_ASYNC16(sb + swo[j], gs[j] + off);
            }
            CP_COMMIT();
        }

        const uint32_t ab = s0 + stage * STGB;
        const uint32_t bb = ab + OPA;
        #pragma unroll
        for (int ks = 0; ks < 4; ++ks) {
            uint32_t a[4][4], b[NT][2];
            #pragma unroll
            for (int mt = 0; mt < 4; ++mt) {
                int row = arow[mt];
                int ch = ks * 2 + lhalf;
                uint32_t ad = ab + row * 128 + (((ch ^ (row & 7))) << 4);
                LDSM_X4(a[mt][0], a[mt][1], a[mt][2], a[mt][3], ad);
            }
            #pragma unroll
            for (int np = 0; np < NP; ++np) {
                int row = brow[np];
                int ch = ks * 2 + lhalf;
                uint32_t bd = bb + row * 128 + (((ch ^ (row & 7))) << 4);
                uint32_t r0, r1, r2, r3;
                LDSM_X4(r0, r1, r2, r3, bd);
                b[np * 2 + 0][0] = r0; b[np * 2 + 0][1] = r2;
                b[np * 2 + 1][0] = r1; b[np * 2 + 1][1] = r3;
            }
            #pragma unroll
            for (int mt = 0; mt < 4; ++mt)
                #pragma unroll
                for (int nt = 0; nt < NT; ++nt)
                    MMAF16(acc[mt][nt][0], acc[mt][nt][1], acc[mt][nt][2], acc[mt][nt][3],
                           a[mt][0], a[mt][1], a[mt][2], a[mt][3],
                           b[nt][0], b[nt][1]);
        }
    }

    #pragma unroll
    for (int mt = 0; mt < 4; ++mt) {
        int row0 = by * BM + wm * 64 + mt * 16 + (lane >> 2);
        if (rcos != nullptr) {
            int la = row0 & lmask;
            int lb = (row0 + 8) & lmask;
            #pragma unroll
            for (int nt = 0; nt < NT; ++nt) {
                int col = bx * BN + wn * WTN + nt * 8 + (lane & 3) * 2;
                int f = (col & 63) >> 1;
                float ca = rcos[la * 32 + f], sa = rsin[la * 32 + f];
                float cb = rcos[lb * 32 + f], sb = rsin[lb * 32 + f];
                float a0 = acc[mt][nt][0], a1 = acc[mt][nt][1];
                acc[mt][nt][0] = a0 * ca - a1 * sa;
                acc[mt][nt][1] = a0 * sa + a1 * ca;
                a0 = acc[mt][nt][2]; a1 = acc[mt][nt][3];
                acc[mt][nt][2] = a0 * cb - a1 * sb;
                acc[mt][nt][3] = a0 * sb + a1 * cb;
            }
        }
        #pragma unroll
        for (int nt = 0; nt < NT; ++nt) {
            int col = bx * BN + wn * WTN + nt * 8 + (lane & 3) * 2;
            if (Ch != nullptr) {
                *(__half2*)(Ch + (size_t)row0 * D_ + col) =
                    __floats2half2_rn(acc[mt][nt][0], acc[mt][nt][1]);
                *(__half2*)(Ch + (size_t)(row0 + 8) * D_ + col) =
                    __floats2half2_rn(acc[mt][nt][2], acc[mt][nt][3]);
            } else {
                *(float2*)(Cf + (size_t)row0 * D_ + col) =
                    make_float2(acc[mt][nt][0], acc[mt][nt][1]);
                *(float2*)(Cf + (size_t)(row0 + 8) * D_ + col) =
                    make_float2(acc[mt][nt][2], acc[mt][nt][3]);
            }
        }
    }
}

// ===================================================================
// K_proj/V_proj
// ===================================================================
__global__ void proj_kernel(const float* __restrict__ Kb, const float* __restrict__ Vb,
                            const float* __restrict__ kpm, const float* __restrict__ vpm,
                            float* __restrict__ Kp, float* __restrict__ Vp)
{
    int p  = blockIdx.x;
    int bh = blockIdx.y;
    int b = bh >> 4, h = bh & 15;
    int d = threadIdx.x;
    const float* kbase = Kb + (size_t)b * P_ * D_ + h * HD_ + d;
    const float* vbase = Vb + (size_t)b * P_ * D_ + h * HD_ + d;
    float ak = 0.f, av = 0.f;
    for (int l = 0; l <= p; ++l) {
        float mk = kpm[p * MAXLEN_ + l];
        float mv = vpm[p * MAXLEN_ + l];
        ak += mk * kbase[(size_t)l * D_];
        av += mv * vbase[(size_t)l * D_];
    }
    size_t o = ((size_t)bh * P_ + p) * HD_ + d;
    Kp[o] = ak;
    Vp[o] = av;
}

// ===================================================================
// Attention: 2 Q-tiles (256 l's) per CTA, K/V smem loaded once.
// ===================================================================
#define QH_OFF   0                      // 128 x 72 half  = 18432
#define KH_OFF   18432                  // 128 x 72 half  = 18432
#define VT_OFF   36864                  // 64  x 136 half = 17408
#define PH_OFF   54272                  // 128 x 136 half = 34816
#define REDM_OFF 89088                  // 512 f32
#define REDS_OFF 91136                  // 512 f32
#define ATT_SMEM 93184

__global__ __launch_bounds__(256) void attn_mma(
    const __half* __restrict__ Q, const float* __restrict__ Kp,
    const float* __restrict__ Vp, __half* __restrict__ As)
{
    extern __shared__ char sm[];
    const uint32_t s0 = smem_u32(sm);
    const int tid = threadIdx.x;
    const int lane = tid & 31;
    const int wid = tid >> 5;
    const int wm = wid >> 2;
    const int wn = wid & 3;
    const int lhalf = lane >> 4;
    const int bh = blockIdx.y;
    const int b = bh >> 4, h = bh & 15;

    // K/V tiles once per CTA
    const float* kg = Kp + (size_t)bh * P_ * HD_;
    const float* vg = Vp + (size_t)bh * P_ * HD_;
    #pragma unroll
    for (int t = 0; t < 8; ++t) {
        int e = t * 256 + tid;
        int r = e >> 4;
        int d0 = (e & 15) * 4;
        float4 k = *(const float4*)(kg + r * HD_ + d0);
        __half2* dk = (__half2*)(sm + KH_OFF + (r * 72 + d0) * 2);
        dk[0] = __floats2half2_rn(k.x, k.y);
        dk[1] = __floats2half2_rn(k.z, k.w);
        float4 w = *(const float4*)(vg + r * HD_ + d0);
        __half* vt = (__half*)(sm + VT_OFF);
        vt[(d0 + 0) * 136 + r] = __float2half_rn(w.x);
        vt[(d0 + 1) * 136 + r] = __float2half_rn(w.y);
        vt[(d0 + 2) * 136 + r] = __float2half_rn(w.z);
        vt[(d0 + 3) * 136 + r] = __float2half_rn(w.w);
    }

    float* redm = (float*)(sm + REDM_OFF);
    float* reds = (float*)(sm + REDS_OFF);

    for (int t2 = 0; t2 < 2; ++t2) {
        const int l0 = blockIdx.x * 256 + t2 * 128;

        const __half* qg = Q + ((size_t)(b * L_ + l0)) * D_ + h * HD_;
        #pragma unroll
        for (int t = 0; t < 4; ++t) {
            int e = t * 256 + tid;
            int r = e >> 3;
            int c = (e & 7) * 8;
            uint4 v = *(const uint4*)(qg + (size_t)r * D_ + c);
            *(uint4*)(sm + QH_OFF + (r * 72 + c) * 2) = v;
        }
        __syncthreads();

        // S = Q * Kp^T
        float sc[4][4][4];
        #pragma unroll
        for (int i = 0; i < 4; ++i)
            #pragma unroll
            for (int j = 0; j < 4; ++j)
                #pragma unroll
                for (int q = 0; q < 4; ++q) sc[i][j][q] = 0.f;

        #pragma unroll
        for (int kc = 0; kc < 4; ++kc) {
            uint32_t a[4][4], bfr[4][2];
            #pragma unroll
            for (int mt = 0; mt < 4; ++mt) {
                uint32_t ad = s0 + QH_OFF + ((wm * 64 + mt * 16 + (lane & 15)) * 72) * 2
                            + (kc * 2 + lhalf) * 16;
                LDSM_X4(a[mt][0], a[mt][1], a[mt][2], a[mt][3], ad);
            }
            #pragma unroll
            for (int np = 0; np < 2; ++np) {
                uint32_t bd = s0 + KH_OFF + ((wn * 32 + np * 16 + (lane & 15)) * 72) * 2
                            + (kc * 2 + lhalf) * 16;
                uint32_t r0, r1, r2, r3;
                LDSM_X4(r0, r1, r2, r3, bd);
                bfr[np * 2 + 0][0] = r0; bfr[np * 2 + 0][1] = r2;
                bfr[np * 2 + 1][0] = r1; bfr[np * 2 + 1][1] = r3;
            }
            #pragma unroll
            for (int mt = 0; mt < 4; ++mt)
                #pragma unroll
                for (int nt = 0; nt < 4; ++nt)
                    MMAF16(sc[mt][nt][0], sc[mt][nt][1], sc[mt][nt][2], sc[mt][nt][3],
                           a[mt][0], a[mt][1], a[mt][2], a[mt][3],
                           bfr[nt][0], bfr[nt][1]);
        }

        const bool dom = (blockIdx.x == 0) && (t2 == 0);
        #pragma unroll
        for (int mt = 0; mt < 4; ++mt) {
            int r0 = wm * 64 + mt * 16 + (lane >> 2);
            #pragma unroll
            for (int nt = 0; nt < 4; ++nt) {
                int c0 = wn * 32 + nt * 8 + (lane & 3) * 2;
                #pragma unroll
                for (int q = 0; q < 4; ++q) {
                    sc[mt][nt][q] *= 0.125f;
                    if (dom) {
                        int rr = r0 + ((q >= 2) ? 8 : 0);
                        int cc = c0 + (q & 1);
                        if (cc > rr) sc[mt][nt][q] = -1e30f;
                    }
                }
            }
        }

        #pragma unroll
        for (int mt = 0; mt < 4; ++mt) {
            float mlo = -1e30f, mhi = -1e30f;
            #pragma unroll
            for (int nt = 0; nt < 4; ++nt) {
                mlo = fmaxf(mlo, fmaxf(sc[mt][nt][0], sc[mt][nt][1]));
                mhi = fmaxf(mhi, fmaxf(sc[mt][nt][2], sc[mt][nt][3]));
            }
            #pragma unroll
            for (int o = 1; o <= 2; o <<= 1) {
                mlo = fmaxf(mlo, __shfl_xor_sync(0xffffffffu, mlo, o));
                mhi = fmaxf(mhi, __shfl_xor_sync(0xffffffffu, mhi, o));
            }
            if ((lane & 3) == 0) {
                int r0 = wm * 64 + mt * 16 + (lane >> 2);
                redm[wn * 128 + r0] = mlo;
                redm[wn * 128 + r0 + 8] = mhi;
            }
        }
        __syncthreads();

        #pragma unroll
        for (int mt = 0; mt < 4; ++mt) {
            int r0 = wm * 64 + mt * 16 + (lane >> 2);
            float mlo = fmaxf(fmaxf(redm[r0], redm[128 + r0]),
                              fmaxf(redm[256 + r0], redm[384 + r0]));
            int r1 = r0 + 8;
            float mhi = fmaxf(fmaxf(redm[r1], redm[128 + r1]),
                              fmaxf(redm[256 + r1], redm[384 + r1]));
            float slo = 0.f, shi = 0.f;
            #pragma unroll
            for (int nt = 0; nt < 4; ++nt) {
                sc[mt][nt][0] = __expf(sc[mt][nt][0] - mlo);
                sc[mt][nt][1] = __expf(sc[mt][nt][1] - mlo);
                sc[mt][nt][2] = __expf(sc[mt][nt][2] - mhi);
                sc[mt][nt][3] = __expf(sc[mt][nt][3] - mhi);
                slo += sc[mt][nt][0] + sc[mt][nt][1];
                shi += sc[mt][nt][2] + sc[mt][nt][3];
            }
            #pragma unroll
            for (int o = 1; o <= 2; o <<= 1) {
                slo += __shfl_xor_sync(0xffffffffu, slo, o);
                shi += __shfl_xor_sync(0xffffffffu, shi, o);
            }
            if ((lane & 3) == 0) {
                reds[wn * 128 + r0] = slo;
                reds[wn * 128 + r0 + 8] = shi;
            }
        }
        __syncthreads();

        #pragma unroll
        for (int mt = 0; mt < 4; ++mt) {
            int r0 = wm * 64 + mt * 16 + (lane >> 2);
            int r1 = r0 + 8;
            float ilo = __frcp_rn(reds[r0] + reds[128 + r0] + reds[256 + r0] + reds[384 + r0]);
            float ihi = __frcp_rn(reds[r1] + reds[128 + r1] + reds[256 + r1] + reds[384 + r1]);
            #pragma unroll
            for (int nt = 0; nt < 4; ++nt) {
                int c0 = wn * 32 + nt * 8 + (lane & 3) * 2;
                *(__half2*)(sm + PH_OFF + (r0 * 136 + c0) * 2) =
                    __floats2half2_rn(sc[mt][nt][0] * ilo, sc[mt][nt][1] * ilo);
                *(__half2*)(sm + PH_OFF + (r1 * 136 + c0) * 2) =
                    __floats2half2_rn(sc[mt][nt][2] * ihi, sc[mt][nt][3] * ihi);
            }
        }
        __syncthreads();

        // O = P * Vp
        float oc[4][2][4];
        #pragma unroll
        for (int i = 0; i < 4; ++i)
            #pragma unroll
            for (int j = 0; j < 2; ++j)
                #pragma unroll
                for (int q = 0; q < 4; ++q) oc[i][j][q] = 0.f;

        #pragma unroll
        for (int kc = 0; kc < 8; ++kc) {
            uint32_t a[4][4], bfr[2][2];
            #pragma unroll
            for (int mt = 0; mt < 4; ++mt) {
                uint32_t ad = s0 + PH_OFF + ((wm * 64 + mt * 16 + (lane & 15)) * 136) * 2
                            + (kc * 2 + lhalf) * 16;
                LDSM_X4(a[mt][0], a[mt][1], a[mt][2], a[mt][3], ad);
            }
            {
                uint32_t bd = s0 + VT_OFF + ((wn * 16 + (lane & 15)) * 136) * 2
                            + (kc * 2 + lhalf) * 16;
                uint32_t r0, r1, r2, r3;
                LDSM_X4(r0, r1, r2, r3, bd);
                bfr[0][0] = r0; bfr[0][1] = r2;
                bfr[1][0] = r1; bfr[1][1] = r3;
            }
            #pragma unroll
            for (int mt = 0; mt < 4; ++mt)
                #pragma unroll
                for (int nt = 0; nt < 2; ++nt)
                    MMAF16(oc[mt][nt][0], oc[mt][nt][1], oc[mt][nt][2], oc[mt][nt][3],
                           a[mt][0], a[mt][1], a[mt][2], a[mt][3],
                           bfr[nt][0], bfr[nt][1]);
        }

        #pragma unroll
        for (int mt = 0; mt < 4; ++mt) {
            int r0 = wm * 64 + mt * 16 + (lane >> 2);
            #pragma unroll
            for (int nt = 0; nt < 2; ++nt) {
                int cd = wn * 16 + nt * 8 + (lane & 3) * 2;
                int gcol = h * HD_ + cd;
                *(__half2*)(As + (size_t)(b * L_ + l0 + r0) * D_ + gcol) =
                    __floats2half2_rn(oc[mt][nt][0], oc[mt][nt][1]);
                *(__half2*)(As + (size_t)(b * L_ + l0 + r0 + 8) * D_ + gcol) =
                    __floats2half2_rn(oc[mt][nt][2], oc[mt][nt][3]);
            }
        }
        __syncthreads();
    }
}

// ===================================================================
extern "C" void kernel_launch(void* const* d_in, const int* in_sizes, int n_in,
                              void* d_out, int out_size)
{
    const float* x   = (const float*)d_in[0];
    const float* fc  = (const float*)d_in[1];
    const float* fs  = (const float*)d_in[2];
    const float* Wq  = (const float*)d_in[3];
    const float* Wk  = (const float*)d_in[4];
    const float* Wv  = (const float*)d_in[5];
    const float* Wo  = (const float*)d_in[6];
    const float* kpm = (const float*)d_in[7];
    const float* vpm = (const float*)d_in[8];
    float* out = (float*)d_out;

    __half *xh, *As, *kvh, *Wq2, *Wk2, *Wv2, *Wo2, *Qh;
    float *Kb, *Vb, *Kpp, *Vpp;
    cudaGetSymbolAddress((void**)&xh,  g_xh);
    cudaGetSymbolAddress((void**)&As,  g_As);
    cudaGetSymbolAddress((void**)&kvh, g_kvh);
    cudaGetSymbolAddress((void**)&Wq2, g_Wq2);
    cudaGetSymbolAddress((void**)&Wk2, g_Wk2);
    cudaGetSymbolAddress((void**)&Wv2, g_Wv2);
    cudaGetSymbolAddress((void**)&Wo2, g_Wo2);
    cudaGetSymbolAddress((void**)&Qh,  g_Q);
    cudaGetSymbolAddress((void**)&Kb,  g_K);
    cudaGetSymbolAddress((void**)&Vb,  g_V);
    cudaGetSymbolAddress((void**)&Kpp, g_Kp);
    cudaGetSymbolAddress((void**)&Vpp, g_Vp);

    // smem sizes: WTN=64 -> 4*(128+256)*128 = 192 KB ; WTN=32 -> 128 KB
    cudaFuncSetAttribute(gemm_f16<64>, cudaFuncAttributeMaxDynamicSharedMemorySize, 196608);
    cudaFuncSetAttribute(gemm_f16<32>, cudaFuncAttributeMaxDynamicSharedMemorySize, 131072);
    cudaFuncSetAttribute(attn_mma, cudaFuncAttributeMaxDynamicSharedMemorySize, ATT_SMEM);

    // conversions
    conv_x<<<(M_FULL * 128 + 255) / 256, 256>>>(x, xh, M_FULL, M_FULL, M_FULL);
    conv_x<<<(M_KV * 128 + 255) / 256, 256>>>(x, kvh, M_KV, P_, L_);
    conv_w4<<<(4 * D_ * 128 + 255) / 256, 256>>>(Wq, Wk, Wv, Wo, Wq2, Wk2, Wv2, Wo2);

    // projections: Q (rope, fp16 out) on wide tile; K/V on narrow tile
    gemm_f16<64><<<dim3(D_ / 256, M_FULL / BM), 256, 196608>>>(xh, Wq2, nullptr, Qh, fc, fs, L_ - 1);
    gemm_f16<32><<<dim3(D_ / 128, M_KV / BM), 256, 131072>>>(kvh, Wk2, Kb, nullptr, fc, fs, P_ - 1);
    gemm_f16<32><<<dim3(D_ / 128, M_KV / BM), 256, 131072>>>(kvh, Wv2, Vb, nullptr, nullptr, nullptr, 0);

    // low-rank projections (tril-masked)
    proj_kernel<<<dim3(P_, BH_), 64>>>(Kb, Vb, kpm, vpm, Kpp, Vpp);

    // attention (2 tiles per CTA)
    attn_mma<<<dim3(L_ / 256, BH_), 256, ATT_SMEM>>>(Qh, Kpp, Vpp, As);

    // final projection (fp32 out) on wide tile
    gemm_f16<64><<<dim3(D_ / 256, M_FULL / BM), 256, 196608>>>(As, Wo2, out, nullptr, nullptr, nullptr, 0);
}

// round 9
// speedup vs baseline: 6.6295x; 1.1046x over previous
#include <cuda_runtime.h>
#include <cuda_bf16.h>
#include <cuda_fp16.h>
#include <cstdint>

// Problem constants
#define B_  4
#define L_  4096
#define D_  1024
#define H_  16
#define HD_ 64
#define P_  128
#define MAXLEN_ 4096
#define BH_ (B_ * H_)
#define M_FULL (B_ * L_)       // 16384
#define M_KV   (B_ * P_)       // 512

__device__ __forceinline__ uint32_t smem_u32(const void* p) {
    uint32_t a;
    asm("{ .reg .u64 t; cvta.to.shared.u64 t, %1; cvt.u32.u64 %0, t; }" : "=r"(a) : "l"(p));
    return a;
}
#define CP_ASYNC16(dst, src) \
    asm volatile("cp.async.cg.shared.global [%0], [%1], 16;" :: "r"(dst), "l"(src))
#define CP_COMMIT() asm volatile("cp.async.commit_group;" ::: "memory")
#define CP_WAIT2()  asm volatile("cp.async.wait_group 2;" ::: "memory")

#define LDSM_X4(R0, R1, R2, R3, A) \
    asm volatile("ldmatrix.sync.aligned.m8n8.x4.shared.b16 {%0,%1,%2,%3}, [%4];" \
        : "=r"(R0), "=r"(R1), "=r"(R2), "=r"(R3) : "r"(A))

#define MMAF16(D0, D1, D2, D3, A0, A1, A2, A3, B0, B1) \
    asm volatile("mma.sync.aligned.m16n8k16.row.col.f32.f16.f16.f32 " \
        "{%0,%1,%2,%3}, {%4,%5,%6,%7}, {%8,%9}, {%0,%1,%2,%3};" \
        : "+f"(D0), "+f"(D1), "+f"(D2), "+f"(D3) \
        : "r"(A0), "r"(A1), "r"(A2), "r"(A3), "r"(B0), "r"(B1))

// -------- scratch --------
__device__ __half g_xh [M_FULL * (size_t)D_];
__device__ __half g_As [M_FULL * (size_t)D_];
__device__ __half g_kvh[M_KV   * (size_t)D_];
__device__ __half g_Wq2[D_ * (size_t)D_];
__device__ __half g_Wk2[D_ * (size_t)D_];
__device__ __half g_Wv2[D_ * (size_t)D_];
__device__ __half g_Wo2[D_ * (size_t)D_];
__device__ __half g_Q [M_FULL * (size_t)D_];
__device__ float g_K [M_KV   * (size_t)D_];
__device__ float g_V [M_KV   * (size_t)D_];
__device__ float g_Kp[BH_ * P_ * HD_];
__device__ float g_Vp[BH_ * P_ * HD_];

// ===================================================================
// conv_x: fp32 (rows x 1024, optional row gather) -> fp16
// ===================================================================
__global__ __launch_bounds__(256) void conv_x(
    const float* __restrict__ src, __half* __restrict__ dst,
    int rows, int rpb, int bstride)
{
    int i = blockIdx.x * 256 + threadIdx.x;
    if (i >= rows * 128) return;
    int row = i >> 7;
    int c = (i & 127) * 8;
    int srow = (row / rpb) * bstride + (row % rpb);
    const float4* s = (const float4*)(src + (size_t)srow * D_ + c);
    float4 f0 = s[0], f1 = s[1];
    __half2 h[4];
    h[0] = __floats2half2_rn(f0.x, f0.y);
    h[1] = __floats2half2_rn(f0.z, f0.w);
    h[2] = __floats2half2_rn(f1.x, f1.y);
    h[3] = __floats2half2_rn(f1.z, f1.w);
    *(uint4*)(dst + (size_t)row * D_ + c) = *(uint4*)h;
}

// conv_w4: all 4 weight matrices in one launch
__global__ __launch_bounds__(256) void conv_w4(
    const float* __restrict__ w0, const float* __restrict__ w1,
    const float* __restrict__ w2, const float* __restrict__ w3,
    __half* __restrict__ d0, __half* __restrict__ d1,
    __half* __restrict__ d2, __half* __restrict__ d3)
{
    int i = blockIdx.x * 256 + threadIdx.x;          // 4 * 1024 * 128 total
    int sel = i >> 17;
    int r = i & 131071;
    const float* src = (sel == 0) ? w0 : (sel == 1) ? w1 : (sel == 2) ? w2 : w3;
    __half* dst = (sel == 0) ? d0 : (sel == 1) ? d1 : (sel == 2) ? d2 : d3;
    int row = r >> 7;
    int c = (r & 127) * 8;
    const float4* s = (const float4*)(src + (size_t)row * D_ + c);
    float4 f0 = s[0], f1 = s[1];
    __half2 h[4];
    h[0] = __floats2half2_rn(f0.x, f0.y);
    h[1] = __floats2half2_rn(f0.z, f0.w);
    h[2] = __floats2half2_rn(f1.x, f1.y);
    h[3] = __floats2half2_rn(f1.z, f1.w);
    *(uint4*)(dst + (size_t)row * D_ + c) = *(uint4*)h;
}

// ===================================================================
// fp16 mma GEMM: BM=128, BN=128, BK=64, 3-stage cp.async, 8 warps (2x4),
// warp tile 64x32, 2 CTAs/SM (128 regs, 96 KB smem).
// ===================================================================
#define BM 128
#define BN 128
#define BK 64
#define NSTG 3
#define NKC 16
#define OPA  (BM * 128)              // 16 KB
#define STGB ((BM + BN) * 128)       // 32 KB
#define GEMM_SMEM (NSTG * STGB)      // 96 KB

__global__ __launch_bounds__(256, 2) void gemm_f16(
    const __half* __restrict__ A, const __half* __restrict__ W,
    float* __restrict__ Cf, __half* __restrict__ Ch,
    const float* __restrict__ rcos, const float* __restrict__ rsin, int lmask)
{
    extern __shared__ char dsm[];
    const uint32_t s0 = smem_u32(dsm);
    const int tid = threadIdx.x;
    const int wid = tid >> 5;
    const int lane = tid & 31;
    const int bx = blockIdx.x, by = blockIdx.y;

    // register-lean loader: base row = tid>>3 (0..31), j adds 32 rows.
    // swizzle offset invariant under row += 32 (uses row & 7 only).
    const int lrow = tid >> 3;
    const int lch = tid & 7;
    const uint32_t sw0 = (uint32_t)(lrow * 128 + ((lch ^ (lrow & 7)) << 4));
    const char* aB = (const char*)(A + (size_t)(by * BM + lrow) * D_ + lch * 8);
    const char* wB = (const char*)(W + (size_t)(bx * BN + lrow) * D_ + lch * 8);
    const size_t RSTRIDE = (size_t)32 * D_ * 2;      // 32 rows of halfs, bytes

    const int wm = wid >> 2;
    const int wn = wid & 3;
    const int lhalf = lane >> 4;

    float acc[4][4][4];
    #pragma unroll
    for (int i = 0; i < 4; ++i)
        #pragma unroll
        for (int j = 0; j < 4; ++j)
            #pragma unroll
            for (int q = 0; q < 4; ++q) acc[i][j][q] = 0.f;

    // prologue: stages 0..1
    #pragma unroll
    for (int c = 0; c < NSTG - 1; ++c) {
        uint32_t sb = s0 + c * STGB;
        size_t off = (size_t)c * 128;
        #pragma unroll
        for (int j = 0; j < 4; ++j) {
            CP_ASYNC16(sb + sw0 + j * 4096,        aB + j * RSTRIDE + off);
            CP_ASYNC16(sb + OPA + sw0 + j * 4096,  wB + j * RSTRIDE + off);
        }
        CP_COMMIT();
    }

    int stage = 0;
    for (int kc = 0; kc < NKC; ++kc) {
        {
            int ldc = kc + NSTG - 1;
            if (ldc < NKC) {
                int ls = ldc % NSTG;
                uint32_t sb = s0 + ls * STGB;
                size_t off = (size_t)ldc * 128;
                #pragma unroll
                for (int j = 0; j < 4; ++j) {
                    CP_ASYNC16(sb + sw0 + j * 4096,       aB + j * RSTRIDE + off);
                    CP_ASYNC16(sb + OPA + sw0 + j * 4096, wB + j * RSTRIDE + off);
                }
            }
            CP_COMMIT();
        }
        CP_WAIT2();
        __syncthreads();

        const uint32_t ab = s0 + stage * STGB;
        const uint32_t bb = ab + OPA;
        #pragma unroll
        for (int ks = 0; ks < 4; ++ks) {
            uint32_t a[4][4], b[4][2];
            #pragma unroll
            for (int mt = 0; mt < 4; ++mt) {
                int row = wm * 64 + mt * 16 + (lane & 15);
                int ch = ks * 2 + lhalf;
                uint32_t ad = ab + row * 128 + (((ch ^ (row & 7))) << 4);
                LDSM_X4(a[mt][0], a[mt][1], a[mt][2], a[mt][3], ad);
            }
            #pragma unroll
            for (int np = 0; np < 2; ++np) {
                int row = wn * 32 + np * 16 + (lane & 15);
                int ch = ks * 2 + lhalf;
                uint32_t bd = bb + row * 128 + (((ch ^ (row & 7))) << 4);
                uint32_t r0, r1, r2, r3;
                LDSM_X4(r0, r1, r2, r3, bd);
                b[np * 2 + 0][0] = r0; b[np * 2 + 0][1] = r2;
                b[np * 2 + 1][0] = r1; b[np * 2 + 1][1] = r3;
            }
            #pragma unroll
            for (int mt = 0; mt < 4; ++mt)
                #pragma unroll
                for (int nt = 0; nt < 4; ++nt)
                    MMAF16(acc[mt][nt][0], acc[mt][nt][1], acc[mt][nt][2], acc[mt][nt][3],
                           a[mt][0], a[mt][1], a[mt][2], a[mt][3],
                           b[nt][0], b[nt][1]);
        }
        __syncthreads();
        stage = (stage + 1 == NSTG) ? 0 : stage + 1;
    }

    // epilogue: optional RoPE, fp32 or fp16 store
    #pragma unroll
    for (int mt = 0; mt < 4; ++mt) {
        int row0 = by * BM + wm * 64 + mt * 16 + (lane >> 2);
        if (rcos != nullptr) {
            int la = row0 & lmask;
            int lb = (row0 + 8) & lmask;
            #pragma unroll
            for (int nt = 0; nt < 4; ++nt) {
                int col = bx * BN + wn * 32 + nt * 8 + (lane & 3) * 2;
                int f = (col & 63) >> 1;
                float ca = rcos[la * 32 + f], sa = rsin[la * 32 + f];
                float cb = rcos[lb * 32 + f], sb = rsin[lb * 32 + f];
                float a0 = acc[mt][nt][0], a1 = acc[mt][nt][1];
                acc[mt][nt][0] = a0 * ca - a1 * sa;
                acc[mt][nt][1] = a0 * sa + a1 * ca;
                a0 = acc[mt][nt][2]; a1 = acc[mt][nt][3];
                acc[mt][nt][2] = a0 * cb - a1 * sb;
                acc[mt][nt][3] = a0 * sb + a1 * cb;
            }
        }
        #pragma unroll
        for (int nt = 0; nt < 4; ++nt) {
            int col = bx * BN + wn * 32 + nt * 8 + (lane & 3) * 2;
            if (Ch != nullptr) {
                *(__half2*)(Ch + (size_t)row0 * D_ + col) =
                    __floats2half2_rn(acc[mt][nt][0], acc[mt][nt][1]);
                *(__half2*)(Ch + (size_t)(row0 + 8) * D_ + col) =
                    __floats2half2_rn(acc[mt][nt][2], acc[mt][nt][3]);
            } else {
                *(float2*)(Cf + (size_t)row0 * D_ + col) =
                    make_float2(acc[mt][nt][0], acc[mt][nt][1]);
                *(float2*)(Cf + (size_t)(row0 + 8) * D_ + col) =
                    make_float2(acc[mt][nt][2], acc[mt][nt][3]);
            }
        }
    }
}

// ===================================================================
// K_proj/V_proj
// ===================================================================
__global__ void proj_kernel(const float* __restrict__ Kb, const float* __restrict__ Vb,
                            const float* __restrict__ kpm, const float* __restrict__ vpm,
                            float* __restrict__ Kp, float* __restrict__ Vp)
{
    int p  = blockIdx.x;
    int bh = blockIdx.y;
    int b = bh >> 4, h = bh & 15;
    int d = threadIdx.x;
    const float* kbase = Kb + (size_t)b * P_ * D_ + h * HD_ + d;
    const float* vbase = Vb + (size_t)b * P_ * D_ + h * HD_ + d;
    float ak = 0.f, av = 0.f;
    for (int l = 0; l <= p; ++l) {
        float mk = kpm[p * MAXLEN_ + l];
        float mv = vpm[p * MAXLEN_ + l];
        ak += mk * kbase[(size_t)l * D_];
        av += mv * vbase[(size_t)l * D_];
    }
    size_t o = ((size_t)bh * P_ + p) * HD_ + d;
    Kp[o] = ak;
    Vp[o] = av;
}

// ===================================================================
// Attention: 2 Q-tiles (256 l's) per CTA, K/V smem loaded once.
// ===================================================================
#define QH_OFF   0
#define KH_OFF   18432
#define VT_OFF   36864
#define PH_OFF   54272
#define REDM_OFF 89088
#define REDS_OFF 91136
#define ATT_SMEM 93184

__global__ __launch_bounds__(256) void attn_mma(
    const __half* __restrict__ Q, const float* __restrict__ Kp,
    const float* __restrict__ Vp, __half* __restrict__ As)
{
    extern __shared__ char sm[];
    const uint32_t s0 = smem_u32(sm);
    const int tid = threadIdx.x;
    const int lane = tid & 31;
    const int wid = tid >> 5;
    const int wm = wid >> 2;
    const int wn = wid & 3;
    const int lhalf = lane >> 4;
    const int bh = blockIdx.y;
    const int b = bh >> 4, h = bh & 15;

    const float* kg = Kp + (size_t)bh * P_ * HD_;
    const float* vg = Vp + (size_t)bh * P_ * HD_;
    #pragma unroll
    for (int t = 0; t < 8; ++t) {
        int e = t * 256 + tid;
        int r = e >> 4;
        int d0 = (e & 15) * 4;
        float4 k = *(const float4*)(kg + r * HD_ + d0);
        __half2* dk = (__half2*)(sm + KH_OFF + (r * 72 + d0) * 2);
        dk[0] = __floats2half2_rn(k.x, k.y);
        dk[1] = __floats2half2_rn(k.z, k.w);
        float4 w = *(const float4*)(vg + r * HD_ + d0);
        __half* vt = (__half*)(sm + VT_OFF);
        vt[(d0 + 0) * 136 + r] = __float2half_rn(w.x);
        vt[(d0 + 1) * 136 + r] = __float2half_rn(w.y);
        vt[(d0 + 2) * 136 + r] = __float2half_rn(w.z);
        vt[(d0 + 3) * 136 + r] = __float2half_rn(w.w);
    }

    float* redm = (float*)(sm + REDM_OFF);
    float* reds = (float*)(sm + REDS_OFF);

    for (int t2 = 0; t2 < 2; ++t2) {
        const int l0 = blockIdx.x * 256 + t2 * 128;

        const __half* qg = Q + ((size_t)(b * L_ + l0)) * D_ + h * HD_;
        #pragma unroll
        for (int t = 0; t < 4; ++t) {
            int e = t * 256 + tid;
            int r = e >> 3;
            int c = (e & 7) * 8;
            uint4 v = *(const uint4*)(qg + (size_t)r * D_ + c);
            *(uint4*)(sm + QH_OFF + (r * 72 + c) * 2) = v;
        }
        __syncthreads();

        float sc[4][4][4];
        #pragma unroll
        for (int i = 0; i < 4; ++i)
            #pragma unroll
            for (int j = 0; j < 4; ++j)
                #pragma unroll
                for (int q = 0; q < 4; ++q) sc[i][j][q] = 0.f;

        #pragma unroll
        for (int kc = 0; kc < 4; ++kc) {
            uint32_t a[4][4], bfr[4][2];
            #pragma unroll
            for (int mt = 0; mt < 4; ++mt) {
                uint32_t ad = s0 + QH_OFF + ((wm * 64 + mt * 16 + (lane & 15)) * 72) * 2
                            + (kc * 2 + lhalf) * 16;
                LDSM_X4(a[mt][0], a[mt][1], a[mt][2], a[mt][3], ad);
            }
            #pragma unroll
            for (int np = 0; np < 2; ++np) {
                uint32_t bd = s0 + KH_OFF + ((wn * 32 + np * 16 + (lane & 15)) * 72) * 2
                            + (kc * 2 + lhalf) * 16;
                uint32_t r0, r1, r2, r3;
                LDSM_X4(r0, r1, r2, r3, bd);
                bfr[np * 2 + 0][0] = r0; bfr[np * 2 + 0][1] = r2;
                bfr[np * 2 + 1][0] = r1; bfr[np * 2 + 1][1] = r3;
            }
            #pragma unroll
            for (int mt = 0; mt < 4; ++mt)
                #pragma unroll
                for (int nt = 0; nt < 4; ++nt)
                    MMAF16(sc[mt][nt][0], sc[mt][nt][1], sc[mt][nt][2], sc[mt][nt][3],
                           a[mt][0], a[mt][1], a[mt][2], a[mt][3],
                           bfr[nt][0], bfr[nt][1]);
        }

        const bool dom = (blockIdx.x == 0) && (t2 == 0);
        #pragma unroll
        for (int mt = 0; mt < 4; ++mt) {
            int r0 = wm * 64 + mt * 16 + (lane >> 2);
            #pragma unroll
            for (int nt = 0; nt < 4; ++nt) {
                int c0 = wn * 32 + nt * 8 + (lane & 3) * 2;
                #pragma unroll
                for (int q = 0; q < 4; ++q) {
                    sc[mt][nt][q] *= 0.125f;
                    if (dom) {
                        int rr = r0 + ((q >= 2) ? 8 : 0);
                        int cc = c0 + (q & 1);
                        if (cc > rr) sc[mt][nt][q] = -1e30f;
                    }
                }
            }
        }

        #pragma unroll
        for (int mt = 0; mt < 4; ++mt) {
            float mlo = -1e30f, mhi = -1e30f;
            #pragma unroll
            for (int nt = 0; nt < 4; ++nt) {
                mlo = fmaxf(mlo, fmaxf(sc[mt][nt][0], sc[mt][nt][1]));
                mhi = fmaxf(mhi, fmaxf(sc[mt][nt][2], sc[mt][nt][3]));
            }
            #pragma unroll
            for (int o = 1; o <= 2; o <<= 1) {
                mlo = fmaxf(mlo, __shfl_xor_sync(0xffffffffu, mlo, o));
                mhi = fmaxf(mhi, __shfl_xor_sync(0xffffffffu, mhi, o));
            }
            if ((lane & 3) == 0) {
                int r0 = wm * 64 + mt * 16 + (lane >> 2);
                redm[wn * 128 + r0] = mlo;
                redm[wn * 128 + r0 + 8] = mhi;
            }
        }
        __syncthreads();

        #pragma unroll
        for (int mt = 0; mt < 4; ++mt) {
            int r0 = wm * 64 + mt * 16 + (lane >> 2);
            float mlo = fmaxf(fmaxf(redm[r0], redm[128 + r0]),
                              fmaxf(redm[256 + r0], redm[384 + r0]));
            int r1 = r0 + 8;
            float mhi = fmaxf(fmaxf(redm[r1], redm[128 + r1]),
                              fmaxf(redm[256 + r1], redm[384 + r1]));
            float slo = 0.f, shi = 0.f;
            #pragma unroll
            for (int nt = 0; nt < 4; ++nt) {
                sc[mt][nt][0] = __expf(sc[mt][nt][0] - mlo);
                sc[mt][nt][1] = __expf(sc[mt][nt][1] - mlo);
                sc[mt][nt][2] = __expf(sc[mt][nt][2] - mhi);
                sc[mt][nt][3] = __expf(sc[mt][nt][3] - mhi);
                slo += sc[mt][nt][0] + sc[mt][nt][1];
                shi += sc[mt][nt][2] + sc[mt][nt][3];
            }
            #pragma unroll
            for (int o = 1; o <= 2; o <<= 1) {
                slo += __shfl_xor_sync(0xffffffffu, slo, o);
                shi += __shfl_xor_sync(0xffffffffu, shi, o);
            }
            if ((lane & 3) == 0) {
                reds[wn * 128 + r0] = slo;
                reds[wn * 128 + r0 + 8] = shi;
            }
        }
        __syncthreads();

        #pragma unroll
        for (int mt = 0; mt < 4; ++mt) {
            int r0 = wm * 64 + mt * 16 + (lane >> 2);
            int r1 = r0 + 8;
            float ilo = __frcp_rn(reds[r0] + reds[128 + r0] + reds[256 + r0] + reds[384 + r0]);
            float ihi = __frcp_rn(reds[r1] + reds[128 + r1] + reds[256 + r1] + reds[384 + r1]);
            #pragma unroll
            for (int nt = 0; nt < 4; ++nt) {
                int c0 = wn * 32 + nt * 8 + (lane & 3) * 2;
                *(__half2*)(sm + PH_OFF + (r0 * 136 + c0) * 2) =
                    __floats2half2_rn(sc[mt][nt][0] * ilo, sc[mt][nt][1] * ilo);
                *(__half2*)(sm + PH_OFF + (r1 * 136 + c0) * 2) =
                    __floats2half2_rn(sc[mt][nt][2] * ihi, sc[mt][nt][3] * ihi);
            }
        }
        __syncthreads();

        float oc[4][2][4];
        #pragma unroll
        for (int i = 0; i < 4; ++i)
            #pragma unroll
            for (int j = 0; j < 2; ++j)
                #pragma unroll
                for (int q = 0; q < 4; ++q) oc[i][j][q] = 0.f;

        #pragma unroll
        for (int kc = 0; kc < 8; ++kc) {
            uint32_t a[4][4], bfr[2][2];
            #pragma unroll
            for (int mt = 0; mt < 4; ++mt) {
                uint32_t ad = s0 + PH_OFF + ((wm * 64 + mt * 16 + (lane & 15)) * 136) * 2
                            + (kc * 2 + lhalf) * 16;
                LDSM_X4(a[mt][0], a[mt][1], a[mt][2], a[mt][3], ad);
            }
            {
                uint32_t bd = s0 + VT_OFF + ((wn * 16 + (lane & 15)) * 136) * 2
                            + (kc * 2 + lhalf) * 16;
                uint32_t r0, r1, r2, r3;
                LDSM_X4(r0, r1, r2, r3, bd);
                bfr[0][0] = r0; bfr[0][1] = r2;
                bfr[1][0] = r1; bfr[1][1] = r3;
            }
            #pragma unroll
            for (int mt = 0; mt < 4; ++mt)
                #pragma unroll
                for (int nt = 0; nt < 2; ++nt)
                    MMAF16(oc[mt][nt][0], oc[mt][nt][1], oc[mt][nt][2], oc[mt][nt][3],
                           a[mt][0], a[mt][1], a[mt][2], a[mt][3],
                           bfr[nt][0], bfr[nt][1]);
        }

        #pragma unroll
        for (int mt = 0; mt < 4; ++mt) {
            int r0 = wm * 64 + mt * 16 + (lane >> 2);
            #pragma unroll
            for (int nt = 0; nt < 2; ++nt) {
                int cd = wn * 16 + nt * 8 + (lane & 3) * 2;
                int gcol = h * HD_ + cd;
                *(__half2*)(As + (size_t)(b * L_ + l0 + r0) * D_ + gcol) =
                    __floats2half2_rn(oc[mt][nt][0], oc[mt][nt][1]);
                *(__half2*)(As + (size_t)(b * L_ + l0 + r0 + 8) * D_ + gcol) =
                    __floats2half2_rn(oc[mt][nt][2], oc[mt][nt][3]);
            }
        }
        __syncthreads();
    }
}

// ===================================================================
extern "C" void kernel_launch(void* const* d_in, const int* in_sizes, int n_in,
                              void* d_out, int out_size)
{
    const float* x   = (const float*)d_in[0];
    const float* fc  = (const float*)d_in[1];
    const float* fs  = (const float*)d_in[2];
    const float* Wq  = (const float*)d_in[3];
    const float* Wk  = (const float*)d_in[4];
    const float* Wv  = (const float*)d_in[5];
    const float* Wo  = (const float*)d_in[6];
    const float* kpm = (const float*)d_in[7];
    const float* vpm = (const float*)d_in[8];
    float* out = (float*)d_out;

    __half *xh, *As, *kvh, *Wq2, *Wk2, *Wv2, *Wo2, *Qh;
    float *Kb, *Vb, *Kpp, *Vpp;
    cudaGetSymbolAddress((void**)&xh,  g_xh);
    cudaGetSymbolAddress((void**)&As,  g_As);
    cudaGetSymbolAddress((void**)&kvh, g_kvh);
    cudaGetSymbolAddress((void**)&Wq2, g_Wq2);
    cudaGetSymbolAddress((void**)&Wk2, g_Wk2);
    cudaGetSymbolAddress((void**)&Wv2, g_Wv2);
    cudaGetSymbolAddress((void**)&Wo2, g_Wo2);
    cudaGetSymbolAddress((void**)&Qh,  g_Q);
    cudaGetSymbolAddress((void**)&Kb,  g_K);
    cudaGetSymbolAddress((void**)&Vb,  g_V);
    cudaGetSymbolAddress((void**)&Kpp, g_Kp);
    cudaGetSymbolAddress((void**)&Vpp, g_Vp);

    cudaFuncSetAttribute(gemm_f16, cudaFuncAttributeMaxDynamicSharedMemorySize, GEMM_SMEM);
    cudaFuncSetAttribute(attn_mma, cudaFuncAttributeMaxDynamicSharedMemorySize, ATT_SMEM);

    // conversions
    conv_x<<<(M_FULL * 128 + 255) / 256, 256>>>(x, xh, M_FULL, M_FULL, M_FULL);
    conv_x<<<(M_KV * 128 + 255) / 256, 256>>>(x, kvh, M_KV, P_, L_);
    conv_w4<<<(4 * D_ * 128 + 255) / 256, 256>>>(Wq, Wk, Wv, Wo, Wq2, Wk2, Wv2, Wo2);

    // projections: Q (rope, fp16 out), K (rope, fp32), V (fp32)
    gemm_f16<<<dim3(D_ / BN, M_FULL / BM), 256, GEMM_SMEM>>>(xh, Wq2, nullptr, Qh, fc, fs, L_ - 1);
    gemm_f16<<<dim3(D_ / BN, M_KV / BM), 256, GEMM_SMEM>>>(kvh, Wk2, Kb, nullptr, fc, fs, P_ - 1);
    gemm_f16<<<dim3(D_ / BN, M_KV / BM), 256, GEMM_SMEM>>>(kvh, Wv2, Vb, nullptr, nullptr, nullptr, 0);

    // low-rank projections (tril-masked)
    proj_kernel<<<dim3(P_, BH_), 64>>>(Kb, Vb, kpm, vpm, Kpp, Vpp);

    // attention (2 tiles per CTA)
    attn_mma<<<dim3(L_ / 256, BH_), 256, ATT_SMEM>>>(Qh, Kpp, Vpp, As);

    // final projection (fp32 out)
    gemm_f16<<<dim3(D_ / BN, M_FULL / BM), 256, GEMM_SMEM>>>(As, Wo2, out, nullptr, nullptr, nullptr, 0);
}

// round 10
// speedup vs baseline: 6.7034x; 1.0111x over previous
#include <cuda_runtime.h>
#include <cuda_bf16.h>
#include <cuda_fp16.h>
#include <cstdint>

// Problem constants
#define B_  4
#define L_  4096
#define D_  1024
#define H_  16
#define HD_ 64
#define P_  128
#define MAXLEN_ 4096
#define BH_ (B_ * H_)
#define M_FULL (B_ * L_)       // 16384
#define M_KV   (B_ * P_)       // 512

__device__ __forceinline__ uint32_t smem_u32(const void* p) {
    uint32_t a;
    asm("{ .reg .u64 t; cvta.to.shared.u64 t, %1; cvt.u32.u64 %0, t; }" : "=r"(a) : "l"(p));
    return a;
}
#define CP_ASYNC16(dst, src) \
    asm volatile("cp.async.cg.shared.global [%0], [%1], 16;" :: "r"(dst), "l"(src))
#define CP_COMMIT() asm volatile("cp.async.commit_group;" ::: "memory")
#define CP_WAIT1()  asm volatile("cp.async.wait_group 1;" ::: "memory")

#define LDSM_X4(R0, R1, R2, R3, A) \
    asm volatile("ldmatrix.sync.aligned.m8n8.x4.shared.b16 {%0,%1,%2,%3}, [%4];" \
        : "=r"(R0), "=r"(R1), "=r"(R2), "=r"(R3) : "r"(A))

#define MMAF16(D0, D1, D2, D3, A0, A1, A2, A3, B0, B1) \
    asm volatile("mma.sync.aligned.m16n8k16.row.col.f32.f16.f16.f32 " \
        "{%0,%1,%2,%3}, {%4,%5,%6,%7}, {%8,%9}, {%0,%1,%2,%3};" \
        : "+f"(D0), "+f"(D1), "+f"(D2), "+f"(D3) \
        : "r"(A0), "r"(A1), "r"(A2), "r"(A3), "r"(B0), "r"(B1))

// -------- scratch --------
__device__ __half g_xh [M_FULL * (size_t)D_];
__device__ __half g_As [M_FULL * (size_t)D_];
__device__ __half g_kvh[M_KV   * (size_t)D_];
__device__ __half g_Wq2[D_ * (size_t)D_];
__device__ __half g_Wk2[D_ * (size_t)D_];
__device__ __half g_Wv2[D_ * (size_t)D_];
__device__ __half g_Wo2[D_ * (size_t)D_];
__device__ __half g_Q [M_FULL * (size_t)D_];
__device__ float g_K [M_KV   * (size_t)D_];
__device__ float g_V [M_KV   * (size_t)D_];
__device__ float g_Kp[BH_ * P_ * HD_];
__device__ float g_Vp[BH_ * P_ * HD_];

// ===================================================================
// conv_x: fp32 (rows x 1024, optional row gather) -> fp16
// ===================================================================
__global__ __launch_bounds__(256) void conv_x(
    const float* __restrict__ src, __half* __restrict__ dst,
    int rows, int rpb, int bstride)
{
    int i = blockIdx.x * 256 + threadIdx.x;
    if (i >= rows * 128) return;
    int row = i >> 7;
    int c = (i & 127) * 8;
    int srow = (row / rpb) * bstride + (row % rpb);
    const float4* s = (const float4*)(src + (size_t)srow * D_ + c);
    float4 f0 = s[0], f1 = s[1];
    __half2 h[4];
    h[0] = __floats2half2_rn(f0.x, f0.y);
    h[1] = __floats2half2_rn(f0.z, f0.w);
    h[2] = __floats2half2_rn(f1.x, f1.y);
    h[3] = __floats2half2_rn(f1.z, f1.w);
    *(uint4*)(dst + (size_t)row * D_ + c) = *(uint4*)h;
}

// conv_w4: all 4 weight matrices in one launch
__global__ __launch_bounds__(256) void conv_w4(
    const float* __restrict__ w0, const float* __restrict__ w1,
    const float* __restrict__ w2, const float* __restrict__ w3,
    __half* __restrict__ d0, __half* __restrict__ d1,
    __half* __restrict__ d2, __half* __restrict__ d3)
{
    int i = blockIdx.x * 256 + threadIdx.x;          // 4 * 1024 * 128 total
    int sel = i >> 17;
    int r = i & 131071;
    const float* src = (sel == 0) ? w0 : (sel == 1) ? w1 : (sel == 2) ? w2 : w3;
    __half* dst = (sel == 0) ? d0 : (sel == 1) ? d1 : (sel == 2) ? d2 : d3;
    int row = r >> 7;
    int c = (r & 127) * 8;
    const float4* s = (const float4*)(src + (size_t)row * D_ + c);
    float4 f0 = s[0], f1 = s[1];
    __half2 h[4];
    h[0] = __floats2half2_rn(f0.x, f0.y);
    h[1] = __floats2half2_rn(f0.z, f0.w);
    h[2] = __floats2half2_rn(f1.x, f1.y);
    h[3] = __floats2half2_rn(f1.z, f1.w);
    *(uint4*)(dst + (size_t)row * D_ + c) = *(uint4*)h;
}

// ===================================================================
// fp16 mma GEMM: BM=128, BN=128, BK=64, 3-stage cp.async, 8 warps (2x4),
// warp tile 64x32, 2 CTAs/SM, SINGLE barrier per K-chunk:
//   wait_group(1) -> sync -> issue loads(kc+2) -> MMA(kc)
// ===================================================================
#define BM 128
#define BN 128
#define BK 64
#define NSTG 3
#define NKC 16
#define OPA  (BM * 128)              // 16 KB
#define STGB ((BM + BN) * 128)       // 32 KB
#define GEMM_SMEM (NSTG * STGB)      // 96 KB

__global__ __launch_bounds__(256, 2) void gemm_f16(
    const __half* __restrict__ A, const __half* __restrict__ W,
    float* __restrict__ Cf, __half* __restrict__ Ch,
    const float* __restrict__ rcos, const float* __restrict__ rsin, int lmask)
{
    extern __shared__ char dsm[];
    const uint32_t s0 = smem_u32(dsm);
    const int tid = threadIdx.x;
    const int wid = tid >> 5;
    const int lane = tid & 31;
    const int bx = blockIdx.x, by = blockIdx.y;

    // register-lean loader: base row = tid>>3 (0..31), j adds 32 rows.
    const int lrow = tid >> 3;
    const int lch = tid & 7;
    const uint32_t sw0 = (uint32_t)(lrow * 128 + ((lch ^ (lrow & 7)) << 4));
    const char* aB = (const char*)(A + (size_t)(by * BM + lrow) * D_ + lch * 8);
    const char* wB = (const char*)(W + (size_t)(bx * BN + lrow) * D_ + lch * 8);
    const size_t RSTRIDE = (size_t)32 * D_ * 2;

    const int wm = wid >> 2;
    const int wn = wid & 3;
    const int lhalf = lane >> 4;

    // hoisted LDSM geometry: per-tile row offsets and row-xor nibbles
    uint32_t aro[4], bro[2];
    uint32_t arx[4], brx[2];
    #pragma unroll
    for (int mt = 0; mt < 4; ++mt) {
        int row = wm * 64 + mt * 16 + (lane & 15);
        aro[mt] = (uint32_t)(row * 128);
        arx[mt] = (uint32_t)(row & 7);
    }
    #pragma unroll
    for (int np = 0; np < 2; ++np) {
        int row = wn * 32 + np * 16 + (lane & 15);
        bro[np] = (uint32_t)(row * 128);
        brx[np] = (uint32_t)(row & 7);
    }

    float acc[4][4][4];
    #pragma unroll
    for (int i = 0; i < 4; ++i)
        #pragma unroll
        for (int j = 0; j < 4; ++j)
            #pragma unroll
            for (int q = 0; q < 4; ++q) acc[i][j][q] = 0.f;

    // prologue: stages 0..1
    #pragma unroll
    for (int c = 0; c < NSTG - 1; ++c) {
        uint32_t sb = s0 + c * STGB;
        size_t off = (size_t)c * 128;
        #pragma unroll
        for (int j = 0; j < 4; ++j) {
            CP_ASYNC16(sb + sw0 + j * 4096,        aB + j * RSTRIDE + off);
            CP_ASYNC16(sb + OPA + sw0 + j * 4096,  wB + j * RSTRIDE + off);
        }
        CP_COMMIT();
    }

    int stage = 0;
    for (int kc = 0; kc < NKC; ++kc) {
        CP_WAIT1();                 // oldest group (stage kc) resident
        __syncthreads();            // visibility + protects stage (kc+2)%3 rewrite

        {
            int ldc = kc + NSTG - 1;
            if (ldc < NKC) {
                int ls = ldc % NSTG;
                uint32_t sb = s0 + ls * STGB;
                size_t off = (size_t)ldc * 128;
                #pragma unroll
                for (int j = 0; j < 4; ++j) {
                    CP_ASYNC16(sb + sw0 + j * 4096,       aB + j * RSTRIDE + off);
                    CP_ASYNC16(sb + OPA + sw0 + j * 4096, wB + j * RSTRIDE + off);
                }
            }
            CP_COMMIT();
        }

        const uint32_t ab = s0 + stage * STGB;
        const uint32_t bb = ab + OPA;
        #pragma unroll
        for (int ks = 0; ks < 4; ++ks) {
            const uint32_t ch = (uint32_t)(ks * 2 + lhalf);
            uint32_t a[4][4], b[4][2];
            #pragma unroll
            for (int mt = 0; mt < 4; ++mt) {
                uint32_t ad = ab + aro[mt] + ((ch ^ arx[mt]) << 4);
                LDSM_X4(a[mt][0], a[mt][1], a[mt][2], a[mt][3], ad);
            }
            #pragma unroll
            for (int np = 0; np < 2; ++np) {
                uint32_t bd = bb + bro[np] + ((ch ^ brx[np]) << 4);
                uint32_t r0, r1, r2, r3;
                LDSM_X4(r0, r1, r2, r3, bd);
                b[np * 2 + 0][0] = r0; b[np * 2 + 0][1] = r2;
                b[np * 2 + 1][0] = r1; b[np * 2 + 1][1] = r3;
            }
            #pragma unroll
            for (int mt = 0; mt < 4; ++mt)
                #pragma unroll
                for (int nt = 0; nt < 4; ++nt)
                    MMAF16(acc[mt][nt][0], acc[mt][nt][1], acc[mt][nt][2], acc[mt][nt][3],
                           a[mt][0], a[mt][1], a[mt][2], a[mt][3],
                           b[nt][0], b[nt][1]);
        }
        stage = (stage + 1 == NSTG) ? 0 : stage + 1;
    }

    // epilogue: optional RoPE, fp32 or fp16 store
    #pragma unroll
    for (int mt = 0; mt < 4; ++mt) {
        int row0 = by * BM + wm * 64 + mt * 16 + (lane >> 2);
        if (rcos != nullptr) {
            int la = row0 & lmask;
            int lb = (row0 + 8) & lmask;
            #pragma unroll
            for (int nt = 0; nt < 4; ++nt) {
                int col = bx * BN + wn * 32 + nt * 8 + (lane & 3) * 2;
                int f = (col & 63) >> 1;
                float ca = rcos[la * 32 + f], sa = rsin[la * 32 + f];
                float cb = rcos[lb * 32 + f], sb = rsin[lb * 32 + f];
                float a0 = acc[mt][nt][0], a1 = acc[mt][nt][1];
                acc[mt][nt][0] = a0 * ca - a1 * sa;
                acc[mt][nt][1] = a0 * sa + a1 * ca;
                a0 = acc[mt][nt][2]; a1 = acc[mt][nt][3];
                acc[mt][nt][2] = a0 * cb - a1 * sb;
                acc[mt][nt][3] = a0 * sb + a1 * cb;
            }
        }
        #pragma unroll
        for (int nt = 0; nt < 4; ++nt) {
            int col = bx * BN + wn * 32 + nt * 8 + (lane & 3) * 2;
            if (Ch != nullptr) {
                *(__half2*)(Ch + (size_t)row0 * D_ + col) =
                    __floats2half2_rn(acc[mt][nt][0], acc[mt][nt][1]);
                *(__half2*)(Ch + (size_t)(row0 + 8) * D_ + col) =
                    __floats2half2_rn(acc[mt][nt][2], acc[mt][nt][3]);
            } else {
                *(float2*)(Cf + (size_t)row0 * D_ + col) =
                    make_float2(acc[mt][nt][0], acc[mt][nt][1]);
                *(float2*)(Cf + (size_t)(row0 + 8) * D_ + col) =
                    make_float2(acc[mt][nt][2], acc[mt][nt][3]);
            }
        }
    }
}

// ===================================================================
// K_proj/V_proj
// ===================================================================
__global__ void proj_kernel(const float* __restrict__ Kb, const float* __restrict__ Vb,
                            const float* __restrict__ kpm, const float* __restrict__ vpm,
                            float* __restrict__ Kp, float* __restrict__ Vp)
{
    int p  = blockIdx.x;
    int bh = blockIdx.y;
    int b = bh >> 4, h = bh & 15;
    int d = threadIdx.x;
    const float* kbase = Kb + (size_t)b * P_ * D_ + h * HD_ + d;
    const float* vbase = Vb + (size_t)b * P_ * D_ + h * HD_ + d;
    float ak = 0.f, av = 0.f;
    for (int l = 0; l <= p; ++l) {
        float mk = kpm[p * MAXLEN_ + l];
        float mv = vpm[p * MAXLEN_ + l];
        ak += mk * kbase[(size_t)l * D_];
        av += mv * vbase[(size_t)l * D_];
    }
    size_t o = ((size_t)bh * P_ + p) * HD_ + d;
    Kp[o] = ak;
    Vp[o] = av;
}

// ===================================================================
// Attention: 2 Q-tiles (256 l's) per CTA, K/V smem loaded once.
// ===================================================================
#define QH_OFF   0
#define KH_OFF   18432
#define VT_OFF   36864
#define PH_OFF   54272
#define REDM_OFF 89088
#define REDS_OFF 91136
#define ATT_SMEM 93184

__global__ __launch_bounds__(256) void attn_mma(
    const __half* __restrict__ Q, const float* __restrict__ Kp,
    const float* __restrict__ Vp, __half* __restrict__ As)
{
    extern __shared__ char sm[];
    const uint32_t s0 = smem_u32(sm);
    const int tid = threadIdx.x;
    const int lane = tid & 31;
    const int wid = tid >> 5;
    const int wm = wid >> 2;
    const int wn = wid & 3;
    const int lhalf = lane >> 4;
    const int bh = blockIdx.y;
    const int b = bh >> 4, h = bh & 15;

    const float* kg = Kp + (size_t)bh * P_ * HD_;
    const float* vg = Vp + (size_t)bh * P_ * HD_;
    #pragma unroll
    for (int t = 0; t < 8; ++t) {
        int e = t * 256 + tid;
        int r = e >> 4;
        int d0 = (e & 15) * 4;
        float4 k = *(const float4*)(kg + r * HD_ + d0);
        __half2* dk = (__half2*)(sm + KH_OFF + (r * 72 + d0) * 2);
        dk[0] = __floats2half2_rn(k.x, k.y);
        dk[1] = __floats2half2_rn(k.z, k.w);
        float4 w = *(const float4*)(vg + r * HD_ + d0);
        __half* vt = (__half*)(sm + VT_OFF);
        vt[(d0 + 0) * 136 + r] = __float2half_rn(w.x);
        vt[(d0 + 1) * 136 + r] = __float2half_rn(w.y);
        vt[(d0 + 2) * 136 + r] = __float2half_rn(w.z);
        vt[(d0 + 3) * 136 + r] = __float2half_rn(w.w);
    }

    float* redm = (float*)(sm + REDM_OFF);
    float* reds = (float*)(sm + REDS_OFF);

    for (int t2 = 0; t2 < 2; ++t2) {
        const int l0 = blockIdx.x * 256 + t2 * 128;

        const __half* qg = Q + ((size_t)(b * L_ + l0)) * D_ + h * HD_;
        #pragma unroll
        for (int t = 0; t < 4; ++t) {
            int e = t * 256 + tid;
            int r = e >> 3;
            int c = (e & 7) * 8;
            uint4 v = *(const uint4*)(qg + (size_t)r * D_ + c);
            *(uint4*)(sm + QH_OFF + (r * 72 + c) * 2) = v;
        }
        __syncthreads();

        float sc[4][4][4];
        #pragma unroll
        for (int i = 0; i < 4; ++i)
            #pragma unroll
            for (int j = 0; j < 4; ++j)
                #pragma unroll
                for (int q = 0; q < 4; ++q) sc[i][j][q] = 0.f;

        #pragma unroll
        for (int kc = 0; kc < 4; ++kc) {
            uint32_t a[4][4], bfr[4][2];
            #pragma unroll
            for (int mt = 0; mt < 4; ++mt) {
                uint32_t ad = s0 + QH_OFF + ((wm * 64 + mt * 16 + (lane & 15)) * 72) * 2
                            + (kc * 2 + lhalf) * 16;
                LDSM_X4(a[mt][0], a[mt][1], a[mt][2], a[mt][3], ad);
            }
            #pragma unroll
            for (int np = 0; np < 2; ++np) {
                uint32_t bd = s0 + KH_OFF + ((wn * 32 + np * 16 + (lane & 15)) * 72) * 2
                            + (kc * 2 + lhalf) * 16;
                uint32_t r0, r1, r2, r3;
                LDSM_X4(r0, r1, r2, r3, bd);
                bfr[np * 2 + 0][0] = r0; bfr[np * 2 + 0][1] = r2;
                bfr[np * 2 + 1][0] = r1; bfr[np * 2 + 1][1] = r3;
            }
            #pragma unroll
            for (int mt = 0; mt < 4; ++mt)
                #pragma unroll
                for (int nt = 0; nt < 4; ++nt)
                    MMAF16(sc[mt][nt][0], sc[mt][nt][1], sc[mt][nt][2], sc[mt][nt][3],
                           a[mt][0], a[mt][1], a[mt][2], a[mt][3],
                           bfr[nt][0], bfr[nt][1]);
        }

        const bool dom = (blockIdx.x == 0) && (t2 == 0);
        #pragma unroll
        for (int mt = 0; mt < 4; ++mt) {
            int r0 = wm * 64 + mt * 16 + (lane >> 2);
            #pragma unroll
            for (int nt = 0; nt < 4; ++nt) {
                int c0 = wn * 32 + nt * 8 + (lane & 3) * 2;
                #pragma unroll
                for (int q = 0; q < 4; ++q) {
                    sc[mt][nt][q] *= 0.125f;
                    if (dom) {
                        int rr = r0 + ((q >= 2) ? 8 : 0);
                        int cc = c0 + (q & 1);
                        if (cc > rr) sc[mt][nt][q] = -1e30f;
                    }
                }
            }
        }

        #pragma unroll
        for (int mt = 0; mt < 4; ++mt) {
            float mlo = -1e30f, mhi = -1e30f;
            #pragma unroll
            for (int nt = 0; nt < 4; ++nt) {
                mlo = fmaxf(mlo, fmaxf(sc[mt][nt][0], sc[mt][nt][1]));
                mhi = fmaxf(mhi, fmaxf(sc[mt][nt][2], sc[mt][nt][3]));
            }
            #pragma unroll
            for (int o = 1; o <= 2; o <<= 1) {
                mlo = fmaxf(mlo, __shfl_xor_sync(0xffffffffu, mlo, o));
                mhi = fmaxf(mhi, __shfl_xor_sync(0xffffffffu, mhi, o));
            }
            if ((lane & 3) == 0) {
                int r0 = wm * 64 + mt * 16 + (lane >> 2);
                redm[wn * 128 + r0] = mlo;
                redm[wn * 128 + r0 + 8] = mhi;
            }
        }
        __syncthreads();

        #pragma unroll
        for (int mt = 0; mt < 4; ++mt) {
            int r0 = wm * 64 + mt * 16 + (lane >> 2);
            float mlo = fmaxf(fmaxf(redm[r0], redm[128 + r0]),
                              fmaxf(redm[256 + r0], redm[384 + r0]));
            int r1 = r0 + 8;
            float mhi = fmaxf(fmaxf(redm[r1], redm[128 + r1]),
                              fmaxf(redm[256 + r1], redm[384 + r1]));
            float slo = 0.f, shi = 0.f;
            #pragma unroll
            for (int nt = 0; nt < 4; ++nt) {
                sc[mt][nt][0] = __expf(sc[mt][nt][0] - mlo);
                sc[mt][nt][1] = __expf(sc[mt][nt][1] - mlo);
                sc[mt][nt][2] = __expf(sc[mt][nt][2] - mhi);
                sc[mt][nt][3] = __expf(sc[mt][nt][3] - mhi);
                slo += sc[mt][nt][0] + sc[mt][nt][1];
                shi += sc[mt][nt][2] + sc[mt][nt][3];
            }
            #pragma unroll
            for (int o = 1; o <= 2; o <<= 1) {
                slo += __shfl_xor_sync(0xffffffffu, slo, o);
                shi += __shfl_xor_sync(0xffffffffu, shi, o);
            }
            if ((lane & 3) == 0) {
                reds[wn * 128 + r0] = slo;
                reds[wn * 128 + r0 + 8] = shi;
            }
        }
        __syncthreads();

        #pragma unroll
        for (int mt = 0; mt < 4; ++mt) {
            int r0 = wm * 64 + mt * 16 + (lane >> 2);
            int r1 = r0 + 8;
            float ilo = __frcp_rn(reds[r0] + reds[128 + r0] + reds[256 + r0] + reds[384 + r0]);
            float ihi = __frcp_rn(reds[r1] + reds[128 + r1] + reds[256 + r1] + reds[384 + r1]);
            #pragma unroll
            for (int nt = 0; nt < 4; ++nt) {
                int c0 = wn * 32 + nt * 8 + (lane & 3) * 2;
                *(__half2*)(sm + PH_OFF + (r0 * 136 + c0) * 2) =
                    __floats2half2_rn(sc[mt][nt][0] * ilo, sc[mt][nt][1] * ilo);
                *(__half2*)(sm + PH_OFF + (r1 * 136 + c0) * 2) =
                    __floats2half2_rn(sc[mt][nt][2] * ihi, sc[mt][nt][3] * ihi);
            }
        }
        __syncthreads();

        float oc[4][2][4];
        #pragma unroll
        for (int i = 0; i < 4; ++i)
            #pragma unroll
            for (int j = 0; j < 2; ++j)
                #pragma unroll
                for (int q = 0; q < 4; ++q) oc[i][j][q] = 0.f;

        #pragma unroll
        for (int kc = 0; kc < 8; ++kc) {
            uint32_t a[4][4], bfr[2][2];
            #pragma unroll
            for (int mt = 0; mt < 4; ++mt) {
                uint32_t ad = s0 + PH_OFF + ((wm * 64 + mt * 16 + (lane & 15)) * 136) * 2
                            + (kc * 2 + lhalf) * 16;
                LDSM_X4(a[mt][0], a[mt][1], a[mt][2], a[mt][3], ad);
            }
            {
                uint32_t bd = s0 + VT_OFF + ((wn * 16 + (lane & 15)) * 136) * 2
                            + (kc * 2 + lhalf) * 16;
                uint32_t r0, r1, r2, r3;
                LDSM_X4(r0, r1, r2, r3, bd);
                bfr[0][0] = r0; bfr[0][1] = r2;
                bfr[1][0] = r1; bfr[1][1] = r3;
            }
            #pragma unroll
            for (int mt = 0; mt < 4; ++mt)
                #pragma unroll
                for (int nt = 0; nt < 2; ++nt)
                    MMAF16(oc[mt][nt][0], oc[mt][nt][1], oc[mt][nt][2], oc[mt][nt][3],
                           a[mt][0], a[mt][1], a[mt][2], a[mt][3],
                           bfr[nt][0], bfr[nt][1]);
        }

        #pragma unroll
        for (int mt = 0; mt < 4; ++mt) {
            int r0 = wm * 64 + mt * 16 + (lane >> 2);
            #pragma unroll
            for (int nt = 0; nt < 2; ++nt) {
                int cd = wn * 16 + nt * 8 + (lane & 3) * 2;
                int gcol = h * HD_ + cd;
                *(__half2*)(As + (size_t)(b * L_ + l0 + r0) * D_ + gcol) =
                    __floats2half2_rn(oc[mt][nt][0], oc[mt][nt][1]);
                *(__half2*)(As + (size_t)(b * L_ + l0 + r0 + 8) * D_ + gcol) =
                    __floats2half2_rn(oc[mt][nt][2], oc[mt][nt][3]);
            }
        }
        __syncthreads();
    }
}

// ===================================================================
extern "C" void kernel_launch(void* const* d_in, const int* in_sizes, int n_in,
                              void* d_out, int out_size)
{
    const float* x   = (const float*)d_in[0];
    const float* fc  = (const float*)d_in[1];
    const float* fs  = (const float*)d_in[2];
    const float* Wq  = (const float*)d_in[3];
    const float* Wk  = (const float*)d_in[4];
    const float* Wv  = (const float*)d_in[5];
    const float* Wo  = (const float*)d_in[6];
    const float* kpm = (const float*)d_in[7];
    const float* vpm = (const float*)d_in[8];
    float* out = (float*)d_out;

    __half *xh, *As, *kvh, *Wq2, *Wk2, *Wv2, *Wo2, *Qh;
    float *Kb, *Vb, *Kpp, *Vpp;
    cudaGetSymbolAddress((void**)&xh,  g_xh);
    cudaGetSymbolAddress((void**)&As,  g_As);
    cudaGetSymbolAddress((void**)&kvh, g_kvh);
    cudaGetSymbolAddress((void**)&Wq2, g_Wq2);
    cudaGetSymbolAddress((void**)&Wk2, g_Wk2);
    cudaGetSymbolAddress((void**)&Wv2, g_Wv2);
    cudaGetSymbolAddress((void**)&Wo2, g_Wo2);
    cudaGetSymbolAddress((void**)&Qh,  g_Q);
    cudaGetSymbolAddress((void**)&Kb,  g_K);
    cudaGetSymbolAddress((void**)&Vb,  g_V);
    cudaGetSymbolAddress((void**)&Kpp, g_Kp);
    cudaGetSymbolAddress((void**)&Vpp, g_Vp);

    cudaFuncSetAttribute(gemm_f16, cudaFuncAttributeMaxDynamicSharedMemorySize, GEMM_SMEM);
    cudaFuncSetAttribute(attn_mma, cudaFuncAttributeMaxDynamicSharedMemorySize, ATT_SMEM);

    // conversions
    conv_x<<<(M_FULL * 128 + 255) / 256, 256>>>(x, xh, M_FULL, M_FULL, M_FULL);
    conv_x<<<(M_KV * 128 + 255) / 256, 256>>>(x, kvh, M_KV, P_, L_);
    conv_w4<<<(4 * D_ * 128 + 255) / 256, 256>>>(Wq, Wk, Wv, Wo, Wq2, Wk2, Wv2, Wo2);

    // projections: Q (rope, fp16 out), K (rope, fp32), V (fp32)
    gemm_f16<<<dim3(D_ / BN, M_FULL / BM), 256, GEMM_SMEM>>>(xh, Wq2, nullptr, Qh, fc, fs, L_ - 1);
    gemm_f16<<<dim3(D_ / BN, M_KV / BM), 256, GEMM_SMEM>>>(kvh, Wk2, Kb, nullptr, fc, fs, P_ - 1);
    gemm_f16<<<dim3(D_ / BN, M_KV / BM), 256, GEMM_SMEM>>>(kvh, Wv2, Vb, nullptr, nullptr, nullptr, 0);

    // low-rank projections (tril-masked)
    proj_kernel<<<dim3(P_, BH_), 64>>>(Kb, Vb, kpm, vpm, Kpp, Vpp);

    // attention (2 tiles per CTA)
    attn_mma<<<dim3(L_ / 256, BH_), 256, ATT_SMEM>>>(Qh, Kpp, Vpp, As);

    // final projection (fp32 out)
    gemm_f16<<<dim3(D_ / BN, M_FULL / BM), 256, GEMM_SMEM>>>(As, Wo2, out, nullptr, nullptr, nullptr, 0);
}

// round 11
// speedup vs baseline: 7.1357x; 1.0645x over previous
#include <cuda_runtime.h>
#include <cuda_bf16.h>
#include <cuda_fp16.h>
#include <cstdint>

// Problem constants
#define B_  4
#define L_  4096
#define D_  1024
#define H_  16
#define HD_ 64
#define P_  128
#define MAXLEN_ 4096
#define BH_ (B_ * H_)
#define M_FULL (B_ * L_)       // 16384
#define M_KV   (B_ * P_)       // 512

__device__ __forceinline__ uint32_t smem_u32(const void* p) {
    uint32_t a;
    asm("{ .reg .u64 t; cvta.to.shared.u64 t, %1; cvt.u32.u64 %0, t; }" : "=r"(a) : "l"(p));
    return a;
}
#define CP_ASYNC16(dst, src) \
    asm volatile("cp.async.cg.shared.global [%0], [%1], 16;" :: "r"(dst), "l"(src))
#define CP_COMMIT() asm volatile("cp.async.commit_group;" ::: "memory")
#define CP_WAIT1()  asm volatile("cp.async.wait_group 1;" ::: "memory")

#define LDSM_X4(R0, R1, R2, R3, A) \
    asm volatile("ldmatrix.sync.aligned.m8n8.x4.shared.b16 {%0,%1,%2,%3}, [%4];" \
        : "=r"(R0), "=r"(R1), "=r"(R2), "=r"(R3) : "r"(A))

#define MMAF16(D0, D1, D2, D3, A0, A1, A2, A3, B0, B1) \
    asm volatile("mma.sync.aligned.m16n8k16.row.col.f32.f16.f16.f32 " \
        "{%0,%1,%2,%3}, {%4,%5,%6,%7}, {%8,%9}, {%0,%1,%2,%3};" \
        : "+f"(D0), "+f"(D1), "+f"(D2), "+f"(D3) \
        : "r"(A0), "r"(A1), "r"(A2), "r"(A3), "r"(B0), "r"(B1))

// -------- scratch --------
__device__ __half g_xh [M_FULL * (size_t)D_];
__device__ __half g_As [M_FULL * (size_t)D_];
__device__ __half g_kvh[M_KV   * (size_t)D_];
__device__ __half g_Wq2[D_ * (size_t)D_];
__device__ __half g_Wkv[2 * D_ * (size_t)D_];   // [Wk rows | Wv rows]
__device__ __half g_Wo2[D_ * (size_t)D_];
__device__ __half g_Q [M_FULL * (size_t)D_];
__device__ float g_KV [M_KV * (size_t)(2 * D_)]; // cols 0..1023 K(rope), 1024..2047 V
__device__ float g_Kp[BH_ * P_ * HD_];
__device__ float g_Vp[BH_ * P_ * HD_];

// ===================================================================
// conv_all: one launch does xh (gather-free), kvh (gathered first-128 rows),
// and the 3 weight buffers (Wq2, Wkv[2 halves], Wo2). Indexed by flat id.
//   segment 0: [0, 2097152)          xh       (16384 rows)
//   segment 1: [2097152, 2162688)    kvh      (512 rows gathered)
//   segment 2: [2162688, +131072)    Wq2
//   segment 3: next 131072           Wkv rows 0..1023   (Wk)
//   segment 4: next 131072           Wkv rows 1024..2047(Wv)
//   segment 5: next 131072           Wo2
// ===================================================================
#define SEG0 (M_FULL * 128)
#define SEG1 (SEG0 + M_KV * 128)
#define SEGW 131072
#define CONV_TOT (SEG1 + 4 * SEGW)

__global__ __launch_bounds__(256) void conv_all(
    const float* __restrict__ x,  const float* __restrict__ Wq,
    const float* __restrict__ Wk, const float* __restrict__ Wv,
    const float* __restrict__ Wo,
    __half* __restrict__ xh, __half* __restrict__ kvh,
    __half* __restrict__ Wq2, __half* __restrict__ Wkv, __half* __restrict__ Wo2)
{
    int i = blockIdx.x * 256 + threadIdx.x;
    if (i >= CONV_TOT) return;
    const float* src;
    __half* dst;
    int row, c;
    if (i < SEG0) {
        row = i >> 7; c = (i & 127) * 8;
        src = x; dst = xh;
    } else if (i < SEG1) {
        int r = i - SEG0;
        int drow = r >> 7; c = (r & 127) * 8;
        int b = drow >> 7, l = drow & 127;
        src = x; dst = kvh;
        // gather: source row = b*L + l ; dest row = drow
        const float4* s = (const float4*)(x + ((size_t)b * L_ + l) * D_ + c);
        float4 f0 = s[0], f1 = s[1];
        __half2 h[4];
        h[0] = __floats2half2_rn(f0.x, f0.y);
        h[1] = __floats2half2_rn(f0.z, f0.w);
        h[2] = __floats2half2_rn(f1.x, f1.y);
        h[3] = __floats2half2_rn(f1.z, f1.w);
        *(uint4*)(kvh + (size_t)drow * D_ + c) = *(uint4*)h;
        return;
    } else {
        int r = i - SEG1;
        int seg = r / SEGW;
        int q = r - seg * SEGW;
        row = q >> 7; c = (q & 127) * 8;
        if (seg == 0)      { src = Wq; dst = Wq2; }
        else if (seg == 1) { src = Wk; dst = Wkv; }
        else if (seg == 2) { src = Wv; dst = Wkv + (size_t)D_ * D_; }
        else               { src = Wo; dst = Wo2; }
    }
    const float4* s = (const float4*)(src + (size_t)row * D_ + c);
    float4 f0 = s[0], f1 = s[1];
    __half2 h[4];
    h[0] = __floats2half2_rn(f0.x, f0.y);
    h[1] = __floats2half2_rn(f0.z, f0.w);
    h[2] = __floats2half2_rn(f1.x, f1.y);
    h[3] = __floats2half2_rn(f1.z, f1.w);
    *(uint4*)(dst + (size_t)row * D_ + c) = *(uint4*)h;
}

// ===================================================================
// fp16 mma GEMM: BM=128, BN=128, BK=64, 3-stage cp.async, 8 warps (2x4),
// warp tile 64x32, 2 CTAs/SM, single barrier per K-chunk.
// NW = output width (D_ for normal, 2*D_ for fused KV).
// ropeN: if >0, apply rope only when bx < ropeN (K half of fused KV).
// ===================================================================
#define BM 128
#define BN 128
#define BK 64
#define NSTG 3
#define NKC 16
#define OPA  (BM * 128)              // 16 KB
#define STGB ((BM + BN) * 128)       // 32 KB
#define GEMM_SMEM (NSTG * STGB)      // 96 KB

__global__ __launch_bounds__(256, 2) void gemm_f16(
    const __half* __restrict__ A, const __half* __restrict__ W,
    float* __restrict__ Cf, __half* __restrict__ Ch, int NW,
    const float* __restrict__ rcos, const float* __restrict__ rsin,
    int lmask, int ropeN)
{
    extern __shared__ char dsm[];
    const uint32_t s0 = smem_u32(dsm);
    const int tid = threadIdx.x;
    const int wid = tid >> 5;
    const int lane = tid & 31;
    const int bx = blockIdx.x, by = blockIdx.y;

    const int lrow = tid >> 3;
    const int lch = tid & 7;
    const uint32_t sw0 = (uint32_t)(lrow * 128 + ((lch ^ (lrow & 7)) << 4));
    const char* aB = (const char*)(A + (size_t)(by * BM + lrow) * D_ + lch * 8);
    const char* wB = (const char*)(W + (size_t)(bx * BN + lrow) * D_ + lch * 8);
    const size_t RSTRIDE = (size_t)32 * D_ * 2;

    const int wm = wid >> 2;
    const int wn = wid & 3;
    const int lhalf = lane >> 4;

    uint32_t aro[4], bro[2];
    uint32_t arx[4], brx[2];
    #pragma unroll
    for (int mt = 0; mt < 4; ++mt) {
        int row = wm * 64 + mt * 16 + (lane & 15);
        aro[mt] = (uint32_t)(row * 128);
        arx[mt] = (uint32_t)(row & 7);
    }
    #pragma unroll
    for (int np = 0; np < 2; ++np) {
        int row = wn * 32 + np * 16 + (lane & 15);
        bro[np] = (uint32_t)(row * 128);
        brx[np] = (uint32_t)(row & 7);
    }

    float acc[4][4][4];
    #pragma unroll
    for (int i = 0; i < 4; ++i)
        #pragma unroll
        for (int j = 0; j < 4; ++j)
            #pragma unroll
            for (int q = 0; q < 4; ++q) acc[i][j][q] = 0.f;

    #pragma unroll
    for (int c = 0; c < NSTG - 1; ++c) {
        uint32_t sb = s0 + c * STGB;
        size_t off = (size_t)c * 128;
        #pragma unroll
        for (int j = 0; j < 4; ++j) {
            CP_ASYNC16(sb + sw0 + j * 4096,        aB + j * RSTRIDE + off);
            CP_ASYNC16(sb + OPA + sw0 + j * 4096,  wB + j * RSTRIDE + off);
        }
        CP_COMMIT();
    }

    int stage = 0;
    for (int kc = 0; kc < NKC; ++kc) {
        CP_WAIT1();
        __syncthreads();

        {
            int ldc = kc + NSTG - 1;
            if (ldc < NKC) {
                int ls = ldc % NSTG;
                uint32_t sb = s0 + ls * STGB;
                size_t off = (size_t)ldc * 128;
                #pragma unroll
                for (int j = 0; j < 4; ++j) {
                    CP_ASYNC16(sb + sw0 + j * 4096,       aB + j * RSTRIDE + off);
                    CP_ASYNC16(sb + OPA + sw0 + j * 4096, wB + j * RSTRIDE + off);
                }
            }
            CP_COMMIT();
        }

        const uint32_t ab = s0 + stage * STGB;
        const uint32_t bb = ab + OPA;
        #pragma unroll
        for (int ks = 0; ks < 4; ++ks) {
            const uint32_t ch = (uint32_t)(ks * 2 + lhalf);
            uint32_t a[4][4], b[4][2];
            #pragma unroll
            for (int mt = 0; mt < 4; ++mt) {
                uint32_t ad = ab + aro[mt] + ((ch ^ arx[mt]) << 4);
                LDSM_X4(a[mt][0], a[mt][1], a[mt][2], a[mt][3], ad);
            }
            #pragma unroll
            for (int np = 0; np < 2; ++np) {
                uint32_t bd = bb + bro[np] + ((ch ^ brx[np]) << 4);
                uint32_t r0, r1, r2, r3;
                LDSM_X4(r0, r1, r2, r3, bd);
                b[np * 2 + 0][0] = r0; b[np * 2 + 0][1] = r2;
                b[np * 2 + 1][0] = r1; b[np * 2 + 1][1] = r3;
            }
            #pragma unroll
            for (int mt = 0; mt < 4; ++mt)
                #pragma unroll
                for (int nt = 0; nt < 4; ++nt)
                    MMAF16(acc[mt][nt][0], acc[mt][nt][1], acc[mt][nt][2], acc[mt][nt][3],
                           a[mt][0], a[mt][1], a[mt][2], a[mt][3],
                           b[nt][0], b[nt][1]);
        }
        stage = (stage + 1 == NSTG) ? 0 : stage + 1;
    }

    const bool doRope = (rcos != nullptr) && (bx < ropeN);
    #pragma unroll
    for (int mt = 0; mt < 4; ++mt) {
        int row0 = by * BM + wm * 64 + mt * 16 + (lane >> 2);
        if (doRope) {
            int la = row0 & lmask;
            int lb = (row0 + 8) & lmask;
            #pragma unroll
            for (int nt = 0; nt < 4; ++nt) {
                int col = bx * BN + wn * 32 + nt * 8 + (lane & 3) * 2;
                int f = (col & 63) >> 1;
                float ca = rcos[la * 32 + f], sa = rsin[la * 32 + f];
                float cb = rcos[lb * 32 + f], sb = rsin[lb * 32 + f];
                float a0 = acc[mt][nt][0], a1 = acc[mt][nt][1];
                acc[mt][nt][0] = a0 * ca - a1 * sa;
                acc[mt][nt][1] = a0 * sa + a1 * ca;
                a0 = acc[mt][nt][2]; a1 = acc[mt][nt][3];
                acc[mt][nt][2] = a0 * cb - a1 * sb;
                acc[mt][nt][3] = a0 * sb + a1 * cb;
            }
        }
        #pragma unroll
        for (int nt = 0; nt < 4; ++nt) {
            int col = bx * BN + wn * 32 + nt * 8 + (lane & 3) * 2;
            if (Ch != nullptr) {
                *(__half2*)(Ch + (size_t)row0 * NW + col) =
                    __floats2half2_rn(acc[mt][nt][0], acc[mt][nt][1]);
                *(__half2*)(Ch + (size_t)(row0 + 8) * NW + col) =
                    __floats2half2_rn(acc[mt][nt][2], acc[mt][nt][3]);
            } else {
                *(float2*)(Cf + (size_t)row0 * NW + col) =
                    make_float2(acc[mt][nt][0], acc[mt][nt][1]);
                *(float2*)(Cf + (size_t)(row0 + 8) * NW + col) =
                    make_float2(acc[mt][nt][2], acc[mt][nt][3]);
            }
        }
    }
}

// ===================================================================
// K_proj/V_proj from fused KV buffer (row stride 2048; V at +1024)
// ===================================================================
__global__ void proj_kernel(const float* __restrict__ KV,
                            const float* __restrict__ kpm, const float* __restrict__ vpm,
                            float* __restrict__ Kp, float* __restrict__ Vp)
{
    int p  = blockIdx.x;
    int bh = blockIdx.y;
    int b = bh >> 4, h = bh & 15;
    int d = threadIdx.x;
    const float* kbase = KV + (size_t)b * P_ * (2 * D_) + h * HD_ + d;
    const float* vbase = kbase + D_;
    float ak = 0.f, av = 0.f;
    for (int l = 0; l <= p; ++l) {
        float mk = kpm[p * MAXLEN_ + l];
        float mv = vpm[p * MAXLEN_ + l];
        ak += mk * kbase[(size_t)l * (2 * D_)];
        av += mv * vbase[(size_t)l * (2 * D_)];
    }
    size_t o = ((size_t)bh * P_ + p) * HD_ + d;
    Kp[o] = ak;
    Vp[o] = av;
}

// ===================================================================
// Attention: 4 Q-tiles (512 l's) per CTA, K/V smem loaded once.
// ===================================================================
#define QH_OFF   0
#define KH_OFF   18432
#define VT_OFF   36864
#define PH_OFF   54272
#define REDM_OFF 89088
#define REDS_OFF 91136
#define ATT_SMEM 93184
#define ATT_TILES 4

__global__ __launch_bounds__(256) void attn_mma(
    const __half* __restrict__ Q, const float* __restrict__ Kp,
    const float* __restrict__ Vp, __half* __restrict__ As)
{
    extern __shared__ char sm[];
    const uint32_t s0 = smem_u32(sm);
    const int tid = threadIdx.x;
    const int lane = tid & 31;
    const int wid = tid >> 5;
    const int wm = wid >> 2;
    const int wn = wid & 3;
    const int lhalf = lane >> 4;
    const int bh = blockIdx.y;
    const int b = bh >> 4, h = bh & 15;

    const float* kg = Kp + (size_t)bh * P_ * HD_;
    const float* vg = Vp + (size_t)bh * P_ * HD_;
    #pragma unroll
    for (int t = 0; t < 8; ++t) {
        int e = t * 256 + tid;
        int r = e >> 4;
        int d0 = (e & 15) * 4;
        float4 k = *(const float4*)(kg + r * HD_ + d0);
        __half2* dk = (__half2*)(sm + KH_OFF + (r * 72 + d0) * 2);
        dk[0] = __floats2half2_rn(k.x, k.y);
        dk[1] = __floats2half2_rn(k.z, k.w);
        float4 w = *(const float4*)(vg + r * HD_ + d0);
        __half* vt = (__half*)(sm + VT_OFF);
        vt[(d0 + 0) * 136 + r] = __float2half_rn(w.x);
        vt[(d0 + 1) * 136 + r] = __float2half_rn(w.y);
        vt[(d0 + 2) * 136 + r] = __float2half_rn(w.z);
        vt[(d0 + 3) * 136 + r] = __float2half_rn(w.w);
    }

    float* redm = (float*)(sm + REDM_OFF);
    float* reds = (float*)(sm + REDS_OFF);

    for (int t2 = 0; t2 < ATT_TILES; ++t2) {
        const int l0 = blockIdx.x * (128 * ATT_TILES) + t2 * 128;

        const __half* qg = Q + ((size_t)(b * L_ + l0)) * D_ + h * HD_;
        #pragma unroll
        for (int t = 0; t < 4; ++t) {
            int e = t * 256 + tid;
            int r = e >> 3;
            int c = (e & 7) * 8;
            uint4 v = *(const uint4*)(qg + (size_t)r * D_ + c);
            *(uint4*)(sm + QH_OFF + (r * 72 + c) * 2) = v;
        }
        __syncthreads();

        float sc[4][4][4];
        #pragma unroll
        for (int i = 0; i < 4; ++i)
            #pragma unroll
            for (int j = 0; j < 4; ++j)
                #pragma unroll
                for (int q = 0; q < 4; ++q) sc[i][j][q] = 0.f;

        #pragma unroll
        for (int kc = 0; kc < 4; ++kc) {
            uint32_t a[4][4], bfr[4][2];
            #pragma unroll
            for (int mt = 0; mt < 4; ++mt) {
                uint32_t ad = s0 + QH_OFF + ((wm * 64 + mt * 16 + (lane & 15)) * 72) * 2
                            + (kc * 2 + lhalf) * 16;
                LDSM_X4(a[mt][0], a[mt][1], a[mt][2], a[mt][3], ad);
            }
            #pragma unroll
            for (int np = 0; np < 2; ++np) {
                uint32_t bd = s0 + KH_OFF + ((wn * 32 + np * 16 + (lane & 15)) * 72) * 2
                            + (kc * 2 + lhalf) * 16;
                uint32_t r0, r1, r2, r3;
                LDSM_X4(r0, r1, r2, r3, bd);
                bfr[np * 2 + 0][0] = r0; bfr[np * 2 + 0][1] = r2;
                bfr[np * 2 + 1][0] = r1; bfr[np * 2 + 1][1] = r3;
            }
            #pragma unroll
            for (int mt = 0; mt < 4; ++mt)
                #pragma unroll
                for (int nt = 0; nt < 4; ++nt)
                    MMAF16(sc[mt][nt][0], sc[mt][nt][1], sc[mt][nt][2], sc[mt][nt][3],
                           a[mt][0], a[mt][1], a[mt][2], a[mt][3],
                           bfr[nt][0], bfr[nt][1]);
        }

        const bool dom = (blockIdx.x == 0) && (t2 == 0);
        #pragma unroll
        for (int mt = 0; mt < 4; ++mt) {
            int r0 = wm * 64 + mt * 16 + (lane >> 2);
            #pragma unroll
            for (int nt = 0; nt < 4; ++nt) {
                int c0 = wn * 32 + nt * 8 + (lane & 3) * 2;
                #pragma unroll
                for (int q = 0; q < 4; ++q) {
                    sc[mt][nt][q] *= 0.125f;
                    if (dom) {
                        int rr = r0 + ((q >= 2) ? 8 : 0);
                        int cc = c0 + (q & 1);
                        if (cc > rr) sc[mt][nt][q] = -1e30f;
                    }
                }
            }
        }

        #pragma unroll
        for (int mt = 0; mt < 4; ++mt) {
            float mlo = -1e30f, mhi = -1e30f;
            #pragma unroll
            for (int nt = 0; nt < 4; ++nt) {
                mlo = fmaxf(mlo, fmaxf(sc[mt][nt][0], sc[mt][nt][1]));
                mhi = fmaxf(mhi, fmaxf(sc[mt][nt][2], sc[mt][nt][3]));
            }
            #pragma unroll
            for (int o = 1; o <= 2; o <<= 1) {
                mlo = fmaxf(mlo, __shfl_xor_sync(0xffffffffu, mlo, o));
                mhi = fmaxf(mhi, __shfl_xor_sync(0xffffffffu, mhi, o));
            }
            if ((lane & 3) == 0) {
                int r0 = wm * 64 + mt * 16 + (lane >> 2);
                redm[wn * 128 + r0] = mlo;
                redm[wn * 128 + r0 + 8] = mhi;
            }
        }
        __syncthreads();

        #pragma unroll
        for (int mt = 0; mt < 4; ++mt) {
            int r0 = wm * 64 + mt * 16 + (lane >> 2);
            float mlo = fmaxf(fmaxf(redm[r0], redm[128 + r0]),
                              fmaxf(redm[256 + r0], redm[384 + r0]));
            int r1 = r0 + 8;
            float mhi = fmaxf(fmaxf(redm[r1], redm[128 + r1]),
                              fmaxf(redm[256 + r1], redm[384 + r1]));
            float slo = 0.f, shi = 0.f;
            #pragma unroll
            for (int nt = 0; nt < 4; ++nt) {
                sc[mt][nt][0] = __expf(sc[mt][nt][0] - mlo);
                sc[mt][nt][1] = __expf(sc[mt][nt][1] - mlo);
                sc[mt][nt][2] = __expf(sc[mt][nt][2] - mhi);
                sc[mt][nt][3] = __expf(sc[mt][nt][3] - mhi);
                slo += sc[mt][nt][0] + sc[mt][nt][1];
                shi += sc[mt][nt][2] + sc[mt][nt][3];
            }
            #pragma unroll
            for (int o = 1; o <= 2; o <<= 1) {
                slo += __shfl_xor_sync(0xffffffffu, slo, o);
                shi += __shfl_xor_sync(0xffffffffu, shi, o);
            }
            if ((lane & 3) == 0) {
                reds[wn * 128 + r0] = slo;
                reds[wn * 128 + r0 + 8] = shi;
            }
        }
        __syncthreads();

        #pragma unroll
        for (int mt = 0; mt < 4; ++mt) {
            int r0 = wm * 64 + mt * 16 + (lane >> 2);
            int r1 = r0 + 8;
            float ilo = __frcp_rn(reds[r0] + reds[128 + r0] + reds[256 + r0] + reds[384 + r0]);
            float ihi = __frcp_rn(reds[r1] + reds[128 + r1] + reds[256 + r1] + reds[384 + r1]);
            #pragma unroll
            for (int nt = 0; nt < 4; ++nt) {
                int c0 = wn * 32 + nt * 8 + (lane & 3) * 2;
                *(__half2*)(sm + PH_OFF + (r0 * 136 + c0) * 2) =
                    __floats2half2_rn(sc[mt][nt][0] * ilo, sc[mt][nt][1] * ilo);
                *(__half2*)(sm + PH_OFF + (r1 * 136 + c0) * 2) =
                    __floats2half2_rn(sc[mt][nt][2] * ihi, sc[mt][nt][3] * ihi);
            }
        }
        __syncthreads();

        float oc[4][2][4];
        #pragma unroll
        for (int i = 0; i < 4; ++i)
            #pragma unroll
            for (int j = 0; j < 2; ++j)
                #pragma unroll
                for (int q = 0; q < 4; ++q) oc[i][j][q] = 0.f;

        #pragma unroll
        for (int kc = 0; kc < 8; ++kc) {
            uint32_t a[4][4], bfr[2][2];
            #pragma unroll
            for (int mt = 0; mt < 4; ++mt) {
                uint32_t ad = s0 + PH_OFF + ((wm * 64 + mt * 16 + (lane & 15)) * 136) * 2
                            + (kc * 2 + lhalf) * 16;
                LDSM_X4(a[mt][0], a[mt][1], a[mt][2], a[mt][3], ad);
            }
            {
                uint32_t bd = s0 + VT_OFF + ((wn * 16 + (lane & 15)) * 136) * 2
                            + (kc * 2 + lhalf) * 16;
                uint32_t r0, r1, r2, r3;
                LDSM_X4(r0, r1, r2, r3, bd);
                bfr[0][0] = r0; bfr[0][1] = r2;
                bfr[1][0] = r1; bfr[1][1] = r3;
            }
            #pragma unroll
            for (int mt = 0; mt < 4; ++mt)
                #pragma unroll
                for (int nt = 0; nt < 2; ++nt)
                    MMAF16(oc[mt][nt][0], oc[mt][nt][1], oc[mt][nt][2], oc[mt][nt][3],
                           a[mt][0], a[mt][1], a[mt][2], a[mt][3],
                           bfr[nt][0], bfr[nt][1]);
        }

        #pragma unroll
        for (int mt = 0; mt < 4; ++mt) {
            int r0 = wm * 64 + mt * 16 + (lane >> 2);
            #pragma unroll
            for (int nt = 0; nt < 2; ++nt) {
                int cd = wn * 16 + nt * 8 + (lane & 3) * 2;
                int gcol = h * HD_ + cd;
                *(__half2*)(As + (size_t)(b * L_ + l0 + r0) * D_ + gcol) =
                    __floats2half2_rn(oc[mt][nt][0], oc[mt][nt][1]);
                *(__half2*)(As + (size_t)(b * L_ + l0 + r0 + 8) * D_ + gcol) =
                    __floats2half2_rn(oc[mt][nt][2], oc[mt][nt][3]);
            }
        }
        __syncthreads();
    }
}

// ===================================================================
extern "C" void kernel_launch(void* const* d_in, const int* in_sizes, int n_in,
                              void* d_out, int out_size)
{
    const float* x   = (const float*)d_in[0];
    const float* fc  = (const float*)d_in[1];
    const float* fs  = (const float*)d_in[2];
    const float* Wq  = (const float*)d_in[3];
    const float* Wk  = (const float*)d_in[4];
    const float* Wv  = (const float*)d_in[5];
    const float* Wo  = (const float*)d_in[6];
    const float* kpm = (const float*)d_in[7];
    const float* vpm = (const float*)d_in[8];
    float* out = (float*)d_out;

    __half *xh, *As, *kvh, *Wq2, *Wkv, *Wo2, *Qh;
    float *KV, *Kpp, *Vpp;
    cudaGetSymbolAddress((void**)&xh,  g_xh);
    cudaGetSymbolAddress((void**)&As,  g_As);
    cudaGetSymbolAddress((void**)&kvh, g_kvh);
    cudaGetSymbolAddress((void**)&Wq2, g_Wq2);
    cudaGetSymbolAddress((void**)&Wkv, g_Wkv);
    cudaGetSymbolAddress((void**)&Wo2, g_Wo2);
    cudaGetSymbolAddress((void**)&Qh,  g_Q);
    cudaGetSymbolAddress((void**)&KV,  g_KV);
    cudaGetSymbolAddress((void**)&Kpp, g_Kp);
    cudaGetSymbolAddress((void**)&Vpp, g_Vp);

    cudaFuncSetAttribute(gemm_f16, cudaFuncAttributeMaxDynamicSharedMemorySize, GEMM_SMEM);
    cudaFuncSetAttribute(attn_mma, cudaFuncAttributeMaxDynamicSharedMemorySize, ATT_SMEM);

    // one conversion launch
    conv_all<<<(CONV_TOT + 255) / 256, 256>>>(x, Wq, Wk, Wv, Wo, xh, kvh, Wq2, Wkv, Wo2);

    // Q projection (rope on all tiles, fp16 out)
    gemm_f16<<<dim3(D_ / BN, M_FULL / BM), 256, GEMM_SMEM>>>(
        xh, Wq2, nullptr, Qh, D_, fc, fs, L_ - 1, D_ / BN);

    // fused K+V projection: W = [Wk|Wv] (2048 rows), out KV[512 x 2048];
    // rope only on bx < 8 (K half), l = row % 128
    gemm_f16<<<dim3(2 * D_ / BN, M_KV / BM), 256, GEMM_SMEM>>>(
        kvh, Wkv, KV, nullptr, 2 * D_, fc, fs, P_ - 1, D_ / BN);

    // low-rank projections (tril-masked) from fused KV
    proj_kernel<<<dim3(P_, BH_), 64>>>(KV, kpm, vpm, Kpp, Vpp);

    // attention (4 tiles per CTA)
    attn_mma<<<dim3(L_ / (128 * ATT_TILES), BH_), 256, ATT_SMEM>>>(Qh, Kpp, Vpp, As);

    // final projection (fp32 out)
    gemm_f16<<<dim3(D_ / BN, M_FULL / BM), 256, GEMM_SMEM>>>(
        As, Wo2, out, nullptr, D_, nullptr, nullptr, 0, 0);
}